// round 2
// baseline (speedup 1.0000x reference)
#include <cuda_runtime.h>
#include <math.h>

#define BN_EPS 1e-5f
#define ATT_SCALE 0.125f   // 64^-0.5

typedef unsigned long long u64;

// ---------------- packed f32x2 helpers (Blackwell FFMA2) ----------------
__device__ __forceinline__ u64 pk2(float v) {
    u64 r; asm("mov.b64 %0, {%1, %1};" : "=l"(r) : "f"(v)); return r;
}
__device__ __forceinline__ void fma2(u64 &d, u64 a, u64 b) {
    asm("fma.rn.f32x2 %0, %1, %2, %0;" : "+l"(d) : "l"(a), "l"(b));
}
__device__ __forceinline__ float2 up2(u64 v) {
    float2 r; asm("mov.b64 {%0, %1}, %2;" : "=f"(r.x), "=f"(r.y) : "l"(v)); return r;
}

// ---------------- scratch (no allocations allowed) ----------------
// z = t*8 + b : t=0 -> x side, t=1 -> y side
__device__ float g_hq [16u * 256 * 1024];   // dw+bn stride1 out  [z][256][1024]
__device__ float g_hkv[16u * 256 * 256];    // dw+bn stride2 out  [z][256][256]
__device__ float g_q  [16u * 512 * 1024];   // q pointwise        [z][512][1024]
__device__ float g_kv [16u * 1024 * 256];   // kv pointwise       [z][1024][256]
__device__ float g_ao [16u * 512 * 1024];   // attention output   [z][512][1024]

// ---------------- depthwise 3x3 conv + BN (eval) ----------------
__global__ void dw_bn_kernel(const float* __restrict__ in,   // [8,256,32,32]
                             const float* __restrict__ w,    // [256,1,3,3]
                             const float* __restrict__ gamma,
                             const float* __restrict__ beta,
                             const float* __restrict__ mean,
                             const float* __restrict__ var,
                             float* __restrict__ out,        // [8,256,HO,HO]
                             int stride, int HO) {
    int idx = blockIdx.x * blockDim.x + threadIdx.x;
    int total = 8 * 256 * HO * HO;
    if (idx >= total) return;
    int ow = idx % HO;
    int oh = (idx / HO) % HO;
    int c  = (idx / (HO * HO)) % 256;
    int b  = idx / (HO * HO * 256);
    const float* ip = in + (size_t)(b * 256 + c) * 1024;
    const float* wp = w + c * 9;
    float acc = 0.f;
    int ih0 = oh * stride - 1, iw0 = ow * stride - 1;
#pragma unroll
    for (int kh = 0; kh < 3; kh++) {
        int ih = ih0 + kh;
        if (ih < 0 || ih > 31) continue;
#pragma unroll
        for (int kw = 0; kw < 3; kw++) {
            int iw = iw0 + kw;
            if (iw < 0 || iw > 31) continue;
            acc += wp[kh * 3 + kw] * ip[ih * 32 + iw];
        }
    }
    float sc = gamma[c] * rsqrtf(var[c] + BN_EPS);
    float sh = beta[c] - mean[c] * sc;
    out[idx] = acc * sc + sh;
}

// ---------------- batched GEMM: C[z] = A[M,K] * B[z][K,N] (+bias[m]) ----------------
// grid (N/64, M/64, nbatch), 256 threads, BK=32, thread tile 4x4 (2 f32x2 pairs)
__global__ void gemm64(const float* __restrict__ A, const float* __restrict__ B,
                       float* __restrict__ C, const float* __restrict__ bias,
                       int M, int N, int K) {
    __shared__ float As[32][68];   // [k][m] padded
    __shared__ float Bs[32][64];   // [k][n]
    const int tid = threadIdx.x;
    const int tx = tid & 15, ty = tid >> 4;
    const float* Bb = B + (size_t)blockIdx.z * K * N;
    float* Cb = C + (size_t)blockIdx.z * M * N;
    const int m0 = blockIdx.y * 64, n0 = blockIdx.x * 64;
    const int am = tid >> 3, ak = (tid & 7) * 4;
    const int bk = tid >> 4, bn = (tid & 15) * 4;

    u64 acc[4][2];
#pragma unroll
    for (int i = 0; i < 4; i++) { acc[i][0] = 0ull; acc[i][1] = 0ull; }

    for (int k0 = 0; k0 < K; k0 += 32) {
        float4 a0 = *(const float4*)&A[(size_t)(m0 + am) * K + k0 + ak];
        float4 a1 = *(const float4*)&A[(size_t)(m0 + am + 32) * K + k0 + ak];
        As[ak + 0][am] = a0.x; As[ak + 1][am] = a0.y;
        As[ak + 2][am] = a0.z; As[ak + 3][am] = a0.w;
        As[ak + 0][am + 32] = a1.x; As[ak + 1][am + 32] = a1.y;
        As[ak + 2][am + 32] = a1.z; As[ak + 3][am + 32] = a1.w;
        *(float4*)&Bs[bk][bn] =
            *(const float4*)&Bb[(size_t)(k0 + bk) * N + n0 + bn];
        *(float4*)&Bs[bk + 16][bn] =
            *(const float4*)&Bb[(size_t)(k0 + bk + 16) * N + n0 + bn];
        __syncthreads();
#pragma unroll
        for (int kk = 0; kk < 32; kk++) {
            float4 av = *(const float4*)&As[kk][ty * 4];
            u64 b0 = *(const u64*)&Bs[kk][tx * 4];
            u64 b1 = *(const u64*)&Bs[kk][tx * 4 + 2];
            u64 ap;
            ap = pk2(av.x); fma2(acc[0][0], ap, b0); fma2(acc[0][1], ap, b1);
            ap = pk2(av.y); fma2(acc[1][0], ap, b0); fma2(acc[1][1], ap, b1);
            ap = pk2(av.z); fma2(acc[2][0], ap, b0); fma2(acc[2][1], ap, b1);
            ap = pk2(av.w); fma2(acc[3][0], ap, b0); fma2(acc[3][1], ap, b1);
        }
        __syncthreads();
    }
#pragma unroll
    for (int i = 0; i < 4; i++) {
        float bv = bias ? bias[m0 + ty * 4 + i] : 0.f;
        float2 c0 = up2(acc[i][0]), c1 = up2(acc[i][1]);
        float4 o = make_float4(c0.x + bv, c0.y + bv, c1.x + bv, c1.y + bv);
        *(float4*)&Cb[(size_t)(m0 + ty * 4 + i) * N + n0 + tx * 4] = o;
    }
}

// ---------------- fused cross-attention ----------------
// grid (16 qtiles, 8 heads, 16 z). z=t*8+b: queries side t, K/V side 1-t.
// Block: 64 queries x 256 keys x d=64, fp32 f32x2.
__global__ void __launch_bounds__(256, 1)
attn_kernel(const float* __restrict__ qbuf, const float* __restrict__ kvbuf,
            float* __restrict__ obuf) {
    extern __shared__ float sm[];
    float* Qs = sm;                       // [64][68]: scaled Q[d][r]; reused as Os[d][r]
    float* KP = sm + 64 * 68;             // [64][264]: K[d][j]; reused as P[r][264]
    float* Vs = sm + 64 * 68 + 64 * 264;  // [256][68]: V^T[j][d]

    const int tid = threadIdx.x;
    const int tx = tid & 31, ty = tid >> 5;
    const int qt = blockIdx.x, h = blockIdx.y, z = blockIdx.z;
    const int t = z >> 3, b = z & 7;

    const float* qg = qbuf + ((size_t)z * 512 + h * 64) * 1024 + qt * 64;
    const size_t kvo = ((size_t)((1 - t) * 8 + b) * 1024 + h * 64) * 256;
    const float* kg = kvbuf + kvo;
    const float* vg = kvbuf + kvo + (size_t)512 * 256;

    // ---- stage Q (pre-scaled), K, V(transposed) ----
    {
        int d = tid >> 2;
        int c4 = (tid & 3) * 4;
#pragma unroll
        for (int ii = 0; ii < 4; ii++) {
            int r = c4 + ii * 16;
            float4 v = *(const float4*)&qg[(size_t)d * 1024 + r];
            v.x *= ATT_SCALE; v.y *= ATT_SCALE; v.z *= ATT_SCALE; v.w *= ATT_SCALE;
            *(float4*)&Qs[d * 68 + r] = v;
        }
#pragma unroll
        for (int ii = 0; ii < 16; ii++) {
            int j = c4 + ii * 16;
            *(float4*)&KP[d * 264 + j] = *(const float4*)&kg[d * 256 + j];
        }
#pragma unroll
        for (int ii = 0; ii < 16; ii++) {
            int j = c4 + ii * 16;
            float4 v = *(const float4*)&vg[d * 256 + j];
            Vs[(j + 0) * 68 + d] = v.x;
            Vs[(j + 1) * 68 + d] = v.y;
            Vs[(j + 2) * 68 + d] = v.z;
            Vs[(j + 3) * 68 + d] = v.w;
        }
    }
    __syncthreads();

    // ---- GEMM1: S[r][j] = (scaled Q)^T K ; r = ty*8+i, j = tx*2 + 64*k + {0,1} ----
    u64 acc[8][4];
#pragma unroll
    for (int i = 0; i < 8; i++)
#pragma unroll
        for (int k = 0; k < 4; k++) acc[i][k] = 0ull;

#pragma unroll 2
    for (int d = 0; d < 64; d++) {
        float4 q0 = *(const float4*)&Qs[d * 68 + ty * 8];
        float4 q1 = *(const float4*)&Qs[d * 68 + ty * 8 + 4];
        u64 kp[4];
#pragma unroll
        for (int k = 0; k < 4; k++)
            kp[k] = *(const u64*)&KP[d * 264 + tx * 2 + 64 * k];
        u64 qp[8];
        qp[0] = pk2(q0.x); qp[1] = pk2(q0.y); qp[2] = pk2(q0.z); qp[3] = pk2(q0.w);
        qp[4] = pk2(q1.x); qp[5] = pk2(q1.y); qp[6] = pk2(q1.z); qp[7] = pk2(q1.w);
#pragma unroll
        for (int i = 0; i < 8; i++)
#pragma unroll
            for (int k = 0; k < 4; k++)
                fma2(acc[i][k], qp[i], kp[k]);
    }
    __syncthreads();   // all K reads done before P overwrites KP

    // ---- softmax over j (each warp handles row r together via shfl) ----
#pragma unroll
    for (int i = 0; i < 8; i++) {
        float f[8];
#pragma unroll
        for (int k = 0; k < 4; k++) {
            float2 p = up2(acc[i][k]);
            f[2 * k] = p.x; f[2 * k + 1] = p.y;
        }
        float m = f[0];
#pragma unroll
        for (int k = 1; k < 8; k++) m = fmaxf(m, f[k]);
#pragma unroll
        for (int o = 16; o > 0; o >>= 1) m = fmaxf(m, __shfl_xor_sync(0xffffffffu, m, o));
        float s = 0.f;
#pragma unroll
        for (int k = 0; k < 8; k++) { f[k] = __expf(f[k] - m); s += f[k]; }
#pragma unroll
        for (int o = 16; o > 0; o >>= 1) s += __shfl_xor_sync(0xffffffffu, s, o);
        float inv = 1.f / s;
        int r = ty * 8 + i;
#pragma unroll
        for (int k = 0; k < 4; k++)
            *(float2*)&KP[r * 264 + tx * 2 + 64 * k] =
                make_float2(f[2 * k] * inv, f[2 * k + 1] * inv);
    }
    __syncthreads();

    // ---- GEMM2: out[r][d] = P V^T ; d = tx*2 + {0,1} ----
    u64 o2[8];
#pragma unroll
    for (int i = 0; i < 8; i++) o2[i] = 0ull;
    for (int j = 0; j < 256; j += 4) {
        u64 vv[4];
#pragma unroll
        for (int jj = 0; jj < 4; jj++)
            vv[jj] = *(const u64*)&Vs[(j + jj) * 68 + tx * 2];
#pragma unroll
        for (int i = 0; i < 8; i++) {
            float4 pv = *(const float4*)&KP[(ty * 8 + i) * 264 + j];
            fma2(o2[i], pk2(pv.x), vv[0]);
            fma2(o2[i], pk2(pv.y), vv[1]);
            fma2(o2[i], pk2(pv.z), vv[2]);
            fma2(o2[i], pk2(pv.w), vv[3]);
        }
    }

    // ---- transpose through smem (reuse Qs as Os[d][r]) for coalesced stores ----
#pragma unroll
    for (int i = 0; i < 8; i++) {
        float2 p = up2(o2[i]);
        Qs[(tx * 2 + 0) * 68 + ty * 8 + i] = p.x;
        Qs[(tx * 2 + 1) * 68 + ty * 8 + i] = p.y;
    }
    __syncthreads();
    {
        float* og = obuf + ((size_t)z * 512 + h * 64) * 1024 + qt * 64;
        int d = tid >> 2;
        int c4 = (tid & 3) * 4;
#pragma unroll
        for (int ii = 0; ii < 4; ii++) {
            int r = c4 + ii * 16;
            *(float4*)&og[(size_t)d * 1024 + r] = *(const float4*)&Qs[d * 68 + r];
        }
    }
}

// ---------------- launch ----------------
extern "C" void kernel_launch(void* const* d_in, const int* in_sizes, int n_in,
                              void* d_out, int out_size) {
    const float* x        = (const float*)d_in[0];
    const float* y        = (const float*)d_in[1];
    const float* q_dw_w   = (const float*)d_in[2];
    const float* q_bn_g   = (const float*)d_in[3];
    const float* q_bn_b   = (const float*)d_in[4];
    const float* q_bn_m   = (const float*)d_in[5];
    const float* q_bn_v   = (const float*)d_in[6];
    const float* q_pw_w   = (const float*)d_in[7];
    const float* kv_dw_w  = (const float*)d_in[8];
    const float* kv_bn_g  = (const float*)d_in[9];
    const float* kv_bn_b  = (const float*)d_in[10];
    const float* kv_bn_m  = (const float*)d_in[11];
    const float* kv_bn_v  = (const float*)d_in[12];
    const float* kv_pw_w  = (const float*)d_in[13];
    const float* out_w    = (const float*)d_in[14];
    const float* out_b    = (const float*)d_in[15];
    float* out = (float*)d_out;

    float *p_hq, *p_hkv, *p_q, *p_kv, *p_ao;
    cudaGetSymbolAddress((void**)&p_hq,  g_hq);
    cudaGetSymbolAddress((void**)&p_hkv, g_hkv);
    cudaGetSymbolAddress((void**)&p_q,   g_q);
    cudaGetSymbolAddress((void**)&p_kv,  g_kv);
    cudaGetSymbolAddress((void**)&p_ao,  g_ao);

    const int attn_smem = (64 * 68 + 64 * 264 + 256 * 68) * 4;  // 154624 B
    cudaFuncSetAttribute(attn_kernel,
                         cudaFuncAttributeMaxDynamicSharedMemorySize, attn_smem);

    const int n_s1 = 8 * 256 * 32 * 32;   // 2,097,152
    const int n_s2 = 8 * 256 * 16 * 16;   //   524,288
    const int half_s1 = 8 * 256 * 1024;   // per-side hq elements
    const int half_s2 = 8 * 256 * 256;

    // 1) depthwise + BN : q path (stride 1) on x and y
    dw_bn_kernel<<<(n_s1 + 255) / 256, 256>>>(
        x, q_dw_w, q_bn_g, q_bn_b, q_bn_m, q_bn_v, p_hq, 1, 32);
    dw_bn_kernel<<<(n_s1 + 255) / 256, 256>>>(
        y, q_dw_w, q_bn_g, q_bn_b, q_bn_m, q_bn_v, p_hq + half_s1, 1, 32);
    //    kv path (stride 2) on x and y
    dw_bn_kernel<<<(n_s2 + 255) / 256, 256>>>(
        x, kv_dw_w, kv_bn_g, kv_bn_b, kv_bn_m, kv_bn_v, p_hkv, 2, 16);
    dw_bn_kernel<<<(n_s2 + 255) / 256, 256>>>(
        y, kv_dw_w, kv_bn_g, kv_bn_b, kv_bn_m, kv_bn_v, p_hkv + half_s2, 2, 16);

    // 2) q pointwise: [512,256] x [256,1024] per z
    {
        dim3 grid(1024 / 64, 512 / 64, 16);
        gemm64<<<grid, 256>>>(q_pw_w, p_hq, p_q, nullptr, 512, 1024, 256);
    }
    // 3) kv pointwise: [1024,256] x [256,256] per z
    {
        dim3 grid(256 / 64, 1024 / 64, 16);
        gemm64<<<grid, 256>>>(kv_pw_w, p_hkv, p_kv, nullptr, 1024, 256, 256);
    }
    // 4) fused cross-attention
    {
        dim3 grid(16, 8, 16);
        attn_kernel<<<grid, 256, attn_smem>>>(p_q, p_kv, p_ao);
    }
    // 5) output projection: [256,512] x [512,1024] per z, + bias
    {
        dim3 grid(1024 / 64, 256 / 64, 16);
        gemm64<<<grid, 256>>>(out_w, p_ao, out, out_b, 256, 1024, 512);
    }
}

// round 4
// speedup vs baseline: 1.2288x; 1.2288x over previous
#include <cuda_runtime.h>
#include <cuda_bf16.h>
#include <math.h>
#include <cstdint>

#define BN_EPS 1e-5f
#define ATT_SCALE 0.125f   // 64^-0.5

typedef unsigned long long u64;

// ==================== packed f32x2 helpers ====================
__device__ __forceinline__ u64 pk2(float v) {
    u64 r; asm("mov.b64 %0, {%1, %1};" : "=l"(r) : "f"(v)); return r;
}
__device__ __forceinline__ void fma2(u64 &d, u64 a, u64 b) {
    asm("fma.rn.f32x2 %0, %1, %2, %0;" : "+l"(d) : "l"(a), "l"(b));
}
__device__ __forceinline__ float2 up2(u64 v) {
    float2 r; asm("mov.b64 {%0, %1}, %2;" : "=f"(r.x), "=f"(r.y) : "l"(v)); return r;
}

// ==================== mma.sync helpers (baseline PTX, works on sm_103) ====================
__device__ __forceinline__ uint32_t smem_u32(const void* p) {
    uint32_t a;
    asm("{ .reg .u64 t; cvta.to.shared.u64 t, %1; cvt.u32.u64 %0, t; }" : "=r"(a) : "l"(p));
    return a;
}
__device__ __forceinline__ void ldm_x4(uint32_t* r, uint32_t addr) {
    asm volatile("ldmatrix.sync.aligned.m8n8.x4.shared.b16 {%0,%1,%2,%3}, [%4];"
                 : "=r"(r[0]), "=r"(r[1]), "=r"(r[2]), "=r"(r[3]) : "r"(addr));
}
__device__ __forceinline__ void mma16816(float* d, const uint32_t* a, const uint32_t* b) {
    asm volatile("mma.sync.aligned.m16n8k16.row.col.f32.bf16.bf16.f32 "
        "{%0,%1,%2,%3}, {%4,%5,%6,%7}, {%8,%9}, {%0,%1,%2,%3};"
        : "+f"(d[0]), "+f"(d[1]), "+f"(d[2]), "+f"(d[3])
        : "r"(a[0]), "r"(a[1]), "r"(a[2]), "r"(a[3]), "r"(b[0]), "r"(b[1]));
}

// ==================== scratch ====================
// z = t*8 + b : t=0 -> x side, t=1 -> y side
__device__ float g_hq [16u * 256 * 1024];               // dw+bn stride1 [z][256][1024]
__device__ float g_hkv[16u * 256 * 256];                // dw+bn stride2 [z][256][256]
__device__ __nv_bfloat16 g_hqT_hi [16u * 1024 * 256];   // [z][hw][c]
__device__ __nv_bfloat16 g_hqT_lo [16u * 1024 * 256];
__device__ __nv_bfloat16 g_hkvT_hi[16u * 256 * 256];
__device__ __nv_bfloat16 g_hkvT_lo[16u * 256 * 256];
__device__ __nv_bfloat16 g_wq_hi [512 * 256],  g_wq_lo [512 * 256];
__device__ __nv_bfloat16 g_wkv_hi[1024 * 256], g_wkv_lo[1024 * 256];
__device__ __nv_bfloat16 g_wo_hi [256 * 512],  g_wo_lo [256 * 512];
__device__ float g_q [16u * 512 * 1024];                // [z][512][1024]
__device__ float g_kv[16u * 1024 * 256];                // [z][1024][256]
__device__ __nv_bfloat16 g_ao_hi[16u * 1024 * 512];     // attn out [z][pos][ch]
__device__ __nv_bfloat16 g_ao_lo[16u * 1024 * 512];

// ==================== depthwise 3x3 conv + BN (eval) ====================
__global__ void dw_bn_kernel(const float* __restrict__ in, const float* __restrict__ w,
                             const float* __restrict__ gamma, const float* __restrict__ beta,
                             const float* __restrict__ mean, const float* __restrict__ var,
                             float* __restrict__ out, int stride, int HO) {
    int idx = blockIdx.x * blockDim.x + threadIdx.x;
    int total = 8 * 256 * HO * HO;
    if (idx >= total) return;
    int ow = idx % HO;
    int oh = (idx / HO) % HO;
    int c  = (idx / (HO * HO)) % 256;
    int b  = idx / (HO * HO * 256);
    const float* ip = in + (size_t)(b * 256 + c) * 1024;
    const float* wp = w + c * 9;
    float acc = 0.f;
    int ih0 = oh * stride - 1, iw0 = ow * stride - 1;
#pragma unroll
    for (int kh = 0; kh < 3; kh++) {
        int ih = ih0 + kh;
        if (ih < 0 || ih > 31) continue;
#pragma unroll
        for (int kw = 0; kw < 3; kw++) {
            int iw = iw0 + kw;
            if (iw < 0 || iw > 31) continue;
            acc += wp[kh * 3 + kw] * ip[ih * 32 + iw];
        }
    }
    float sc = gamma[c] * rsqrtf(var[c] + BN_EPS);
    float sh = beta[c] - mean[c] * sc;
    out[idx] = acc * sc + sh;
}

// ==================== split helpers ====================
__global__ void wsplit_kernel(const float* __restrict__ in,
                              __nv_bfloat16* __restrict__ hi,
                              __nv_bfloat16* __restrict__ lo, int n) {
    int i = blockIdx.x * 256 + threadIdx.x;
    if (i >= n) return;
    float v = in[i];
    __nv_bfloat16 h = __float2bfloat16(v);
    hi[i] = h;
    lo[i] = __float2bfloat16(v - __bfloat162float(h));
}

// [z][C][HW] fp32 -> [z][HW][C] bf16 hi/lo  (32x32 tile transpose)
__global__ void tsplit_kernel(const float* __restrict__ in,
                              __nv_bfloat16* __restrict__ hi,
                              __nv_bfloat16* __restrict__ lo, int C, int HW) {
    __shared__ float t[32][33];
    int z = blockIdx.z;
    int hw0 = blockIdx.x * 32, c0 = blockIdx.y * 32;
    const float* ip = in + (size_t)z * C * HW;
    int tx = threadIdx.x, ty = threadIdx.y;   // (32, 8)
#pragma unroll
    for (int r = 0; r < 4; r++)
        t[ty + r * 8][tx] = ip[(size_t)(c0 + ty + r * 8) * HW + hw0 + tx];
    __syncthreads();
    size_t ob = (size_t)z * HW * C;
#pragma unroll
    for (int r = 0; r < 4; r++) {
        float v = t[tx][ty + r * 8];
        __nv_bfloat16 h = __float2bfloat16(v);
        size_t o = ob + (size_t)(hw0 + ty + r * 8) * C + c0 + tx;
        hi[o] = h;
        lo[o] = __float2bfloat16(v - __bfloat162float(h));
    }
}

// ==================== mma.sync bf16-split GEMM ====================
// C[z][M][N] fp32 (+bias[m]) = A[M,K] x B[z][N,K]^T  (hi/lo split, 3 terms)
// grid (N/128, M/128, 16), 256 threads (8 warps, 4(M) x 2(N), warp tile 32x64)
#define SMS 40   // smem row stride in halves (80B -> conflict-optimal ldmatrix)

__global__ void __launch_bounds__(256)
gemm_mma(const __nv_bfloat16* __restrict__ Ahi, const __nv_bfloat16* __restrict__ Alo,
         const __nv_bfloat16* __restrict__ Bhi, const __nv_bfloat16* __restrict__ Blo,
         float* __restrict__ C, const float* __restrict__ bias,
         int M, int N, int K) {
    __shared__ __align__(16) __nv_bfloat16 sAh[128 * SMS];
    __shared__ __align__(16) __nv_bfloat16 sAl[128 * SMS];
    __shared__ __align__(16) __nv_bfloat16 sBh[128 * SMS];
    __shared__ __align__(16) __nv_bfloat16 sBl[128 * SMS];

    const int tid = threadIdx.x, lane = tid & 31, wid = tid >> 5;
    const int warp_m = wid & 3, warp_n = wid >> 2;
    const int m0 = blockIdx.y * 128, n0 = blockIdx.x * 128, z = blockIdx.z;

    const __nv_bfloat16* Bh = Bhi + (size_t)z * N * K;
    const __nv_bfloat16* Bl = Blo + (size_t)z * N * K;

    float acc[2][8][4];
#pragma unroll
    for (int i = 0; i < 2; i++)
#pragma unroll
        for (int j = 0; j < 8; j++)
#pragma unroll
            for (int k = 0; k < 4; k++) acc[i][j][k] = 0.f;

    const int rid = tid >> 2;            // 0..63
    const int cid = (tid & 3) * 8;       // half offset within 32-half row chunk

    // ldmatrix smem addresses (bytes)
    const uint32_t sAh_b = smem_u32(sAh), sAl_b = smem_u32(sAl);
    const uint32_t sBh_b = smem_u32(sBh), sBl_b = smem_u32(sBl);
    // A: lanes 0-15 rows r0..r15 @ colk, lanes 16-31 same rows @ colk+8
    const int a_row = warp_m * 32 + (lane & 15);
    const int a_colx = (lane >> 4) << 3;
    // B: lanes 0-7 n0-7@k0, 8-15 n0-7@k8, 16-23 n8-15@k0, 24-31 n8-15@k8
    const int b_row = warp_n * 64 + (lane & 7) + ((lane >> 4) << 3);
    const int b_colx = ((lane >> 3) & 1) << 3;

    for (int k0 = 0; k0 < K; k0 += 32) {
        // ---- stage tiles (each thread: rows rid, rid+64; 16B per row-chunk) ----
        {
            const int r0g = rid, r1g = rid + 64;
            uint32_t s0 = (uint32_t)(r0g * SMS + cid) * 2;
            uint32_t s1 = (uint32_t)(r1g * SMS + cid) * 2;
            *(uint4*)((char*)sAh + s0) = *(const uint4*)&Ahi[(size_t)(m0 + r0g) * K + k0 + cid];
            *(uint4*)((char*)sAh + s1) = *(const uint4*)&Ahi[(size_t)(m0 + r1g) * K + k0 + cid];
            *(uint4*)((char*)sAl + s0) = *(const uint4*)&Alo[(size_t)(m0 + r0g) * K + k0 + cid];
            *(uint4*)((char*)sAl + s1) = *(const uint4*)&Alo[(size_t)(m0 + r1g) * K + k0 + cid];
            *(uint4*)((char*)sBh + s0) = *(const uint4*)&Bh[(size_t)(n0 + r0g) * K + k0 + cid];
            *(uint4*)((char*)sBh + s1) = *(const uint4*)&Bh[(size_t)(n0 + r1g) * K + k0 + cid];
            *(uint4*)((char*)sBl + s0) = *(const uint4*)&Bl[(size_t)(n0 + r0g) * K + k0 + cid];
            *(uint4*)((char*)sBl + s1) = *(const uint4*)&Bl[(size_t)(n0 + r1g) * K + k0 + cid];
        }
        __syncthreads();

#pragma unroll
        for (int ks = 0; ks < 2; ks++) {
            const int kc = ks * 16;
            uint32_t ah[2][4], al[2][4];
#pragma unroll
            for (int mt = 0; mt < 2; mt++) {
                uint32_t off = (uint32_t)((a_row + mt * 16) * SMS + kc + a_colx) * 2;
                ldm_x4(ah[mt], sAh_b + off);
                ldm_x4(al[mt], sAl_b + off);
            }
#pragma unroll
            for (int ng = 0; ng < 4; ng++) {
                uint32_t bh[4], bl[4];
                uint32_t off = (uint32_t)((b_row + ng * 16) * SMS + kc + b_colx) * 2;
                ldm_x4(bh, sBh_b + off);
                ldm_x4(bl, sBl_b + off);
#pragma unroll
                for (int mt = 0; mt < 2; mt++)
#pragma unroll
                    for (int nt = 0; nt < 2; nt++) {
                        float* c = acc[mt][ng * 2 + nt];
                        mma16816(c, ah[mt], &bh[nt * 2]);
                        mma16816(c, ah[mt], &bl[nt * 2]);
                        mma16816(c, al[mt], &bh[nt * 2]);
                    }
            }
        }
        __syncthreads();
    }

    // ---- epilogue ----
    float* Cz = C + (size_t)z * M * N;
#pragma unroll
    for (int mt = 0; mt < 2; mt++) {
        int mrow0 = m0 + warp_m * 32 + mt * 16 + (lane >> 2);
        int mrow1 = mrow0 + 8;
        float bv0 = bias ? bias[mrow0] : 0.f;
        float bv1 = bias ? bias[mrow1] : 0.f;
#pragma unroll
        for (int j = 0; j < 8; j++) {
            int n = n0 + warp_n * 64 + j * 8 + (lane & 3) * 2;
            float* c = acc[mt][j];
            *(float2*)&Cz[(size_t)mrow0 * N + n] = make_float2(c[0] + bv0, c[1] + bv0);
            *(float2*)&Cz[(size_t)mrow1 * N + n] = make_float2(c[2] + bv1, c[3] + bv1);
        }
    }
}

// ==================== fused cross-attention (fp32 f32x2) ====================
// grid (16 qtiles, 8 heads, 16 z). Output: bf16 hi/lo at [z][pos][512].
__global__ void __launch_bounds__(256, 1)
attn_kernel(const float* __restrict__ qbuf, const float* __restrict__ kvbuf,
            __nv_bfloat16* __restrict__ ao_hi, __nv_bfloat16* __restrict__ ao_lo) {
    extern __shared__ float sm[];
    float* Qs = sm;                       // [64][68]: scaled Q[d][r]
    float* KP = sm + 64 * 68;             // [64][264]: K[d][j]; reused as P[r][264]
    float* Vs = sm + 64 * 68 + 64 * 264;  // [256][68]: V^T[j][d]

    const int tid = threadIdx.x;
    const int tx = tid & 31, ty = tid >> 5;
    const int qt = blockIdx.x, h = blockIdx.y, z = blockIdx.z;
    const int t = z >> 3, b = z & 7;

    const float* qg = qbuf + ((size_t)z * 512 + h * 64) * 1024 + qt * 64;
    const size_t kvo = ((size_t)((1 - t) * 8 + b) * 1024 + h * 64) * 256;
    const float* kg = kvbuf + kvo;
    const float* vg = kvbuf + kvo + (size_t)512 * 256;

    {
        int d = tid >> 2;
        int c4 = (tid & 3) * 4;
#pragma unroll
        for (int ii = 0; ii < 4; ii++) {
            int r = c4 + ii * 16;
            float4 v = *(const float4*)&qg[(size_t)d * 1024 + r];
            v.x *= ATT_SCALE; v.y *= ATT_SCALE; v.z *= ATT_SCALE; v.w *= ATT_SCALE;
            *(float4*)&Qs[d * 68 + r] = v;
        }
#pragma unroll
        for (int ii = 0; ii < 16; ii++) {
            int j = c4 + ii * 16;
            *(float4*)&KP[d * 264 + j] = *(const float4*)&kg[d * 256 + j];
        }
#pragma unroll
        for (int ii = 0; ii < 16; ii++) {
            int j = c4 + ii * 16;
            float4 v = *(const float4*)&vg[d * 256 + j];
            Vs[(j + 0) * 68 + d] = v.x;
            Vs[(j + 1) * 68 + d] = v.y;
            Vs[(j + 2) * 68 + d] = v.z;
            Vs[(j + 3) * 68 + d] = v.w;
        }
    }
    __syncthreads();

    // GEMM1: S[r][j] = (scaled Q)^T K
    u64 acc[8][4];
#pragma unroll
    for (int i = 0; i < 8; i++)
#pragma unroll
        for (int k = 0; k < 4; k++) acc[i][k] = 0ull;

#pragma unroll 2
    for (int d = 0; d < 64; d++) {
        float4 q0 = *(const float4*)&Qs[d * 68 + ty * 8];
        float4 q1 = *(const float4*)&Qs[d * 68 + ty * 8 + 4];
        u64 kp[4];
#pragma unroll
        for (int k = 0; k < 4; k++)
            kp[k] = *(const u64*)&KP[d * 264 + tx * 2 + 64 * k];
        u64 qp[8];
        qp[0] = pk2(q0.x); qp[1] = pk2(q0.y); qp[2] = pk2(q0.z); qp[3] = pk2(q0.w);
        qp[4] = pk2(q1.x); qp[5] = pk2(q1.y); qp[6] = pk2(q1.z); qp[7] = pk2(q1.w);
#pragma unroll
        for (int i = 0; i < 8; i++)
#pragma unroll
            for (int k = 0; k < 4; k++)
                fma2(acc[i][k], qp[i], kp[k]);
    }
    __syncthreads();

    // softmax over j
#pragma unroll
    for (int i = 0; i < 8; i++) {
        float f[8];
#pragma unroll
        for (int k = 0; k < 4; k++) {
            float2 p = up2(acc[i][k]);
            f[2 * k] = p.x; f[2 * k + 1] = p.y;
        }
        float m = f[0];
#pragma unroll
        for (int k = 1; k < 8; k++) m = fmaxf(m, f[k]);
#pragma unroll
        for (int o = 16; o > 0; o >>= 1) m = fmaxf(m, __shfl_xor_sync(0xffffffffu, m, o));
        float s = 0.f;
#pragma unroll
        for (int k = 0; k < 8; k++) { f[k] = __expf(f[k] - m); s += f[k]; }
#pragma unroll
        for (int o = 16; o > 0; o >>= 1) s += __shfl_xor_sync(0xffffffffu, s, o);
        float inv = 1.f / s;
        int r = ty * 8 + i;
#pragma unroll
        for (int k = 0; k < 4; k++)
            *(float2*)&KP[r * 264 + tx * 2 + 64 * k] =
                make_float2(f[2 * k] * inv, f[2 * k + 1] * inv);
    }
    __syncthreads();

    // GEMM2: out[r][d] = P V^T
    u64 o2[8];
#pragma unroll
    for (int i = 0; i < 8; i++) o2[i] = 0ull;
    for (int j = 0; j < 256; j += 4) {
        u64 vv[4];
#pragma unroll
        for (int jj = 0; jj < 4; jj++)
            vv[jj] = *(const u64*)&Vs[(j + jj) * 68 + tx * 2];
#pragma unroll
        for (int i = 0; i < 8; i++) {
            float4 pv = *(const float4*)&KP[(ty * 8 + i) * 264 + j];
            fma2(o2[i], pk2(pv.x), vv[0]);
            fma2(o2[i], pk2(pv.y), vv[1]);
            fma2(o2[i], pk2(pv.z), vv[2]);
            fma2(o2[i], pk2(pv.w), vv[3]);
        }
    }

    // write bf16 hi/lo directly at [z][pos][512]
#pragma unroll
    for (int i = 0; i < 8; i++) {
        float2 p = up2(o2[i]);
        __nv_bfloat16 h0 = __float2bfloat16(p.x);
        __nv_bfloat16 h1 = __float2bfloat16(p.y);
        __nv_bfloat162 hh; hh.x = h0; hh.y = h1;
        __nv_bfloat162 ll;
        ll.x = __float2bfloat16(p.x - __bfloat162float(h0));
        ll.y = __float2bfloat16(p.y - __bfloat162float(h1));
        size_t off = ((size_t)z * 1024 + qt * 64 + ty * 8 + i) * 512 + h * 64 + tx * 2;
        *(__nv_bfloat162*)(ao_hi + off) = hh;
        *(__nv_bfloat162*)(ao_lo + off) = ll;
    }
}

// ==================== launch ====================
extern "C" void kernel_launch(void* const* d_in, const int* in_sizes, int n_in,
                              void* d_out, int out_size) {
    const float* x        = (const float*)d_in[0];
    const float* y        = (const float*)d_in[1];
    const float* q_dw_w   = (const float*)d_in[2];
    const float* q_bn_g   = (const float*)d_in[3];
    const float* q_bn_b   = (const float*)d_in[4];
    const float* q_bn_m   = (const float*)d_in[5];
    const float* q_bn_v   = (const float*)d_in[6];
    const float* q_pw_w   = (const float*)d_in[7];
    const float* kv_dw_w  = (const float*)d_in[8];
    const float* kv_bn_g  = (const float*)d_in[9];
    const float* kv_bn_b  = (const float*)d_in[10];
    const float* kv_bn_m  = (const float*)d_in[11];
    const float* kv_bn_v  = (const float*)d_in[12];
    const float* kv_pw_w  = (const float*)d_in[13];
    const float* out_w    = (const float*)d_in[14];
    const float* out_b    = (const float*)d_in[15];
    float* out = (float*)d_out;

    float *p_hq, *p_hkv, *p_q, *p_kv;
    __nv_bfloat16 *p_hqT_hi, *p_hqT_lo, *p_hkvT_hi, *p_hkvT_lo;
    __nv_bfloat16 *p_wq_hi, *p_wq_lo, *p_wkv_hi, *p_wkv_lo, *p_wo_hi, *p_wo_lo;
    __nv_bfloat16 *p_ao_hi, *p_ao_lo;
    cudaGetSymbolAddress((void**)&p_hq,  g_hq);
    cudaGetSymbolAddress((void**)&p_hkv, g_hkv);
    cudaGetSymbolAddress((void**)&p_q,   g_q);
    cudaGetSymbolAddress((void**)&p_kv,  g_kv);
    cudaGetSymbolAddress((void**)&p_hqT_hi,  g_hqT_hi);
    cudaGetSymbolAddress((void**)&p_hqT_lo,  g_hqT_lo);
    cudaGetSymbolAddress((void**)&p_hkvT_hi, g_hkvT_hi);
    cudaGetSymbolAddress((void**)&p_hkvT_lo, g_hkvT_lo);
    cudaGetSymbolAddress((void**)&p_wq_hi,  g_wq_hi);
    cudaGetSymbolAddress((void**)&p_wq_lo,  g_wq_lo);
    cudaGetSymbolAddress((void**)&p_wkv_hi, g_wkv_hi);
    cudaGetSymbolAddress((void**)&p_wkv_lo, g_wkv_lo);
    cudaGetSymbolAddress((void**)&p_wo_hi,  g_wo_hi);
    cudaGetSymbolAddress((void**)&p_wo_lo,  g_wo_lo);
    cudaGetSymbolAddress((void**)&p_ao_hi,  g_ao_hi);
    cudaGetSymbolAddress((void**)&p_ao_lo,  g_ao_lo);

    const int attn_smem = (64 * 68 + 64 * 264 + 256 * 68) * 4;  // 154624 B
    cudaFuncSetAttribute(attn_kernel,
                         cudaFuncAttributeMaxDynamicSharedMemorySize, attn_smem);

    const int n_s1 = 8 * 256 * 32 * 32;
    const int n_s2 = 8 * 256 * 16 * 16;
    const int half_s1 = 8 * 256 * 1024;
    const int half_s2 = 8 * 256 * 256;

    // 1) depthwise + BN
    dw_bn_kernel<<<(n_s1 + 255) / 256, 256>>>(
        x, q_dw_w, q_bn_g, q_bn_b, q_bn_m, q_bn_v, p_hq, 1, 32);
    dw_bn_kernel<<<(n_s1 + 255) / 256, 256>>>(
        y, q_dw_w, q_bn_g, q_bn_b, q_bn_m, q_bn_v, p_hq + half_s1, 1, 32);
    dw_bn_kernel<<<(n_s2 + 255) / 256, 256>>>(
        x, kv_dw_w, kv_bn_g, kv_bn_b, kv_bn_m, kv_bn_v, p_hkv, 2, 16);
    dw_bn_kernel<<<(n_s2 + 255) / 256, 256>>>(
        y, kv_dw_w, kv_bn_g, kv_bn_b, kv_bn_m, kv_bn_v, p_hkv + half_s2, 2, 16);

    // 2) weight + activation hi/lo splits (activations transposed to [z][hw][c])
    wsplit_kernel<<<512, 256>>>(q_pw_w,  p_wq_hi,  p_wq_lo,  512 * 256);
    wsplit_kernel<<<1024, 256>>>(kv_pw_w, p_wkv_hi, p_wkv_lo, 1024 * 256);
    wsplit_kernel<<<512, 256>>>(out_w,   p_wo_hi,  p_wo_lo,  256 * 512);
    {
        dim3 blk(32, 8);
        dim3 g1(1024 / 32, 256 / 32, 16);
        tsplit_kernel<<<g1, blk>>>(p_hq, p_hqT_hi, p_hqT_lo, 256, 1024);
        dim3 g2(256 / 32, 256 / 32, 16);
        tsplit_kernel<<<g2, blk>>>(p_hkv, p_hkvT_hi, p_hkvT_lo, 256, 256);
    }

    // 3) q pointwise: [512,256] x [256,1024] per z -> g_q [z][512][1024]
    {
        dim3 grid(1024 / 128, 512 / 128, 16);
        gemm_mma<<<grid, 256>>>(p_wq_hi, p_wq_lo, p_hqT_hi, p_hqT_lo,
                                p_q, nullptr, 512, 1024, 256);
    }
    // 4) kv pointwise: [1024,256] x [256,256] per z -> g_kv [z][1024][256]
    {
        dim3 grid(256 / 128, 1024 / 128, 16);
        gemm_mma<<<grid, 256>>>(p_wkv_hi, p_wkv_lo, p_hkvT_hi, p_hkvT_lo,
                                p_kv, nullptr, 1024, 256, 256);
    }
    // 5) fused cross-attention -> bf16 hi/lo [z][1024][512]
    {
        dim3 grid(16, 8, 16);
        attn_kernel<<<grid, 256, attn_smem>>>(p_q, p_kv, p_ao_hi, p_ao_lo);
    }
    // 6) output projection: [256,512] x [512,1024] per z + bias -> d_out
    {
        dim3 grid(1024 / 128, 256 / 128, 16);
        gemm_mma<<<grid, 256>>>(p_wo_hi, p_wo_lo, p_ao_hi, p_ao_lo,
                                out, out_b, 256, 1024, 512);
    }
}

// round 5
// speedup vs baseline: 1.8550x; 1.5095x over previous
#include <cuda_runtime.h>
#include <cuda_bf16.h>
#include <math.h>
#include <cstdint>

#define BN_EPS 1e-5f

typedef unsigned long long u64;

// ==================== mma.sync helpers (baseline PTX, sm_103-safe) ====================
__device__ __forceinline__ uint32_t smem_u32(const void* p) {
    uint32_t a;
    asm("{ .reg .u64 t; cvta.to.shared.u64 t, %1; cvt.u32.u64 %0, t; }" : "=r"(a) : "l"(p));
    return a;
}
__device__ __forceinline__ void ldm_x4(uint32_t* r, uint32_t addr) {
    asm volatile("ldmatrix.sync.aligned.m8n8.x4.shared.b16 {%0,%1,%2,%3}, [%4];"
                 : "=r"(r[0]), "=r"(r[1]), "=r"(r[2]), "=r"(r[3]) : "r"(addr));
}
__device__ __forceinline__ void ldm_x4_t(uint32_t* r, uint32_t addr) {
    asm volatile("ldmatrix.sync.aligned.m8n8.x4.trans.shared.b16 {%0,%1,%2,%3}, [%4];"
                 : "=r"(r[0]), "=r"(r[1]), "=r"(r[2]), "=r"(r[3]) : "r"(addr));
}
__device__ __forceinline__ void mma16816(float* d, const uint32_t* a, const uint32_t* b) {
    asm volatile("mma.sync.aligned.m16n8k16.row.col.f32.bf16.bf16.f32 "
        "{%0,%1,%2,%3}, {%4,%5,%6,%7}, {%8,%9}, {%0,%1,%2,%3};"
        : "+f"(d[0]), "+f"(d[1]), "+f"(d[2]), "+f"(d[3])
        : "r"(a[0]), "r"(a[1]), "r"(a[2]), "r"(a[3]), "r"(b[0]), "r"(b[1]));
}
// pack (x,y) -> bf16x2 hi word + residual lo word  (x in low half)
__device__ __forceinline__ void split2(float x, float y, uint32_t &hi, uint32_t &lo) {
    asm("cvt.rn.bf16x2.f32 %0, %1, %2;" : "=r"(hi) : "f"(y), "f"(x));
    float xh = __uint_as_float(hi << 16);
    float yh = __uint_as_float(hi & 0xffff0000u);
    asm("cvt.rn.bf16x2.f32 %0, %1, %2;" : "=r"(lo) : "f"(y - yh), "f"(x - xh));
}

// ==================== scratch ====================
// z = t*8 + b : t=0 -> x side, t=1 -> y side
__device__ float g_hq [16u * 256 * 1024];               // dw+bn stride1 [z][256][1024]
__device__ float g_hkv[16u * 256 * 256];                // dw+bn stride2 [z][256][256]
__device__ __nv_bfloat16 g_hqT_hi [16u * 1024 * 256];   // [z][hw][c]
__device__ __nv_bfloat16 g_hqT_lo [16u * 1024 * 256];
__device__ __nv_bfloat16 g_hkvT_hi[16u * 256 * 256];
__device__ __nv_bfloat16 g_hkvT_lo[16u * 256 * 256];
__device__ __nv_bfloat16 g_wq_hi [512 * 256],  g_wq_lo [512 * 256];   // pre-scaled by 0.125
__device__ __nv_bfloat16 g_wkv_hi[1024 * 256], g_wkv_lo[1024 * 256];
__device__ __nv_bfloat16 g_wo_hi [256 * 512],  g_wo_lo [256 * 512];
__device__ __nv_bfloat16 g_qs_hi [16u * 1024 * 512], g_qs_lo [16u * 1024 * 512]; // q [z][pos][512]
__device__ __nv_bfloat16 g_kvs_hi[16u * 256 * 1024], g_kvs_lo[16u * 256 * 1024]; // kv [z][pos][1024]
__device__ __nv_bfloat16 g_ao_hi [16u * 1024 * 512], g_ao_lo [16u * 1024 * 512]; // attn out [z][pos][512]

// ==================== depthwise 3x3 conv + BN (eval) ====================
__global__ void dw_bn_kernel(const float* __restrict__ in, const float* __restrict__ w,
                             const float* __restrict__ gamma, const float* __restrict__ beta,
                             const float* __restrict__ mean, const float* __restrict__ var,
                             float* __restrict__ out, int stride, int HO) {
    int idx = blockIdx.x * blockDim.x + threadIdx.x;
    int total = 8 * 256 * HO * HO;
    if (idx >= total) return;
    int ow = idx % HO;
    int oh = (idx / HO) % HO;
    int c  = (idx / (HO * HO)) % 256;
    int b  = idx / (HO * HO * 256);
    const float* ip = in + (size_t)(b * 256 + c) * 1024;
    const float* wp = w + c * 9;
    float acc = 0.f;
    int ih0 = oh * stride - 1, iw0 = ow * stride - 1;
#pragma unroll
    for (int kh = 0; kh < 3; kh++) {
        int ih = ih0 + kh;
        if (ih < 0 || ih > 31) continue;
#pragma unroll
        for (int kw = 0; kw < 3; kw++) {
            int iw = iw0 + kw;
            if (iw < 0 || iw > 31) continue;
            acc += wp[kh * 3 + kw] * ip[ih * 32 + iw];
        }
    }
    float sc = gamma[c] * rsqrtf(var[c] + BN_EPS);
    float sh = beta[c] - mean[c] * sc;
    out[idx] = acc * sc + sh;
}

// ==================== split helpers ====================
__global__ void wsplit_kernel(const float* __restrict__ in,
                              __nv_bfloat16* __restrict__ hi,
                              __nv_bfloat16* __restrict__ lo, int n, float scale) {
    int i = blockIdx.x * 256 + threadIdx.x;
    if (i >= n) return;
    float v = in[i] * scale;
    __nv_bfloat16 h = __float2bfloat16(v);
    hi[i] = h;
    lo[i] = __float2bfloat16(v - __bfloat162float(h));
}

// [z][C][HW] fp32 -> [z][HW][C] bf16 hi/lo  (32x32 tile transpose)
__global__ void tsplit_kernel(const float* __restrict__ in,
                              __nv_bfloat16* __restrict__ hi,
                              __nv_bfloat16* __restrict__ lo, int C, int HW) {
    __shared__ float t[32][33];
    int z = blockIdx.z;
    int hw0 = blockIdx.x * 32, c0 = blockIdx.y * 32;
    const float* ip = in + (size_t)z * C * HW;
    int tx = threadIdx.x, ty = threadIdx.y;   // (32, 8)
#pragma unroll
    for (int r = 0; r < 4; r++)
        t[ty + r * 8][tx] = ip[(size_t)(c0 + ty + r * 8) * HW + hw0 + tx];
    __syncthreads();
    size_t ob = (size_t)z * HW * C;
#pragma unroll
    for (int r = 0; r < 4; r++) {
        float v = t[tx][ty + r * 8];
        __nv_bfloat16 h = __float2bfloat16(v);
        size_t o = ob + (size_t)(hw0 + ty + r * 8) * C + c0 + tx;
        hi[o] = h;
        lo[o] = __float2bfloat16(v - __bfloat162float(h));
    }
}

// ==================== mma.sync bf16-split GEMM ====================
// C[z][M][N] = A[z][M,K] x B[z][N,K]^T  (hi/lo split, 3 terms). strides select batching.
// SPLIT=false: fp32 out + bias[m].  SPLIT=true: bf16 hi/lo out.
#define SMS 40   // smem row stride in halves

template <bool SPLIT>
__global__ void __launch_bounds__(256)
gemm_mma(const __nv_bfloat16* __restrict__ Ahi, const __nv_bfloat16* __restrict__ Alo, size_t sA,
         const __nv_bfloat16* __restrict__ Bhi, const __nv_bfloat16* __restrict__ Blo, size_t sB,
         float* __restrict__ Cf, __nv_bfloat16* __restrict__ Chi, __nv_bfloat16* __restrict__ Clo,
         const float* __restrict__ bias, int M, int N, int K) {
    __shared__ __align__(16) __nv_bfloat16 sAh[128 * SMS];
    __shared__ __align__(16) __nv_bfloat16 sAl[128 * SMS];
    __shared__ __align__(16) __nv_bfloat16 sBh[128 * SMS];
    __shared__ __align__(16) __nv_bfloat16 sBl[128 * SMS];

    const int tid = threadIdx.x, lane = tid & 31, wid = tid >> 5;
    const int warp_m = wid & 3, warp_n = wid >> 2;
    const int m0 = blockIdx.y * 128, n0 = blockIdx.x * 128, z = blockIdx.z;

    const __nv_bfloat16* Ah = Ahi + (size_t)z * sA;
    const __nv_bfloat16* Al = Alo + (size_t)z * sA;
    const __nv_bfloat16* Bh = Bhi + (size_t)z * sB;
    const __nv_bfloat16* Bl = Blo + (size_t)z * sB;

    float acc[2][8][4];
#pragma unroll
    for (int i = 0; i < 2; i++)
#pragma unroll
        for (int j = 0; j < 8; j++)
#pragma unroll
            for (int k = 0; k < 4; k++) acc[i][j][k] = 0.f;

    const int rid = tid >> 2;            // 0..63
    const int cid = (tid & 3) * 8;       // half offset within 32-half row chunk

    const uint32_t sAh_b = smem_u32(sAh), sAl_b = smem_u32(sAl);
    const uint32_t sBh_b = smem_u32(sBh), sBl_b = smem_u32(sBl);
    const int a_row = warp_m * 32 + (lane & 15);
    const int a_colx = (lane >> 4) << 3;
    const int b_row = warp_n * 64 + (lane & 7) + ((lane >> 4) << 3);
    const int b_colx = ((lane >> 3) & 1) << 3;

    for (int k0 = 0; k0 < K; k0 += 32) {
        {
            const int r0g = rid, r1g = rid + 64;
            uint32_t s0 = (uint32_t)(r0g * SMS + cid) * 2;
            uint32_t s1 = (uint32_t)(r1g * SMS + cid) * 2;
            *(uint4*)((char*)sAh + s0) = *(const uint4*)&Ah[(size_t)(m0 + r0g) * K + k0 + cid];
            *(uint4*)((char*)sAh + s1) = *(const uint4*)&Ah[(size_t)(m0 + r1g) * K + k0 + cid];
            *(uint4*)((char*)sAl + s0) = *(const uint4*)&Al[(size_t)(m0 + r0g) * K + k0 + cid];
            *(uint4*)((char*)sAl + s1) = *(const uint4*)&Al[(size_t)(m0 + r1g) * K + k0 + cid];
            *(uint4*)((char*)sBh + s0) = *(const uint4*)&Bh[(size_t)(n0 + r0g) * K + k0 + cid];
            *(uint4*)((char*)sBh + s1) = *(const uint4*)&Bh[(size_t)(n0 + r1g) * K + k0 + cid];
            *(uint4*)((char*)sBl + s0) = *(const uint4*)&Bl[(size_t)(n0 + r0g) * K + k0 + cid];
            *(uint4*)((char*)sBl + s1) = *(const uint4*)&Bl[(size_t)(n0 + r1g) * K + k0 + cid];
        }
        __syncthreads();

#pragma unroll
        for (int ks = 0; ks < 2; ks++) {
            const int kc = ks * 16;
            uint32_t ah[2][4], al[2][4];
#pragma unroll
            for (int mt = 0; mt < 2; mt++) {
                uint32_t off = (uint32_t)((a_row + mt * 16) * SMS + kc + a_colx) * 2;
                ldm_x4(ah[mt], sAh_b + off);
                ldm_x4(al[mt], sAl_b + off);
            }
#pragma unroll
            for (int ng = 0; ng < 4; ng++) {
                uint32_t bh[4], bl[4];
                uint32_t off = (uint32_t)((b_row + ng * 16) * SMS + kc + b_colx) * 2;
                ldm_x4(bh, sBh_b + off);
                ldm_x4(bl, sBl_b + off);
#pragma unroll
                for (int mt = 0; mt < 2; mt++)
#pragma unroll
                    for (int nt = 0; nt < 2; nt++) {
                        float* c = acc[mt][ng * 2 + nt];
                        mma16816(c, ah[mt], &bh[nt * 2]);
                        mma16816(c, ah[mt], &bl[nt * 2]);
                        mma16816(c, al[mt], &bh[nt * 2]);
                    }
            }
        }
        __syncthreads();
    }

    // ---- epilogue ----
#pragma unroll
    for (int mt = 0; mt < 2; mt++) {
        int mrow0 = m0 + warp_m * 32 + mt * 16 + (lane >> 2);
        int mrow1 = mrow0 + 8;
        float bv0 = (!SPLIT && bias) ? bias[mrow0] : 0.f;
        float bv1 = (!SPLIT && bias) ? bias[mrow1] : 0.f;
#pragma unroll
        for (int j = 0; j < 8; j++) {
            int n = n0 + warp_n * 64 + j * 8 + (lane & 3) * 2;
            float* c = acc[mt][j];
            if (SPLIT) {
                uint32_t h0, l0, h1, l1;
                split2(c[0], c[1], h0, l0);
                split2(c[2], c[3], h1, l1);
                size_t o0 = (size_t)z * M * N + (size_t)mrow0 * N + n;
                size_t o1 = (size_t)z * M * N + (size_t)mrow1 * N + n;
                *(uint32_t*)&Chi[o0] = h0; *(uint32_t*)&Clo[o0] = l0;
                *(uint32_t*)&Chi[o1] = h1; *(uint32_t*)&Clo[o1] = l1;
            } else {
                float* Cz = Cf + (size_t)z * M * N;
                *(float2*)&Cz[(size_t)mrow0 * N + n] = make_float2(c[0] + bv0, c[1] + bv0);
                *(float2*)&Cz[(size_t)mrow1 * N + n] = make_float2(c[2] + bv1, c[3] + bv1);
            }
        }
    }
}

// ==================== tensor-core fused cross-attention ====================
// grid (8 qtiles(128), 8 heads, 16 z). 256 threads = 8 warps, warp = 16 rows x 256 kv.
// Q pre-scaled (0.125 folded into q weights). Output bf16 hi/lo at [z][pos][512].
#define ATT_S 72   // smem row stride in halves
#define AQH 0
#define AQL (128 * ATT_S)
#define AKH (2 * 128 * ATT_S)
#define AKL (AKH + 256 * ATT_S)
#define AVH (AKH + 2 * 256 * ATT_S)
#define AVL (AVH + 256 * ATT_S)
#define ATT_SMEM ((2 * 128 + 4 * 256) * ATT_S * 2)   // 184320 B

__global__ void __launch_bounds__(256, 1)
attn_mma(const __nv_bfloat16* __restrict__ qhi, const __nv_bfloat16* __restrict__ qlo,
         const __nv_bfloat16* __restrict__ kvhi, const __nv_bfloat16* __restrict__ kvlo,
         __nv_bfloat16* __restrict__ aohi, __nv_bfloat16* __restrict__ aolo) {
    extern __shared__ __nv_bfloat16 sm[];
    const int tid = threadIdx.x, lane = tid & 31, wid = tid >> 5;
    const int qt = blockIdx.x, h = blockIdx.y, z = blockIdx.z;
    const int zk = ((z >> 3) ^ 1) * 8 + (z & 7);

    // ---- stage Q (128x64), K (256x64), V (256x64) hi/lo ----
    {
        size_t qb = ((size_t)z * 1024 + qt * 128) * 512 + h * 64;
        for (int i = tid; i < 1024; i += 256) {
            int row = i >> 3, ch = (i & 7) * 8;
            *(uint4*)&sm[AQH + row * ATT_S + ch] = *(const uint4*)&qhi[qb + (size_t)row * 512 + ch];
            *(uint4*)&sm[AQL + row * ATT_S + ch] = *(const uint4*)&qlo[qb + (size_t)row * 512 + ch];
        }
        size_t kb = (size_t)zk * 256 * 1024 + h * 64;
        size_t vb = kb + 512;
        for (int i = tid; i < 2048; i += 256) {
            int row = i >> 3, ch = (i & 7) * 8;
            *(uint4*)&sm[AKH + row * ATT_S + ch] = *(const uint4*)&kvhi[kb + (size_t)row * 1024 + ch];
            *(uint4*)&sm[AKL + row * ATT_S + ch] = *(const uint4*)&kvlo[kb + (size_t)row * 1024 + ch];
            *(uint4*)&sm[AVH + row * ATT_S + ch] = *(const uint4*)&kvhi[vb + (size_t)row * 1024 + ch];
            *(uint4*)&sm[AVL + row * ATT_S + ch] = *(const uint4*)&kvlo[vb + (size_t)row * 1024 + ch];
        }
    }
    __syncthreads();

    const uint32_t smb = smem_u32(sm);
    const int r0 = wid * 16;

    // ---- S = Q K^T  (rows r0..r0+15, cols 0..255) ----
    float c[32][4];
#pragma unroll
    for (int t = 0; t < 32; t++)
#pragma unroll
        for (int k = 0; k < 4; k++) c[t][k] = 0.f;

    const int a_row = r0 + (lane & 15);
    const int a_cx = (lane >> 4) << 3;
    const int b_rx = (lane & 7) + ((lane >> 4) << 3);
    const int b_cx = ((lane >> 3) & 1) << 3;

#pragma unroll
    for (int kt = 0; kt < 4; kt++) {
        uint32_t aH[4], aL[4];
        uint32_t aoff = (uint32_t)(a_row * ATT_S + kt * 16 + a_cx) * 2;
        ldm_x4(aH, smb + AQH * 2 + aoff);
        ldm_x4(aL, smb + AQL * 2 + aoff);
#pragma unroll
        for (int jt = 0; jt < 16; jt++) {
            uint32_t bH[4], bL[4];
            uint32_t boff = (uint32_t)((jt * 16 + b_rx) * ATT_S + kt * 16 + b_cx) * 2;
            ldm_x4(bH, smb + AKH * 2 + boff);
            ldm_x4(bL, smb + AKL * 2 + boff);
#pragma unroll
            for (int nt = 0; nt < 2; nt++) {
                float* cc = c[jt * 2 + nt];
                mma16816(cc, aH, &bH[nt * 2]);
                mma16816(cc, aH, &bL[nt * 2]);
                mma16816(cc, aL, &bH[nt * 2]);
            }
        }
    }

    // ---- softmax (row rows: lane>>2 and +8; 4-lane quad shares a row) ----
    {
        float m0 = -1e30f, m1 = -1e30f;
#pragma unroll
        for (int t = 0; t < 32; t++) {
            m0 = fmaxf(m0, fmaxf(c[t][0], c[t][1]));
            m1 = fmaxf(m1, fmaxf(c[t][2], c[t][3]));
        }
        m0 = fmaxf(m0, __shfl_xor_sync(0xffffffffu, m0, 1));
        m0 = fmaxf(m0, __shfl_xor_sync(0xffffffffu, m0, 2));
        m1 = fmaxf(m1, __shfl_xor_sync(0xffffffffu, m1, 1));
        m1 = fmaxf(m1, __shfl_xor_sync(0xffffffffu, m1, 2));
        float s0 = 0.f, s1 = 0.f;
#pragma unroll
        for (int t = 0; t < 32; t++) {
            c[t][0] = __expf(c[t][0] - m0); s0 += c[t][0];
            c[t][1] = __expf(c[t][1] - m0); s0 += c[t][1];
            c[t][2] = __expf(c[t][2] - m1); s1 += c[t][2];
            c[t][3] = __expf(c[t][3] - m1); s1 += c[t][3];
        }
        s0 += __shfl_xor_sync(0xffffffffu, s0, 1);
        s0 += __shfl_xor_sync(0xffffffffu, s0, 2);
        s1 += __shfl_xor_sync(0xffffffffu, s1, 1);
        s1 += __shfl_xor_sync(0xffffffffu, s1, 2);
        float i0 = 1.f / s0, i1 = 1.f / s1;
#pragma unroll
        for (int t = 0; t < 32; t++) {
            c[t][0] *= i0; c[t][1] *= i0; c[t][2] *= i1; c[t][3] *= i1;
        }
    }

    // ---- O = P V  (P fragments straight from S accumulators, hi/lo split) ----
    float o[8][4];
#pragma unroll
    for (int j = 0; j < 8; j++)
#pragma unroll
        for (int k = 0; k < 4; k++) o[j][k] = 0.f;

    const int v_rx = (lane & 7) + (((lane >> 3) & 1) << 3);
    const int v_cx = (lane >> 4) << 3;

#pragma unroll
    for (int kt = 0; kt < 16; kt++) {
        uint32_t aH[4], aL[4];
        split2(c[2 * kt][0], c[2 * kt][1], aH[0], aL[0]);
        split2(c[2 * kt][2], c[2 * kt][3], aH[1], aL[1]);
        split2(c[2 * kt + 1][0], c[2 * kt + 1][1], aH[2], aL[2]);
        split2(c[2 * kt + 1][2], c[2 * kt + 1][3], aH[3], aL[3]);
#pragma unroll
        for (int db = 0; db < 4; db++) {
            uint32_t bH[4], bL[4];
            uint32_t boff = (uint32_t)((kt * 16 + v_rx) * ATT_S + db * 16 + v_cx) * 2;
            ldm_x4_t(bH, smb + AVH * 2 + boff);
            ldm_x4_t(bL, smb + AVL * 2 + boff);
#pragma unroll
            for (int nt = 0; nt < 2; nt++) {
                float* oo = o[db * 2 + nt];
                mma16816(oo, aH, &bH[nt * 2]);
                mma16816(oo, aH, &bL[nt * 2]);
                mma16816(oo, aL, &bH[nt * 2]);
            }
        }
    }

    // ---- store bf16 hi/lo at [z][pos][512] ----
    {
        int row0 = qt * 128 + r0 + (lane >> 2);
        int row1 = row0 + 8;
        size_t b0 = ((size_t)z * 1024 + row0) * 512 + h * 64 + (lane & 3) * 2;
        size_t b1 = ((size_t)z * 1024 + row1) * 512 + h * 64 + (lane & 3) * 2;
#pragma unroll
        for (int nt = 0; nt < 8; nt++) {
            uint32_t h0, l0, h1, l1;
            split2(o[nt][0], o[nt][1], h0, l0);
            split2(o[nt][2], o[nt][3], h1, l1);
            *(uint32_t*)&aohi[b0 + nt * 8] = h0;
            *(uint32_t*)&aolo[b0 + nt * 8] = l0;
            *(uint32_t*)&aohi[b1 + nt * 8] = h1;
            *(uint32_t*)&aolo[b1 + nt * 8] = l1;
        }
    }
}

// ==================== launch ====================
extern "C" void kernel_launch(void* const* d_in, const int* in_sizes, int n_in,
                              void* d_out, int out_size) {
    const float* x        = (const float*)d_in[0];
    const float* y        = (const float*)d_in[1];
    const float* q_dw_w   = (const float*)d_in[2];
    const float* q_bn_g   = (const float*)d_in[3];
    const float* q_bn_b   = (const float*)d_in[4];
    const float* q_bn_m   = (const float*)d_in[5];
    const float* q_bn_v   = (const float*)d_in[6];
    const float* q_pw_w   = (const float*)d_in[7];
    const float* kv_dw_w  = (const float*)d_in[8];
    const float* kv_bn_g  = (const float*)d_in[9];
    const float* kv_bn_b  = (const float*)d_in[10];
    const float* kv_bn_m  = (const float*)d_in[11];
    const float* kv_bn_v  = (const float*)d_in[12];
    const float* kv_pw_w  = (const float*)d_in[13];
    const float* out_w    = (const float*)d_in[14];
    const float* out_b    = (const float*)d_in[15];
    float* out = (float*)d_out;

    float *p_hq, *p_hkv;
    __nv_bfloat16 *p_hqT_hi, *p_hqT_lo, *p_hkvT_hi, *p_hkvT_lo;
    __nv_bfloat16 *p_wq_hi, *p_wq_lo, *p_wkv_hi, *p_wkv_lo, *p_wo_hi, *p_wo_lo;
    __nv_bfloat16 *p_qs_hi, *p_qs_lo, *p_kvs_hi, *p_kvs_lo, *p_ao_hi, *p_ao_lo;
    cudaGetSymbolAddress((void**)&p_hq,  g_hq);
    cudaGetSymbolAddress((void**)&p_hkv, g_hkv);
    cudaGetSymbolAddress((void**)&p_hqT_hi,  g_hqT_hi);
    cudaGetSymbolAddress((void**)&p_hqT_lo,  g_hqT_lo);
    cudaGetSymbolAddress((void**)&p_hkvT_hi, g_hkvT_hi);
    cudaGetSymbolAddress((void**)&p_hkvT_lo, g_hkvT_lo);
    cudaGetSymbolAddress((void**)&p_wq_hi,  g_wq_hi);
    cudaGetSymbolAddress((void**)&p_wq_lo,  g_wq_lo);
    cudaGetSymbolAddress((void**)&p_wkv_hi, g_wkv_hi);
    cudaGetSymbolAddress((void**)&p_wkv_lo, g_wkv_lo);
    cudaGetSymbolAddress((void**)&p_wo_hi,  g_wo_hi);
    cudaGetSymbolAddress((void**)&p_wo_lo,  g_wo_lo);
    cudaGetSymbolAddress((void**)&p_qs_hi,  g_qs_hi);
    cudaGetSymbolAddress((void**)&p_qs_lo,  g_qs_lo);
    cudaGetSymbolAddress((void**)&p_kvs_hi, g_kvs_hi);
    cudaGetSymbolAddress((void**)&p_kvs_lo, g_kvs_lo);
    cudaGetSymbolAddress((void**)&p_ao_hi,  g_ao_hi);
    cudaGetSymbolAddress((void**)&p_ao_lo,  g_ao_lo);

    cudaFuncSetAttribute(attn_mma,
                         cudaFuncAttributeMaxDynamicSharedMemorySize, ATT_SMEM);

    const int n_s1 = 8 * 256 * 32 * 32;
    const int n_s2 = 8 * 256 * 16 * 16;
    const int half_s1 = 8 * 256 * 1024;
    const int half_s2 = 8 * 256 * 256;

    // 1) depthwise + BN
    dw_bn_kernel<<<(n_s1 + 255) / 256, 256>>>(
        x, q_dw_w, q_bn_g, q_bn_b, q_bn_m, q_bn_v, p_hq, 1, 32);
    dw_bn_kernel<<<(n_s1 + 255) / 256, 256>>>(
        y, q_dw_w, q_bn_g, q_bn_b, q_bn_m, q_bn_v, p_hq + half_s1, 1, 32);
    dw_bn_kernel<<<(n_s2 + 255) / 256, 256>>>(
        x, kv_dw_w, kv_bn_g, kv_bn_b, kv_bn_m, kv_bn_v, p_hkv, 2, 16);
    dw_bn_kernel<<<(n_s2 + 255) / 256, 256>>>(
        y, kv_dw_w, kv_bn_g, kv_bn_b, kv_bn_m, kv_bn_v, p_hkv + half_s2, 2, 16);

    // 2) splits (q weight pre-scaled by ATT_SCALE = 0.125, exact)
    wsplit_kernel<<<512, 256>>>(q_pw_w,  p_wq_hi,  p_wq_lo,  512 * 256, 0.125f);
    wsplit_kernel<<<1024, 256>>>(kv_pw_w, p_wkv_hi, p_wkv_lo, 1024 * 256, 1.0f);
    wsplit_kernel<<<512, 256>>>(out_w,   p_wo_hi,  p_wo_lo,  256 * 512, 1.0f);
    {
        dim3 blk(32, 8);
        dim3 g1(1024 / 32, 256 / 32, 16);
        tsplit_kernel<<<g1, blk>>>(p_hq, p_hqT_hi, p_hqT_lo, 256, 1024);
        dim3 g2(256 / 32, 256 / 32, 16);
        tsplit_kernel<<<g2, blk>>>(p_hkv, p_hkvT_hi, p_hkvT_lo, 256, 256);
    }

    // 3) q: [z][1024 pos][256] x [512 ch][256]^T -> bf16 hi/lo [z][pos][512]
    {
        dim3 grid(512 / 128, 1024 / 128, 16);
        gemm_mma<true><<<grid, 256>>>(p_hqT_hi, p_hqT_lo, (size_t)1024 * 256,
                                      p_wq_hi, p_wq_lo, 0,
                                      nullptr, p_qs_hi, p_qs_lo, nullptr,
                                      1024, 512, 256);
    }
    // 4) kv: [z][256 pos][256] x [1024 ch][256]^T -> bf16 hi/lo [z][pos][1024]
    {
        dim3 grid(1024 / 128, 256 / 128, 16);
        gemm_mma<true><<<grid, 256>>>(p_hkvT_hi, p_hkvT_lo, (size_t)256 * 256,
                                      p_wkv_hi, p_wkv_lo, 0,
                                      nullptr, p_kvs_hi, p_kvs_lo, nullptr,
                                      256, 1024, 256);
    }
    // 5) tensor-core fused cross-attention
    {
        dim3 grid(8, 8, 16);
        attn_mma<<<grid, 256, ATT_SMEM>>>(p_qs_hi, p_qs_lo, p_kvs_hi, p_kvs_lo,
                                          p_ao_hi, p_ao_lo);
    }
    // 6) out proj: [256 ch][512] x [z][1024 pos][512]^T + bias -> fp32 [z][256][1024]
    {
        dim3 grid(1024 / 128, 256 / 128, 16);
        gemm_mma<false><<<grid, 256>>>(p_wo_hi, p_wo_lo, 0,
                                       p_ao_hi, p_ao_lo, (size_t)1024 * 512,
                                       out, nullptr, nullptr, out_b,
                                       256, 1024, 512);
    }
}

// round 6
// speedup vs baseline: 2.2531x; 1.2146x over previous
#include <cuda_runtime.h>
#include <cuda_bf16.h>
#include <math.h>
#include <cstdint>

#define BN_EPS 1e-5f

// ==================== PTX helpers (baseline, sm_103-safe) ====================
__device__ __forceinline__ uint32_t smem_u32(const void* p) {
    uint32_t a;
    asm("{ .reg .u64 t; cvta.to.shared.u64 t, %1; cvt.u32.u64 %0, t; }" : "=r"(a) : "l"(p));
    return a;
}
__device__ __forceinline__ void ldm_x4(uint32_t* r, uint32_t addr) {
    asm volatile("ldmatrix.sync.aligned.m8n8.x4.shared.b16 {%0,%1,%2,%3}, [%4];"
                 : "=r"(r[0]), "=r"(r[1]), "=r"(r[2]), "=r"(r[3]) : "r"(addr));
}
__device__ __forceinline__ void ldm_x4_t(uint32_t* r, uint32_t addr) {
    asm volatile("ldmatrix.sync.aligned.m8n8.x4.trans.shared.b16 {%0,%1,%2,%3}, [%4];"
                 : "=r"(r[0]), "=r"(r[1]), "=r"(r[2]), "=r"(r[3]) : "r"(addr));
}
__device__ __forceinline__ void mma16816(float* d, const uint32_t* a, const uint32_t* b) {
    asm volatile("mma.sync.aligned.m16n8k16.row.col.f32.bf16.bf16.f32 "
        "{%0,%1,%2,%3}, {%4,%5,%6,%7}, {%8,%9}, {%0,%1,%2,%3};"
        : "+f"(d[0]), "+f"(d[1]), "+f"(d[2]), "+f"(d[3])
        : "r"(a[0]), "r"(a[1]), "r"(a[2]), "r"(a[3]), "r"(b[0]), "r"(b[1]));
}
__device__ __forceinline__ void split2(float x, float y, uint32_t &hi, uint32_t &lo) {
    asm("cvt.rn.bf16x2.f32 %0, %1, %2;" : "=r"(hi) : "f"(y), "f"(x));
    float xh = __uint_as_float(hi << 16);
    float yh = __uint_as_float(hi & 0xffff0000u);
    asm("cvt.rn.bf16x2.f32 %0, %1, %2;" : "=r"(lo) : "f"(y - yh), "f"(x - xh));
}
__device__ __forceinline__ void cpa16(uint32_t saddr, const void* g) {
    asm volatile("cp.async.cg.shared.global [%0], [%1], 16;" :: "r"(saddr), "l"(g));
}
#define CP_COMMIT() asm volatile("cp.async.commit_group;" ::: "memory")
#define CP_WAIT1()  asm volatile("cp.async.wait_group 1;" ::: "memory")
#define CP_WAIT0()  asm volatile("cp.async.wait_group 0;" ::: "memory")

// ==================== scratch ====================
// z = t*8 + b : t=0 -> x side, t=1 -> y side
__device__ __nv_bfloat16 g_hqT_hi [16u * 1024 * 256];   // [z][hw][c]
__device__ __nv_bfloat16 g_hqT_lo [16u * 1024 * 256];
__device__ __nv_bfloat16 g_hkvT_hi[16u * 256 * 256];
__device__ __nv_bfloat16 g_hkvT_lo[16u * 256 * 256];
__device__ __nv_bfloat16 g_wq_hi [512 * 256],  g_wq_lo [512 * 256];   // pre-scaled 0.125
__device__ __nv_bfloat16 g_wkv_hi[1024 * 256], g_wkv_lo[1024 * 256];
__device__ __nv_bfloat16 g_wo_hi [256 * 512],  g_wo_lo [256 * 512];
__device__ __nv_bfloat16 g_qs_hi [16u * 1024 * 512], g_qs_lo [16u * 1024 * 512];
__device__ __nv_bfloat16 g_kvs_hi[16u * 256 * 1024], g_kvs_lo[16u * 256 * 1024];
__device__ __nv_bfloat16 g_ao_hi [16u * 1024 * 512], g_ao_lo [16u * 1024 * 512];

// ==================== fused dw 3x3 conv + BN + transpose + hi/lo split ====================
// output: [z][hw][256] bf16 hi/lo.  grid (HW/32, 8, 16), block (32,8)
__global__ void dw_bn_split(const float* __restrict__ x, const float* __restrict__ y,
                            const float* __restrict__ w,
                            const float* __restrict__ gamma, const float* __restrict__ beta,
                            const float* __restrict__ mean, const float* __restrict__ var,
                            __nv_bfloat16* __restrict__ hi, __nv_bfloat16* __restrict__ lo,
                            int stride, int HO) {
    __shared__ float t[32][33];
    const int z = blockIdx.z, b = z & 7;
    const float* in = (z >= 8) ? y : x;
    const int HW = HO * HO;
    const int hw0 = blockIdx.x * 32, c0 = blockIdx.y * 32;
    const int tx = threadIdx.x, ty = threadIdx.y;
    const int hw = hw0 + tx;
    const int oh = hw / HO, ow = hw % HO;
    const int ih0 = oh * stride - 1, iw0 = ow * stride - 1;
#pragma unroll
    for (int r = 0; r < 4; r++) {
        int c = c0 + ty + r * 8;
        const float* ip = in + (size_t)(b * 256 + c) * 1024;
        const float* wp = w + c * 9;
        float acc = 0.f;
#pragma unroll
        for (int kh = 0; kh < 3; kh++) {
            int ih = ih0 + kh;
            if (ih < 0 || ih > 31) continue;
#pragma unroll
            for (int kw = 0; kw < 3; kw++) {
                int iw = iw0 + kw;
                if (iw < 0 || iw > 31) continue;
                acc += wp[kh * 3 + kw] * ip[ih * 32 + iw];
            }
        }
        float sc = gamma[c] * rsqrtf(var[c] + BN_EPS);
        float sh = beta[c] - mean[c] * sc;
        t[ty + r * 8][tx] = acc * sc + sh;
    }
    __syncthreads();
    size_t ob = (size_t)z * HW * 256;
#pragma unroll
    for (int r = 0; r < 4; r++) {
        float v = t[tx][ty + r * 8];
        __nv_bfloat16 hh = __float2bfloat16(v);
        size_t o = ob + (size_t)(hw0 + ty + r * 8) * 256 + c0 + tx;
        hi[o] = hh;
        lo[o] = __float2bfloat16(v - __bfloat162float(hh));
    }
}

// ==================== weight split ====================
__global__ void wsplit_kernel(const float* __restrict__ in,
                              __nv_bfloat16* __restrict__ hi,
                              __nv_bfloat16* __restrict__ lo, int n, float scale) {
    int i = blockIdx.x * 256 + threadIdx.x;
    if (i >= n) return;
    float v = in[i] * scale;
    __nv_bfloat16 h = __float2bfloat16(v);
    hi[i] = h;
    lo[i] = __float2bfloat16(v - __bfloat162float(h));
}

// ==================== cp.async double-buffered bf16-split GEMM ====================
// C[z][M][N] = A[z][M,K] x B[z][N,K]^T  (hi/lo, 3 terms)
#define SMS 40
#define OPB (128 * SMS * 2)          // bytes per operand buffer (10240)
#define GEMM_SMEM (2 * 4 * OPB)      // 81920 B

__device__ __forceinline__ void gemm_issue(
    uint32_t smb, int stage,
    const __nv_bfloat16* Ah, const __nv_bfloat16* Al,
    const __nv_bfloat16* Bh, const __nv_bfloat16* Bl,
    int m0, int n0, int K, int k0, int rid, int cid) {
    uint32_t sb = smb + (uint32_t)stage * 4 * OPB;
    uint32_t s0 = (uint32_t)(rid * SMS + cid) * 2;
    uint32_t s1 = (uint32_t)((rid + 64) * SMS + cid) * 2;
    cpa16(sb + s0,            &Ah[(size_t)(m0 + rid) * K + k0 + cid]);
    cpa16(sb + s1,            &Ah[(size_t)(m0 + rid + 64) * K + k0 + cid]);
    cpa16(sb + OPB + s0,      &Al[(size_t)(m0 + rid) * K + k0 + cid]);
    cpa16(sb + OPB + s1,      &Al[(size_t)(m0 + rid + 64) * K + k0 + cid]);
    cpa16(sb + 2 * OPB + s0,  &Bh[(size_t)(n0 + rid) * K + k0 + cid]);
    cpa16(sb + 2 * OPB + s1,  &Bh[(size_t)(n0 + rid + 64) * K + k0 + cid]);
    cpa16(sb + 3 * OPB + s0,  &Bl[(size_t)(n0 + rid) * K + k0 + cid]);
    cpa16(sb + 3 * OPB + s1,  &Bl[(size_t)(n0 + rid + 64) * K + k0 + cid]);
}

template <bool SPLIT>
__global__ void __launch_bounds__(256)
gemm_mma(const __nv_bfloat16* __restrict__ Ahi, const __nv_bfloat16* __restrict__ Alo, size_t sA,
         const __nv_bfloat16* __restrict__ Bhi, const __nv_bfloat16* __restrict__ Blo, size_t sB,
         float* __restrict__ Cf, __nv_bfloat16* __restrict__ Chi, __nv_bfloat16* __restrict__ Clo,
         const float* __restrict__ bias, int M, int N, int K) {
    extern __shared__ __nv_bfloat16 gsm[];
    const uint32_t smb = smem_u32(gsm);
    const int tid = threadIdx.x, lane = tid & 31, wid = tid >> 5;
    const int warp_m = wid & 3, warp_n = wid >> 2;
    const int m0 = blockIdx.y * 128, n0 = blockIdx.x * 128, z = blockIdx.z;

    const __nv_bfloat16* Ah = Ahi + (size_t)z * sA;
    const __nv_bfloat16* Al = Alo + (size_t)z * sA;
    const __nv_bfloat16* Bh = Bhi + (size_t)z * sB;
    const __nv_bfloat16* Bl = Blo + (size_t)z * sB;

    float acc[2][8][4];
#pragma unroll
    for (int i = 0; i < 2; i++)
#pragma unroll
        for (int j = 0; j < 8; j++)
#pragma unroll
            for (int k = 0; k < 4; k++) acc[i][j][k] = 0.f;

    const int rid = tid >> 2;
    const int cid = (tid & 3) * 8;
    const int a_row = warp_m * 32 + (lane & 15);
    const int a_colx = (lane >> 4) << 3;
    const int b_row = warp_n * 64 + (lane & 7) + ((lane >> 4) << 3);
    const int b_colx = ((lane >> 3) & 1) << 3;

    const int nk = K / 32;
    gemm_issue(smb, 0, Ah, Al, Bh, Bl, m0, n0, K, 0, rid, cid);
    CP_COMMIT();

    for (int i = 0; i < nk; i++) {
        const int stage = i & 1;
        if (i + 1 < nk) {
            gemm_issue(smb, stage ^ 1, Ah, Al, Bh, Bl, m0, n0, K, (i + 1) * 32, rid, cid);
            CP_COMMIT();
            CP_WAIT1();
        } else {
            CP_WAIT0();
        }
        __syncthreads();

        const uint32_t base = smb + (uint32_t)stage * 4 * OPB;
#pragma unroll
        for (int ks = 0; ks < 2; ks++) {
            const int kc = ks * 16;
            uint32_t ah[2][4], al[2][4];
#pragma unroll
            for (int mt = 0; mt < 2; mt++) {
                uint32_t off = (uint32_t)((a_row + mt * 16) * SMS + kc + a_colx) * 2;
                ldm_x4(ah[mt], base + off);
                ldm_x4(al[mt], base + OPB + off);
            }
#pragma unroll
            for (int ng = 0; ng < 4; ng++) {
                uint32_t bh[4], bl[4];
                uint32_t off = (uint32_t)((b_row + ng * 16) * SMS + kc + b_colx) * 2;
                ldm_x4(bh, base + 2 * OPB + off);
                ldm_x4(bl, base + 3 * OPB + off);
#pragma unroll
                for (int mt = 0; mt < 2; mt++)
#pragma unroll
                    for (int nt = 0; nt < 2; nt++) {
                        float* c = acc[mt][ng * 2 + nt];
                        mma16816(c, ah[mt], &bh[nt * 2]);
                        mma16816(c, ah[mt], &bl[nt * 2]);
                        mma16816(c, al[mt], &bh[nt * 2]);
                    }
            }
        }
        __syncthreads();
    }

    // ---- epilogue ----
#pragma unroll
    for (int mt = 0; mt < 2; mt++) {
        int mrow0 = m0 + warp_m * 32 + mt * 16 + (lane >> 2);
        int mrow1 = mrow0 + 8;
        float bv0 = (!SPLIT && bias) ? bias[mrow0] : 0.f;
        float bv1 = (!SPLIT && bias) ? bias[mrow1] : 0.f;
#pragma unroll
        for (int j = 0; j < 8; j++) {
            int n = n0 + warp_n * 64 + j * 8 + (lane & 3) * 2;
            float* c = acc[mt][j];
            if (SPLIT) {
                uint32_t h0, l0, h1, l1;
                split2(c[0], c[1], h0, l0);
                split2(c[2], c[3], h1, l1);
                size_t o0 = (size_t)z * M * N + (size_t)mrow0 * N + n;
                size_t o1 = (size_t)z * M * N + (size_t)mrow1 * N + n;
                *(uint32_t*)&Chi[o0] = h0; *(uint32_t*)&Clo[o0] = l0;
                *(uint32_t*)&Chi[o1] = h1; *(uint32_t*)&Clo[o1] = l1;
            } else {
                float* Cz = Cf + (size_t)z * M * N;
                *(float2*)&Cz[(size_t)mrow0 * N + n] = make_float2(c[0] + bv0, c[1] + bv0);
                *(float2*)&Cz[(size_t)mrow1 * N + n] = make_float2(c[2] + bv1, c[3] + bv1);
            }
        }
    }
}

// ==================== persistent-KV tensor-core cross-attention ====================
// grid (8 heads, 16 z). 256 threads = 8 warps; K/V staged ONCE, loop 8 q-tiles of 128.
#define ATT_S 72
#define AQH 0
#define AQL (128 * ATT_S)
#define AKH (2 * 128 * ATT_S)
#define AKL (AKH + 256 * ATT_S)
#define AVH (AKH + 2 * 256 * ATT_S)
#define AVL (AVH + 256 * ATT_S)
#define ATT_SMEM ((2 * 128 + 4 * 256) * ATT_S * 2)   // 184320 B

__global__ void __launch_bounds__(256, 1)
attn_mma(const __nv_bfloat16* __restrict__ qhi, const __nv_bfloat16* __restrict__ qlo,
         const __nv_bfloat16* __restrict__ kvhi, const __nv_bfloat16* __restrict__ kvlo,
         __nv_bfloat16* __restrict__ aohi, __nv_bfloat16* __restrict__ aolo) {
    extern __shared__ __nv_bfloat16 sm[];
    const int tid = threadIdx.x, lane = tid & 31, wid = tid >> 5;
    const int h = blockIdx.x, z = blockIdx.y;
    const int zk = ((z >> 3) ^ 1) * 8 + (z & 7);

    // ---- stage K, V (256x64 each, hi/lo) once ----
    {
        size_t kb = (size_t)zk * 256 * 1024 + h * 64;
        size_t vb = kb + 512;
        for (int i = tid; i < 2048; i += 256) {
            int row = i >> 3, ch = (i & 7) * 8;
            *(uint4*)&sm[AKH + row * ATT_S + ch] = *(const uint4*)&kvhi[kb + (size_t)row * 1024 + ch];
            *(uint4*)&sm[AKL + row * ATT_S + ch] = *(const uint4*)&kvlo[kb + (size_t)row * 1024 + ch];
            *(uint4*)&sm[AVH + row * ATT_S + ch] = *(const uint4*)&kvhi[vb + (size_t)row * 1024 + ch];
            *(uint4*)&sm[AVL + row * ATT_S + ch] = *(const uint4*)&kvlo[vb + (size_t)row * 1024 + ch];
        }
    }

    const uint32_t smb = smem_u32(sm);
    const int r0 = wid * 16;
    const int a_row = r0 + (lane & 15);
    const int a_cx = (lane >> 4) << 3;
    const int b_rx = (lane & 7) + ((lane >> 4) << 3);
    const int b_cx = ((lane >> 3) & 1) << 3;
    const int v_rx = (lane & 7) + (((lane >> 3) & 1) << 3);
    const int v_cx = (lane >> 4) << 3;

    for (int qt = 0; qt < 8; qt++) {
        // ---- stage Q tile (128x64 hi/lo) ----
        {
            size_t qb = ((size_t)z * 1024 + qt * 128) * 512 + h * 64;
            for (int i = tid; i < 1024; i += 256) {
                int row = i >> 3, ch = (i & 7) * 8;
                *(uint4*)&sm[AQH + row * ATT_S + ch] = *(const uint4*)&qhi[qb + (size_t)row * 512 + ch];
                *(uint4*)&sm[AQL + row * ATT_S + ch] = *(const uint4*)&qlo[qb + (size_t)row * 512 + ch];
            }
        }
        __syncthreads();

        // ---- S = Q K^T ----
        float c[32][4];
#pragma unroll
        for (int t = 0; t < 32; t++)
#pragma unroll
            for (int k = 0; k < 4; k++) c[t][k] = 0.f;

#pragma unroll
        for (int kt = 0; kt < 4; kt++) {
            uint32_t aH[4], aL[4];
            uint32_t aoff = (uint32_t)(a_row * ATT_S + kt * 16 + a_cx) * 2;
            ldm_x4(aH, smb + AQH * 2 + aoff);
            ldm_x4(aL, smb + AQL * 2 + aoff);
#pragma unroll
            for (int jt = 0; jt < 16; jt++) {
                uint32_t bH[4], bL[4];
                uint32_t boff = (uint32_t)((jt * 16 + b_rx) * ATT_S + kt * 16 + b_cx) * 2;
                ldm_x4(bH, smb + AKH * 2 + boff);
                ldm_x4(bL, smb + AKL * 2 + boff);
#pragma unroll
                for (int nt = 0; nt < 2; nt++) {
                    float* cc = c[jt * 2 + nt];
                    mma16816(cc, aH, &bH[nt * 2]);
                    mma16816(cc, aH, &bL[nt * 2]);
                    mma16816(cc, aL, &bH[nt * 2]);
                }
            }
        }

        // ---- softmax ----
        {
            float m0 = -1e30f, m1 = -1e30f;
#pragma unroll
            for (int t = 0; t < 32; t++) {
                m0 = fmaxf(m0, fmaxf(c[t][0], c[t][1]));
                m1 = fmaxf(m1, fmaxf(c[t][2], c[t][3]));
            }
            m0 = fmaxf(m0, __shfl_xor_sync(0xffffffffu, m0, 1));
            m0 = fmaxf(m0, __shfl_xor_sync(0xffffffffu, m0, 2));
            m1 = fmaxf(m1, __shfl_xor_sync(0xffffffffu, m1, 1));
            m1 = fmaxf(m1, __shfl_xor_sync(0xffffffffu, m1, 2));
            float s0 = 0.f, s1 = 0.f;
#pragma unroll
            for (int t = 0; t < 32; t++) {
                c[t][0] = __expf(c[t][0] - m0); s0 += c[t][0];
                c[t][1] = __expf(c[t][1] - m0); s0 += c[t][1];
                c[t][2] = __expf(c[t][2] - m1); s1 += c[t][2];
                c[t][3] = __expf(c[t][3] - m1); s1 += c[t][3];
            }
            s0 += __shfl_xor_sync(0xffffffffu, s0, 1);
            s0 += __shfl_xor_sync(0xffffffffu, s0, 2);
            s1 += __shfl_xor_sync(0xffffffffu, s1, 1);
            s1 += __shfl_xor_sync(0xffffffffu, s1, 2);
            float i0 = 1.f / s0, i1 = 1.f / s1;
#pragma unroll
            for (int t = 0; t < 32; t++) {
                c[t][0] *= i0; c[t][1] *= i0; c[t][2] *= i1; c[t][3] *= i1;
            }
        }

        // ---- O = P V ----
        float o[8][4];
#pragma unroll
        for (int j = 0; j < 8; j++)
#pragma unroll
            for (int k = 0; k < 4; k++) o[j][k] = 0.f;

#pragma unroll
        for (int kt = 0; kt < 16; kt++) {
            uint32_t aH[4], aL[4];
            split2(c[2 * kt][0], c[2 * kt][1], aH[0], aL[0]);
            split2(c[2 * kt][2], c[2 * kt][3], aH[1], aL[1]);
            split2(c[2 * kt + 1][0], c[2 * kt + 1][1], aH[2], aL[2]);
            split2(c[2 * kt + 1][2], c[2 * kt + 1][3], aH[3], aL[3]);
#pragma unroll
            for (int db = 0; db < 4; db++) {
                uint32_t bH[4], bL[4];
                uint32_t boff = (uint32_t)((kt * 16 + v_rx) * ATT_S + db * 16 + v_cx) * 2;
                ldm_x4_t(bH, smb + AVH * 2 + boff);
                ldm_x4_t(bL, smb + AVL * 2 + boff);
#pragma unroll
                for (int nt = 0; nt < 2; nt++) {
                    float* oo = o[db * 2 + nt];
                    mma16816(oo, aH, &bH[nt * 2]);
                    mma16816(oo, aH, &bL[nt * 2]);
                    mma16816(oo, aL, &bH[nt * 2]);
                }
            }
        }

        // ---- store bf16 hi/lo at [z][pos][512] ----
        {
            int row0 = qt * 128 + r0 + (lane >> 2);
            int row1 = row0 + 8;
            size_t b0 = ((size_t)z * 1024 + row0) * 512 + h * 64 + (lane & 3) * 2;
            size_t b1 = ((size_t)z * 1024 + row1) * 512 + h * 64 + (lane & 3) * 2;
#pragma unroll
            for (int nt = 0; nt < 8; nt++) {
                uint32_t h0, l0, h1, l1;
                split2(o[nt][0], o[nt][1], h0, l0);
                split2(o[nt][2], o[nt][3], h1, l1);
                *(uint32_t*)&aohi[b0 + nt * 8] = h0;
                *(uint32_t*)&aolo[b0 + nt * 8] = l0;
                *(uint32_t*)&aohi[b1 + nt * 8] = h1;
                *(uint32_t*)&aolo[b1 + nt * 8] = l1;
            }
        }
        __syncthreads();   // Q buffer reuse fence for next tile
    }
}

// ==================== launch ====================
extern "C" void kernel_launch(void* const* d_in, const int* in_sizes, int n_in,
                              void* d_out, int out_size) {
    const float* x        = (const float*)d_in[0];
    const float* y        = (const float*)d_in[1];
    const float* q_dw_w   = (const float*)d_in[2];
    const float* q_bn_g   = (const float*)d_in[3];
    const float* q_bn_b   = (const float*)d_in[4];
    const float* q_bn_m   = (const float*)d_in[5];
    const float* q_bn_v   = (const float*)d_in[6];
    const float* q_pw_w   = (const float*)d_in[7];
    const float* kv_dw_w  = (const float*)d_in[8];
    const float* kv_bn_g  = (const float*)d_in[9];
    const float* kv_bn_b  = (const float*)d_in[10];
    const float* kv_bn_m  = (const float*)d_in[11];
    const float* kv_bn_v  = (const float*)d_in[12];
    const float* kv_pw_w  = (const float*)d_in[13];
    const float* out_w    = (const float*)d_in[14];
    const float* out_b    = (const float*)d_in[15];
    float* out = (float*)d_out;

    __nv_bfloat16 *p_hqT_hi, *p_hqT_lo, *p_hkvT_hi, *p_hkvT_lo;
    __nv_bfloat16 *p_wq_hi, *p_wq_lo, *p_wkv_hi, *p_wkv_lo, *p_wo_hi, *p_wo_lo;
    __nv_bfloat16 *p_qs_hi, *p_qs_lo, *p_kvs_hi, *p_kvs_lo, *p_ao_hi, *p_ao_lo;
    cudaGetSymbolAddress((void**)&p_hqT_hi,  g_hqT_hi);
    cudaGetSymbolAddress((void**)&p_hqT_lo,  g_hqT_lo);
    cudaGetSymbolAddress((void**)&p_hkvT_hi, g_hkvT_hi);
    cudaGetSymbolAddress((void**)&p_hkvT_lo, g_hkvT_lo);
    cudaGetSymbolAddress((void**)&p_wq_hi,  g_wq_hi);
    cudaGetSymbolAddress((void**)&p_wq_lo,  g_wq_lo);
    cudaGetSymbolAddress((void**)&p_wkv_hi, g_wkv_hi);
    cudaGetSymbolAddress((void**)&p_wkv_lo, g_wkv_lo);
    cudaGetSymbolAddress((void**)&p_wo_hi,  g_wo_hi);
    cudaGetSymbolAddress((void**)&p_wo_lo,  g_wo_lo);
    cudaGetSymbolAddress((void**)&p_qs_hi,  g_qs_hi);
    cudaGetSymbolAddress((void**)&p_qs_lo,  g_qs_lo);
    cudaGetSymbolAddress((void**)&p_kvs_hi, g_kvs_hi);
    cudaGetSymbolAddress((void**)&p_kvs_lo, g_kvs_lo);
    cudaGetSymbolAddress((void**)&p_ao_hi,  g_ao_hi);
    cudaGetSymbolAddress((void**)&p_ao_lo,  g_ao_lo);

    cudaFuncSetAttribute(attn_mma,
                         cudaFuncAttributeMaxDynamicSharedMemorySize, ATT_SMEM);
    cudaFuncSetAttribute(gemm_mma<true>,
                         cudaFuncAttributeMaxDynamicSharedMemorySize, GEMM_SMEM);
    cudaFuncSetAttribute(gemm_mma<false>,
                         cudaFuncAttributeMaxDynamicSharedMemorySize, GEMM_SMEM);

    // 1) fused dw conv + BN + transpose + split  -> [z][hw][256] bf16 hi/lo
    {
        dim3 blk(32, 8);
        dim3 gq(1024 / 32, 256 / 32, 16);
        dw_bn_split<<<gq, blk>>>(x, y, q_dw_w, q_bn_g, q_bn_b, q_bn_m, q_bn_v,
                                 p_hqT_hi, p_hqT_lo, 1, 32);
        dim3 gk(256 / 32, 256 / 32, 16);
        dw_bn_split<<<gk, blk>>>(x, y, kv_dw_w, kv_bn_g, kv_bn_b, kv_bn_m, kv_bn_v,
                                 p_hkvT_hi, p_hkvT_lo, 2, 16);
    }

    // 2) weight splits (q pre-scaled by 0.125, exact)
    wsplit_kernel<<<512, 256>>>(q_pw_w,  p_wq_hi,  p_wq_lo,  512 * 256, 0.125f);
    wsplit_kernel<<<1024, 256>>>(kv_pw_w, p_wkv_hi, p_wkv_lo, 1024 * 256, 1.0f);
    wsplit_kernel<<<512, 256>>>(out_w,   p_wo_hi,  p_wo_lo,  256 * 512, 1.0f);

    // 3) q: [z][1024][256] x [512][256]^T -> bf16 hi/lo [z][pos][512]
    {
        dim3 grid(512 / 128, 1024 / 128, 16);
        gemm_mma<true><<<grid, 256, GEMM_SMEM>>>(p_hqT_hi, p_hqT_lo, (size_t)1024 * 256,
                                                 p_wq_hi, p_wq_lo, 0,
                                                 nullptr, p_qs_hi, p_qs_lo, nullptr,
                                                 1024, 512, 256);
    }
    // 4) kv: [z][256][256] x [1024][256]^T -> bf16 hi/lo [z][pos][1024]
    {
        dim3 grid(1024 / 128, 256 / 128, 16);
        gemm_mma<true><<<grid, 256, GEMM_SMEM>>>(p_hkvT_hi, p_hkvT_lo, (size_t)256 * 256,
                                                 p_wkv_hi, p_wkv_lo, 0,
                                                 nullptr, p_kvs_hi, p_kvs_lo, nullptr,
                                                 256, 1024, 256);
    }
    // 5) persistent-KV tensor-core attention
    {
        dim3 grid(8, 16);
        attn_mma<<<grid, 256, ATT_SMEM>>>(p_qs_hi, p_qs_lo, p_kvs_hi, p_kvs_lo,
                                          p_ao_hi, p_ao_lo);
    }
    // 6) out proj: [256][512] x [z][1024][512]^T + bias -> fp32 [z][256][1024]
    {
        dim3 grid(1024 / 128, 256 / 128, 16);
        gemm_mma<false><<<grid, 256, GEMM_SMEM>>>(p_wo_hi, p_wo_lo, 0,
                                                  p_ao_hi, p_ao_lo, (size_t)1024 * 512,
                                                  out, nullptr, nullptr, out_b,
                                                  256, 1024, 512);
    }
}

// round 7
// speedup vs baseline: 2.3928x; 1.0620x over previous
#include <cuda_runtime.h>
#include <cuda_bf16.h>
#include <math.h>
#include <cstdint>

#define BN_EPS 1e-5f

// ==================== PTX helpers (baseline, sm_103-safe) ====================
__device__ __forceinline__ uint32_t smem_u32(const void* p) {
    uint32_t a;
    asm("{ .reg .u64 t; cvta.to.shared.u64 t, %1; cvt.u32.u64 %0, t; }" : "=r"(a) : "l"(p));
    return a;
}
__device__ __forceinline__ void ldm_x4(uint32_t* r, uint32_t addr) {
    asm volatile("ldmatrix.sync.aligned.m8n8.x4.shared.b16 {%0,%1,%2,%3}, [%4];"
                 : "=r"(r[0]), "=r"(r[1]), "=r"(r[2]), "=r"(r[3]) : "r"(addr));
}
__device__ __forceinline__ void ldm_x4_t(uint32_t* r, uint32_t addr) {
    asm volatile("ldmatrix.sync.aligned.m8n8.x4.trans.shared.b16 {%0,%1,%2,%3}, [%4];"
                 : "=r"(r[0]), "=r"(r[1]), "=r"(r[2]), "=r"(r[3]) : "r"(addr));
}
__device__ __forceinline__ void mma16816(float* d, const uint32_t* a, const uint32_t* b) {
    asm volatile("mma.sync.aligned.m16n8k16.row.col.f32.bf16.bf16.f32 "
        "{%0,%1,%2,%3}, {%4,%5,%6,%7}, {%8,%9}, {%0,%1,%2,%3};"
        : "+f"(d[0]), "+f"(d[1]), "+f"(d[2]), "+f"(d[3])
        : "r"(a[0]), "r"(a[1]), "r"(a[2]), "r"(a[3]), "r"(b[0]), "r"(b[1]));
}
__device__ __forceinline__ void split2(float x, float y, uint32_t &hi, uint32_t &lo) {
    asm("cvt.rn.bf16x2.f32 %0, %1, %2;" : "=r"(hi) : "f"(y), "f"(x));
    float xh = __uint_as_float(hi << 16);
    float yh = __uint_as_float(hi & 0xffff0000u);
    asm("cvt.rn.bf16x2.f32 %0, %1, %2;" : "=r"(lo) : "f"(y - yh), "f"(x - xh));
}
__device__ __forceinline__ void cpa16(uint32_t saddr, const void* g) {
    asm volatile("cp.async.cg.shared.global [%0], [%1], 16;" :: "r"(saddr), "l"(g));
}
#define CP_COMMIT() asm volatile("cp.async.commit_group;" ::: "memory")
#define CP_WAIT1()  asm volatile("cp.async.wait_group 1;" ::: "memory")
#define CP_WAIT0()  asm volatile("cp.async.wait_group 0;" ::: "memory")

// ==================== scratch ====================
__device__ __nv_bfloat16 g_hqT_hi [16u * 1024 * 256];
__device__ __nv_bfloat16 g_hqT_lo [16u * 1024 * 256];
__device__ __nv_bfloat16 g_hkvT_hi[16u * 256 * 256];
__device__ __nv_bfloat16 g_hkvT_lo[16u * 256 * 256];
__device__ __nv_bfloat16 g_wq_hi [512 * 256],  g_wq_lo [512 * 256];
__device__ __nv_bfloat16 g_wkv_hi[1024 * 256], g_wkv_lo[1024 * 256];
__device__ __nv_bfloat16 g_wo_hi [256 * 512],  g_wo_lo [256 * 512];
__device__ __nv_bfloat16 g_qs_hi [16u * 1024 * 512], g_qs_lo [16u * 1024 * 512];
__device__ __nv_bfloat16 g_kvs_hi[16u * 256 * 1024], g_kvs_lo[16u * 256 * 1024];
__device__ __nv_bfloat16 g_ao_hi [16u * 1024 * 512], g_ao_lo [16u * 1024 * 512];

// ==================== merged dw conv + BN + transpose + split ====================
// grid (32, 8, 32), block (32,8). z<16: q path (HO=32, stride 1); z>=16: kv path (HO=16, stride 2)
__global__ void dw_bn_split2(const float* __restrict__ x, const float* __restrict__ y,
                             const float* __restrict__ qw, const float* __restrict__ qg,
                             const float* __restrict__ qb, const float* __restrict__ qm,
                             const float* __restrict__ qv,
                             const float* __restrict__ kw, const float* __restrict__ kg,
                             const float* __restrict__ kb, const float* __restrict__ km,
                             const float* __restrict__ kvv,
                             __nv_bfloat16* __restrict__ qhi, __nv_bfloat16* __restrict__ qlo,
                             __nv_bfloat16* __restrict__ khi, __nv_bfloat16* __restrict__ klo) {
    const int zz = blockIdx.z;
    const bool isQ = (zz < 16);
    if (!isQ && blockIdx.x >= 8) return;
    __shared__ float t[32][33];
    const int z = isQ ? zz : zz - 16;
    const int b = z & 7;
    const int HO = isQ ? 32 : 16;
    const int stride = isQ ? 1 : 2;
    const float* in = (z >= 8) ? y : x;
    const float* w     = isQ ? qw : kw;
    const float* gamma = isQ ? qg : kg;
    const float* beta  = isQ ? qb : kb;
    const float* mean  = isQ ? qm : km;
    const float* var   = isQ ? qv : kvv;
    __nv_bfloat16* hi = isQ ? qhi : khi;
    __nv_bfloat16* lo = isQ ? qlo : klo;

    const int HW = HO * HO;
    const int hw0 = blockIdx.x * 32, c0 = blockIdx.y * 32;
    const int tx = threadIdx.x, ty = threadIdx.y;
    const int hw = hw0 + tx;
    const int oh = hw / HO, ow = hw % HO;
    const int ih0 = oh * stride - 1, iw0 = ow * stride - 1;
#pragma unroll
    for (int r = 0; r < 4; r++) {
        int c = c0 + ty + r * 8;
        const float* ip = in + (size_t)(b * 256 + c) * 1024;
        const float* wp = w + c * 9;
        float acc = 0.f;
#pragma unroll
        for (int kh = 0; kh < 3; kh++) {
            int ih = ih0 + kh;
            if (ih < 0 || ih > 31) continue;
#pragma unroll
            for (int kw2 = 0; kw2 < 3; kw2++) {
                int iw = iw0 + kw2;
                if (iw < 0 || iw > 31) continue;
                acc += wp[kh * 3 + kw2] * ip[ih * 32 + iw];
            }
        }
        float sc = gamma[c] * rsqrtf(var[c] + BN_EPS);
        float sh = beta[c] - mean[c] * sc;
        t[ty + r * 8][tx] = acc * sc + sh;
    }
    __syncthreads();
    size_t ob = (size_t)z * HW * 256;
#pragma unroll
    for (int r = 0; r < 4; r++) {
        float v = t[tx][ty + r * 8];
        __nv_bfloat16 hh = __float2bfloat16(v);
        size_t o = ob + (size_t)(hw0 + ty + r * 8) * 256 + c0 + tx;
        hi[o] = hh;
        lo[o] = __float2bfloat16(v - __bfloat162float(hh));
    }
}

// ==================== merged weight split (all 3 weights, one launch) ====================
__global__ void wsplit_all(const float* __restrict__ qw, const float* __restrict__ kvw,
                           const float* __restrict__ ow,
                           __nv_bfloat16* __restrict__ qhi, __nv_bfloat16* __restrict__ qlo,
                           __nv_bfloat16* __restrict__ kvhi, __nv_bfloat16* __restrict__ kvlo,
                           __nv_bfloat16* __restrict__ ohi, __nv_bfloat16* __restrict__ olo) {
    int i = blockIdx.x * 256 + threadIdx.x;   // 0 .. 524287
    const float* in; __nv_bfloat16 *hi, *lo; int j; float sc = 1.f;
    if (i < 131072)      { in = qw;  hi = qhi;  lo = qlo;  j = i;          sc = 0.125f; }
    else if (i < 393216) { in = kvw; hi = kvhi; lo = kvlo; j = i - 131072; }
    else                 { in = ow;  hi = ohi;  lo = olo;  j = i - 393216; }
    float v = in[j] * sc;
    __nv_bfloat16 h = __float2bfloat16(v);
    hi[j] = h;
    lo[j] = __float2bfloat16(v - __bfloat162float(h));
}

// ==================== cp.async bf16-split GEMM core ====================
#define SMS 40
#define OPB (128 * SMS * 2)          // 10240 B per operand buffer
#define GEMM_SMEM (2 * 4 * OPB)      // 81920 B

__device__ __forceinline__ void gemm_issue(
    uint32_t smb, int stage,
    const __nv_bfloat16* Ah, const __nv_bfloat16* Al,
    const __nv_bfloat16* Bh, const __nv_bfloat16* Bl,
    int m0, int n0, int K, int k0, int rid, int cid) {
    uint32_t sb = smb + (uint32_t)stage * 4 * OPB;
    uint32_t s0 = (uint32_t)(rid * SMS + cid) * 2;
    uint32_t s1 = (uint32_t)((rid + 64) * SMS + cid) * 2;
    cpa16(sb + s0,           &Ah[(size_t)(m0 + rid) * K + k0 + cid]);
    cpa16(sb + s1,           &Ah[(size_t)(m0 + rid + 64) * K + k0 + cid]);
    cpa16(sb + OPB + s0,     &Al[(size_t)(m0 + rid) * K + k0 + cid]);
    cpa16(sb + OPB + s1,     &Al[(size_t)(m0 + rid + 64) * K + k0 + cid]);
    cpa16(sb + 2 * OPB + s0, &Bh[(size_t)(n0 + rid) * K + k0 + cid]);
    cpa16(sb + 2 * OPB + s1, &Bh[(size_t)(n0 + rid + 64) * K + k0 + cid]);
    cpa16(sb + 3 * OPB + s0, &Bl[(size_t)(n0 + rid) * K + k0 + cid]);
    cpa16(sb + 3 * OPB + s1, &Bl[(size_t)(n0 + rid + 64) * K + k0 + cid]);
}

// pointers already z-offset; C* already z-offset
template <bool SPLIT>
__device__ __forceinline__ void gemm_core(
    uint32_t smb,
    const __nv_bfloat16* Ah, const __nv_bfloat16* Al,
    const __nv_bfloat16* Bh, const __nv_bfloat16* Bl,
    float* Cf, __nv_bfloat16* Chi, __nv_bfloat16* Clo,
    const float* bias, int N, int K, int m0, int n0) {
    const int tid = threadIdx.x, lane = tid & 31, wid = tid >> 5;
    const int warp_m = wid & 3, warp_n = wid >> 2;

    float acc[2][8][4];
#pragma unroll
    for (int i = 0; i < 2; i++)
#pragma unroll
        for (int j = 0; j < 8; j++)
#pragma unroll
            for (int k = 0; k < 4; k++) acc[i][j][k] = 0.f;

    const int rid = tid >> 2;
    const int cid = (tid & 3) * 8;
    const int a_row = warp_m * 32 + (lane & 15);
    const int a_colx = (lane >> 4) << 3;
    const int b_row = warp_n * 64 + (lane & 7) + ((lane >> 4) << 3);
    const int b_colx = ((lane >> 3) & 1) << 3;

    const int nk = K / 32;
    gemm_issue(smb, 0, Ah, Al, Bh, Bl, m0, n0, K, 0, rid, cid);
    CP_COMMIT();

    for (int i = 0; i < nk; i++) {
        const int stage = i & 1;
        if (i + 1 < nk) {
            gemm_issue(smb, stage ^ 1, Ah, Al, Bh, Bl, m0, n0, K, (i + 1) * 32, rid, cid);
            CP_COMMIT();
            CP_WAIT1();
        } else {
            CP_WAIT0();
        }
        __syncthreads();

        const uint32_t base = smb + (uint32_t)stage * 4 * OPB;
#pragma unroll
        for (int ks = 0; ks < 2; ks++) {
            const int kc = ks * 16;
            uint32_t ah[2][4], al[2][4];
#pragma unroll
            for (int mt = 0; mt < 2; mt++) {
                uint32_t off = (uint32_t)((a_row + mt * 16) * SMS + kc + a_colx) * 2;
                ldm_x4(ah[mt], base + off);
                ldm_x4(al[mt], base + OPB + off);
            }
#pragma unroll
            for (int ng = 0; ng < 4; ng++) {
                uint32_t bh[4], bl[4];
                uint32_t off = (uint32_t)((b_row + ng * 16) * SMS + kc + b_colx) * 2;
                ldm_x4(bh, base + 2 * OPB + off);
                ldm_x4(bl, base + 3 * OPB + off);
#pragma unroll
                for (int mt = 0; mt < 2; mt++)
#pragma unroll
                    for (int nt = 0; nt < 2; nt++) {
                        float* c = acc[mt][ng * 2 + nt];
                        mma16816(c, ah[mt], &bh[nt * 2]);
                        mma16816(c, ah[mt], &bl[nt * 2]);
                        mma16816(c, al[mt], &bh[nt * 2]);
                    }
            }
        }
        __syncthreads();
    }

#pragma unroll
    for (int mt = 0; mt < 2; mt++) {
        int mrow0 = m0 + warp_m * 32 + mt * 16 + (lane >> 2);
        int mrow1 = mrow0 + 8;
        float bv0 = (!SPLIT && bias) ? bias[mrow0] : 0.f;
        float bv1 = (!SPLIT && bias) ? bias[mrow1] : 0.f;
#pragma unroll
        for (int j = 0; j < 8; j++) {
            int n = n0 + warp_n * 64 + j * 8 + (lane & 3) * 2;
            float* c = acc[mt][j];
            if (SPLIT) {
                uint32_t h0, l0, h1, l1;
                split2(c[0], c[1], h0, l0);
                split2(c[2], c[3], h1, l1);
                size_t o0 = (size_t)mrow0 * N + n;
                size_t o1 = (size_t)mrow1 * N + n;
                *(uint32_t*)&Chi[o0] = h0; *(uint32_t*)&Clo[o0] = l0;
                *(uint32_t*)&Chi[o1] = h1; *(uint32_t*)&Clo[o1] = l1;
            } else {
                *(float2*)&Cf[(size_t)mrow0 * N + n] = make_float2(c[0] + bv0, c[1] + bv0);
                *(float2*)&Cf[(size_t)mrow1 * N + n] = make_float2(c[2] + bv1, c[3] + bv1);
            }
        }
    }
}

// ---- merged q + kv pointwise GEMMs.  grid (48, 16) ----
__global__ void __launch_bounds__(256)
gemm_dual(const __nv_bfloat16* __restrict__ qAh, const __nv_bfloat16* __restrict__ qAl,
          const __nv_bfloat16* __restrict__ qBh, const __nv_bfloat16* __restrict__ qBl,
          __nv_bfloat16* __restrict__ qChi, __nv_bfloat16* __restrict__ qClo,
          const __nv_bfloat16* __restrict__ kAh, const __nv_bfloat16* __restrict__ kAl,
          const __nv_bfloat16* __restrict__ kBh, const __nv_bfloat16* __restrict__ kBl,
          __nv_bfloat16* __restrict__ kChi, __nv_bfloat16* __restrict__ kClo) {
    extern __shared__ __nv_bfloat16 gsm[];
    const uint32_t smb = smem_u32(gsm);
    const int bx = blockIdx.x, z = blockIdx.y;
    if (bx < 32) {
        // q: M=1024 pos, N=512 ch, K=256
        int m0 = (bx >> 2) * 128, n0 = (bx & 3) * 128;
        gemm_core<true>(smb,
            qAh + (size_t)z * 1024 * 256, qAl + (size_t)z * 1024 * 256,
            qBh, qBl,
            nullptr, qChi + (size_t)z * 1024 * 512, qClo + (size_t)z * 1024 * 512,
            nullptr, 512, 256, m0, n0);
    } else {
        // kv: M=256 pos, N=1024 ch, K=256
        int bk = bx - 32;
        int m0 = (bk >> 3) * 128, n0 = (bk & 7) * 128;
        gemm_core<true>(smb,
            kAh + (size_t)z * 256 * 256, kAl + (size_t)z * 256 * 256,
            kBh, kBl,
            nullptr, kChi + (size_t)z * 256 * 1024, kClo + (size_t)z * 256 * 1024,
            nullptr, 1024, 256, m0, n0);
    }
}

// ---- out projection GEMM.  grid (8, 2, 16) ----
__global__ void __launch_bounds__(256)
gemm_out(const __nv_bfloat16* __restrict__ Ah, const __nv_bfloat16* __restrict__ Al,
         const __nv_bfloat16* __restrict__ Bh, const __nv_bfloat16* __restrict__ Bl,
         float* __restrict__ Cf, const float* __restrict__ bias) {
    extern __shared__ __nv_bfloat16 gsm[];
    const uint32_t smb = smem_u32(gsm);
    const int z = blockIdx.z;
    int m0 = blockIdx.y * 128, n0 = blockIdx.x * 128;
    // M=256 ch, N=1024 pos, K=512 ; A = wo (no batch), B = ao[z]
    gemm_core<false>(smb,
        Ah, Al,
        Bh + (size_t)z * 1024 * 512, Bl + (size_t)z * 1024 * 512,
        Cf + (size_t)z * 256 * 1024, nullptr, nullptr,
        bias, 1024, 512, m0, n0);
}

// ==================== persistent-KV attention, cp.async + double-buffered Q ====================
#define ATT_S 72
#define AQBUF(s) ((s) * (2 * 128 * ATT_S))      // hi at +0, lo at +AQL_OFF
#define AQL_OFF (128 * ATT_S)
#define AKH (4 * 128 * ATT_S)
#define AKL (AKH + 256 * ATT_S)
#define AVH (AKH + 2 * 256 * ATT_S)
#define AVL (AKH + 3 * 256 * ATT_S)
#define ATT_SMEM ((4 * 128 + 4 * 256) * ATT_S * 2)   // 221184 B

__device__ __forceinline__ void att_stage_q(uint32_t smb, int buf,
                                            const __nv_bfloat16* qhi, const __nv_bfloat16* qlo,
                                            size_t qb, int tid) {
    uint32_t base = smb + (uint32_t)AQBUF(buf) * 2;
    for (int i = tid; i < 1024; i += 256) {
        int row = i >> 3, ch = (i & 7) * 8;
        uint32_t so = (uint32_t)(row * ATT_S + ch) * 2;
        cpa16(base + so,                 &qhi[qb + (size_t)row * 512 + ch]);
        cpa16(base + AQL_OFF * 2 + so,   &qlo[qb + (size_t)row * 512 + ch]);
    }
}

__global__ void __launch_bounds__(256, 1)
attn_mma(const __nv_bfloat16* __restrict__ qhi, const __nv_bfloat16* __restrict__ qlo,
         const __nv_bfloat16* __restrict__ kvhi, const __nv_bfloat16* __restrict__ kvlo,
         __nv_bfloat16* __restrict__ aohi, __nv_bfloat16* __restrict__ aolo) {
    extern __shared__ __nv_bfloat16 sm[];
    const int tid = threadIdx.x, lane = tid & 31, wid = tid >> 5;
    const int h = blockIdx.x, z = blockIdx.y;
    const int zk = ((z >> 3) ^ 1) * 8 + (z & 7);
    const uint32_t smb = smem_u32(sm);

    // ---- stage K, V (once) + Q tile 0 via cp.async ----
    {
        size_t kb = (size_t)zk * 256 * 1024 + h * 64;
        size_t vb = kb + 512;
        for (int i = tid; i < 2048; i += 256) {
            int row = i >> 3, ch = (i & 7) * 8;
            uint32_t so = (uint32_t)(row * ATT_S + ch) * 2;
            cpa16(smb + AKH * 2 + so, &kvhi[kb + (size_t)row * 1024 + ch]);
            cpa16(smb + AKL * 2 + so, &kvlo[kb + (size_t)row * 1024 + ch]);
            cpa16(smb + AVH * 2 + so, &kvhi[vb + (size_t)row * 1024 + ch]);
            cpa16(smb + AVL * 2 + so, &kvlo[vb + (size_t)row * 1024 + ch]);
        }
        att_stage_q(smb, 0, qhi, qlo, ((size_t)z * 1024) * 512 + h * 64, tid);
        CP_COMMIT();
        CP_WAIT0();
        __syncthreads();
    }

    const int r0 = wid * 16;
    const int a_row = r0 + (lane & 15);
    const int a_cx = (lane >> 4) << 3;
    const int b_rx = (lane & 7) + ((lane >> 4) << 3);
    const int b_cx = ((lane >> 3) & 1) << 3;
    const int v_rx = (lane & 7) + (((lane >> 3) & 1) << 3);
    const int v_cx = (lane >> 4) << 3;

    for (int qt = 0; qt < 8; qt++) {
        // prefetch next Q tile (buffer last used two tiles ago — safe after loop-end sync)
        if (qt < 7) {
            att_stage_q(smb, (qt + 1) & 1, qhi, qlo,
                        ((size_t)z * 1024 + (qt + 1) * 128) * 512 + h * 64, tid);
            CP_COMMIT();
        }
        const uint32_t qbase = smb + (uint32_t)AQBUF(qt & 1) * 2;

        // ---- S = Q K^T ----
        float c[32][4];
#pragma unroll
        for (int t = 0; t < 32; t++)
#pragma unroll
            for (int k = 0; k < 4; k++) c[t][k] = 0.f;

#pragma unroll
        for (int kt = 0; kt < 4; kt++) {
            uint32_t aH[4], aL[4];
            uint32_t aoff = (uint32_t)(a_row * ATT_S + kt * 16 + a_cx) * 2;
            ldm_x4(aH, qbase + aoff);
            ldm_x4(aL, qbase + AQL_OFF * 2 + aoff);
#pragma unroll
            for (int jt = 0; jt < 16; jt++) {
                uint32_t bH[4], bL[4];
                uint32_t boff = (uint32_t)((jt * 16 + b_rx) * ATT_S + kt * 16 + b_cx) * 2;
                ldm_x4(bH, smb + AKH * 2 + boff);
                ldm_x4(bL, smb + AKL * 2 + boff);
#pragma unroll
                for (int nt = 0; nt < 2; nt++) {
                    float* cc = c[jt * 2 + nt];
                    mma16816(cc, aH, &bH[nt * 2]);
                    mma16816(cc, aH, &bL[nt * 2]);
                    mma16816(cc, aL, &bH[nt * 2]);
                }
            }
        }

        // ---- softmax ----
        {
            float m0 = -1e30f, m1 = -1e30f;
#pragma unroll
            for (int t = 0; t < 32; t++) {
                m0 = fmaxf(m0, fmaxf(c[t][0], c[t][1]));
                m1 = fmaxf(m1, fmaxf(c[t][2], c[t][3]));
            }
            m0 = fmaxf(m0, __shfl_xor_sync(0xffffffffu, m0, 1));
            m0 = fmaxf(m0, __shfl_xor_sync(0xffffffffu, m0, 2));
            m1 = fmaxf(m1, __shfl_xor_sync(0xffffffffu, m1, 1));
            m1 = fmaxf(m1, __shfl_xor_sync(0xffffffffu, m1, 2));
            float s0 = 0.f, s1 = 0.f;
#pragma unroll
            for (int t = 0; t < 32; t++) {
                c[t][0] = __expf(c[t][0] - m0); s0 += c[t][0];
                c[t][1] = __expf(c[t][1] - m0); s0 += c[t][1];
                c[t][2] = __expf(c[t][2] - m1); s1 += c[t][2];
                c[t][3] = __expf(c[t][3] - m1); s1 += c[t][3];
            }
            s0 += __shfl_xor_sync(0xffffffffu, s0, 1);
            s0 += __shfl_xor_sync(0xffffffffu, s0, 2);
            s1 += __shfl_xor_sync(0xffffffffu, s1, 1);
            s1 += __shfl_xor_sync(0xffffffffu, s1, 2);
            float i0 = 1.f / s0, i1 = 1.f / s1;
#pragma unroll
            for (int t = 0; t < 32; t++) {
                c[t][0] *= i0; c[t][1] *= i0; c[t][2] *= i1; c[t][3] *= i1;
            }
        }

        // ---- O = P V ----
        float o[8][4];
#pragma unroll
        for (int j = 0; j < 8; j++)
#pragma unroll
            for (int k = 0; k < 4; k++) o[j][k] = 0.f;

#pragma unroll
        for (int kt = 0; kt < 16; kt++) {
            uint32_t aH[4], aL[4];
            split2(c[2 * kt][0], c[2 * kt][1], aH[0], aL[0]);
            split2(c[2 * kt][2], c[2 * kt][3], aH[1], aL[1]);
            split2(c[2 * kt + 1][0], c[2 * kt + 1][1], aH[2], aL[2]);
            split2(c[2 * kt + 1][2], c[2 * kt + 1][3], aH[3], aL[3]);
#pragma unroll
            for (int db = 0; db < 4; db++) {
                uint32_t bH[4], bL[4];
                uint32_t boff = (uint32_t)((kt * 16 + v_rx) * ATT_S + db * 16 + v_cx) * 2;
                ldm_x4_t(bH, smb + AVH * 2 + boff);
                ldm_x4_t(bL, smb + AVL * 2 + boff);
#pragma unroll
                for (int nt = 0; nt < 2; nt++) {
                    float* oo = o[db * 2 + nt];
                    mma16816(oo, aH, &bH[nt * 2]);
                    mma16816(oo, aH, &bL[nt * 2]);
                    mma16816(oo, aL, &bH[nt * 2]);
                }
            }
        }

        // ---- store ----
        {
            int row0 = qt * 128 + r0 + (lane >> 2);
            int row1 = row0 + 8;
            size_t b0 = ((size_t)z * 1024 + row0) * 512 + h * 64 + (lane & 3) * 2;
            size_t b1 = ((size_t)z * 1024 + row1) * 512 + h * 64 + (lane & 3) * 2;
#pragma unroll
            for (int nt = 0; nt < 8; nt++) {
                uint32_t h0, l0, h1, l1;
                split2(o[nt][0], o[nt][1], h0, l0);
                split2(o[nt][2], o[nt][3], h1, l1);
                *(uint32_t*)&aohi[b0 + nt * 8] = h0;
                *(uint32_t*)&aolo[b0 + nt * 8] = l0;
                *(uint32_t*)&aohi[b1 + nt * 8] = h1;
                *(uint32_t*)&aolo[b1 + nt * 8] = l1;
            }
        }
        if (qt < 7) {
            CP_WAIT0();
            __syncthreads();
        }
    }
}

// ==================== launch ====================
extern "C" void kernel_launch(void* const* d_in, const int* in_sizes, int n_in,
                              void* d_out, int out_size) {
    const float* x        = (const float*)d_in[0];
    const float* y        = (const float*)d_in[1];
    const float* q_dw_w   = (const float*)d_in[2];
    const float* q_bn_g   = (const float*)d_in[3];
    const float* q_bn_b   = (const float*)d_in[4];
    const float* q_bn_m   = (const float*)d_in[5];
    const float* q_bn_v   = (const float*)d_in[6];
    const float* q_pw_w   = (const float*)d_in[7];
    const float* kv_dw_w  = (const float*)d_in[8];
    const float* kv_bn_g  = (const float*)d_in[9];
    const float* kv_bn_b  = (const float*)d_in[10];
    const float* kv_bn_m  = (const float*)d_in[11];
    const float* kv_bn_v  = (const float*)d_in[12];
    const float* kv_pw_w  = (const float*)d_in[13];
    const float* out_w    = (const float*)d_in[14];
    const float* out_b    = (const float*)d_in[15];
    float* out = (float*)d_out;

    __nv_bfloat16 *p_hqT_hi, *p_hqT_lo, *p_hkvT_hi, *p_hkvT_lo;
    __nv_bfloat16 *p_wq_hi, *p_wq_lo, *p_wkv_hi, *p_wkv_lo, *p_wo_hi, *p_wo_lo;
    __nv_bfloat16 *p_qs_hi, *p_qs_lo, *p_kvs_hi, *p_kvs_lo, *p_ao_hi, *p_ao_lo;
    cudaGetSymbolAddress((void**)&p_hqT_hi,  g_hqT_hi);
    cudaGetSymbolAddress((void**)&p_hqT_lo,  g_hqT_lo);
    cudaGetSymbolAddress((void**)&p_hkvT_hi, g_hkvT_hi);
    cudaGetSymbolAddress((void**)&p_hkvT_lo, g_hkvT_lo);
    cudaGetSymbolAddress((void**)&p_wq_hi,  g_wq_hi);
    cudaGetSymbolAddress((void**)&p_wq_lo,  g_wq_lo);
    cudaGetSymbolAddress((void**)&p_wkv_hi, g_wkv_hi);
    cudaGetSymbolAddress((void**)&p_wkv_lo, g_wkv_lo);
    cudaGetSymbolAddress((void**)&p_wo_hi,  g_wo_hi);
    cudaGetSymbolAddress((void**)&p_wo_lo,  g_wo_lo);
    cudaGetSymbolAddress((void**)&p_qs_hi,  g_qs_hi);
    cudaGetSymbolAddress((void**)&p_qs_lo,  g_qs_lo);
    cudaGetSymbolAddress((void**)&p_kvs_hi, g_kvs_hi);
    cudaGetSymbolAddress((void**)&p_kvs_lo, g_kvs_lo);
    cudaGetSymbolAddress((void**)&p_ao_hi,  g_ao_hi);
    cudaGetSymbolAddress((void**)&p_ao_lo,  g_ao_lo);

    cudaFuncSetAttribute(attn_mma,
                         cudaFuncAttributeMaxDynamicSharedMemorySize, ATT_SMEM);
    cudaFuncSetAttribute(gemm_dual,
                         cudaFuncAttributeMaxDynamicSharedMemorySize, GEMM_SMEM);
    cudaFuncSetAttribute(gemm_out,
                         cudaFuncAttributeMaxDynamicSharedMemorySize, GEMM_SMEM);

    // 1) merged dw conv + BN + transpose + split
    {
        dim3 blk(32, 8);
        dim3 grid(32, 8, 32);
        dw_bn_split2<<<grid, blk>>>(x, y,
                                    q_dw_w, q_bn_g, q_bn_b, q_bn_m, q_bn_v,
                                    kv_dw_w, kv_bn_g, kv_bn_b, kv_bn_m, kv_bn_v,
                                    p_hqT_hi, p_hqT_lo, p_hkvT_hi, p_hkvT_lo);
    }
    // 2) merged weight splits
    wsplit_all<<<2048, 256>>>(q_pw_w, kv_pw_w, out_w,
                              p_wq_hi, p_wq_lo, p_wkv_hi, p_wkv_lo, p_wo_hi, p_wo_lo);
    // 3) merged q + kv pointwise GEMMs
    {
        dim3 grid(48, 16);
        gemm_dual<<<grid, 256, GEMM_SMEM>>>(p_hqT_hi, p_hqT_lo, p_wq_hi, p_wq_lo,
                                            p_qs_hi, p_qs_lo,
                                            p_hkvT_hi, p_hkvT_lo, p_wkv_hi, p_wkv_lo,
                                            p_kvs_hi, p_kvs_lo);
    }
    // 4) persistent-KV attention
    {
        dim3 grid(8, 16);
        attn_mma<<<grid, 256, ATT_SMEM>>>(p_qs_hi, p_qs_lo, p_kvs_hi, p_kvs_lo,
                                          p_ao_hi, p_ao_lo);
    }
    // 5) out projection
    {
        dim3 grid(8, 2, 16);
        gemm_out<<<grid, 256, GEMM_SMEM>>>(p_wo_hi, p_wo_lo, p_ao_hi, p_ao_lo,
                                           out, out_b);
    }
}

// round 8
// speedup vs baseline: 2.3965x; 1.0015x over previous
#include <cuda_runtime.h>
#include <cuda_bf16.h>
#include <math.h>
#include <cstdint>

#define BN_EPS 1e-5f

// ==================== PTX helpers (baseline, sm_103-safe) ====================
__device__ __forceinline__ uint32_t smem_u32(const void* p) {
    uint32_t a;
    asm("{ .reg .u64 t; cvta.to.shared.u64 t, %1; cvt.u32.u64 %0, t; }" : "=r"(a) : "l"(p));
    return a;
}
__device__ __forceinline__ void ldm_x4(uint32_t* r, uint32_t addr) {
    asm volatile("ldmatrix.sync.aligned.m8n8.x4.shared.b16 {%0,%1,%2,%3}, [%4];"
                 : "=r"(r[0]), "=r"(r[1]), "=r"(r[2]), "=r"(r[3]) : "r"(addr));
}
__device__ __forceinline__ void ldm_x4_t(uint32_t* r, uint32_t addr) {
    asm volatile("ldmatrix.sync.aligned.m8n8.x4.trans.shared.b16 {%0,%1,%2,%3}, [%4];"
                 : "=r"(r[0]), "=r"(r[1]), "=r"(r[2]), "=r"(r[3]) : "r"(addr));
}
__device__ __forceinline__ void mma16816(float* d, const uint32_t* a, const uint32_t* b) {
    asm volatile("mma.sync.aligned.m16n8k16.row.col.f32.bf16.bf16.f32 "
        "{%0,%1,%2,%3}, {%4,%5,%6,%7}, {%8,%9}, {%0,%1,%2,%3};"
        : "+f"(d[0]), "+f"(d[1]), "+f"(d[2]), "+f"(d[3])
        : "r"(a[0]), "r"(a[1]), "r"(a[2]), "r"(a[3]), "r"(b[0]), "r"(b[1]));
}
__device__ __forceinline__ void split2(float x, float y, uint32_t &hi, uint32_t &lo) {
    asm("cvt.rn.bf16x2.f32 %0, %1, %2;" : "=r"(hi) : "f"(y), "f"(x));
    float xh = __uint_as_float(hi << 16);
    float yh = __uint_as_float(hi & 0xffff0000u);
    asm("cvt.rn.bf16x2.f32 %0, %1, %2;" : "=r"(lo) : "f"(y - yh), "f"(x - xh));
}
__device__ __forceinline__ void cpa16(uint32_t saddr, const void* g) {
    asm volatile("cp.async.cg.shared.global [%0], [%1], 16;" :: "r"(saddr), "l"(g));
}
#define CP_COMMIT() asm volatile("cp.async.commit_group;" ::: "memory")
#define CP_WAIT1()  asm volatile("cp.async.wait_group 1;" ::: "memory")
#define CP_WAIT0()  asm volatile("cp.async.wait_group 0;" ::: "memory")

// ==================== scratch ====================
__device__ __nv_bfloat16 g_hqT_hi [16u * 1024 * 256];
__device__ __nv_bfloat16 g_hqT_lo [16u * 1024 * 256];
__device__ __nv_bfloat16 g_hkvT_hi[16u * 256 * 256];
__device__ __nv_bfloat16 g_hkvT_lo[16u * 256 * 256];
__device__ __nv_bfloat16 g_wq_hi [512 * 256],  g_wq_lo [512 * 256];
__device__ __nv_bfloat16 g_wkv_hi[1024 * 256], g_wkv_lo[1024 * 256];
__device__ __nv_bfloat16 g_wo_hi [256 * 512],  g_wo_lo [256 * 512];
__device__ __nv_bfloat16 g_qs_hi [16u * 1024 * 512], g_qs_lo [16u * 1024 * 512];
__device__ __nv_bfloat16 g_kvs_hi[16u * 256 * 1024], g_kvs_lo[16u * 256 * 1024];
__device__ __nv_bfloat16 g_ao_hi [16u * 1024 * 512], g_ao_lo [16u * 1024 * 512];

// ==================== merged dw conv + BN + transpose + split ====================
__global__ void dw_bn_split2(const float* __restrict__ x, const float* __restrict__ y,
                             const float* __restrict__ qw, const float* __restrict__ qg,
                             const float* __restrict__ qb, const float* __restrict__ qm,
                             const float* __restrict__ qv,
                             const float* __restrict__ kw, const float* __restrict__ kg,
                             const float* __restrict__ kb, const float* __restrict__ km,
                             const float* __restrict__ kvv,
                             __nv_bfloat16* __restrict__ qhi, __nv_bfloat16* __restrict__ qlo,
                             __nv_bfloat16* __restrict__ khi, __nv_bfloat16* __restrict__ klo) {
    const int zz = blockIdx.z;
    const bool isQ = (zz < 16);
    if (!isQ && blockIdx.x >= 8) return;
    __shared__ float t[32][33];
    const int z = isQ ? zz : zz - 16;
    const int b = z & 7;
    const int HO = isQ ? 32 : 16;
    const int stride = isQ ? 1 : 2;
    const float* in = (z >= 8) ? y : x;
    const float* w     = isQ ? qw : kw;
    const float* gamma = isQ ? qg : kg;
    const float* beta  = isQ ? qb : kb;
    const float* mean  = isQ ? qm : km;
    const float* var   = isQ ? qv : kvv;
    __nv_bfloat16* hi = isQ ? qhi : khi;
    __nv_bfloat16* lo = isQ ? qlo : klo;

    const int HW = HO * HO;
    const int hw0 = blockIdx.x * 32, c0 = blockIdx.y * 32;
    const int tx = threadIdx.x, ty = threadIdx.y;
    const int hw = hw0 + tx;
    const int oh = hw / HO, ow = hw % HO;
    const int ih0 = oh * stride - 1, iw0 = ow * stride - 1;
#pragma unroll
    for (int r = 0; r < 4; r++) {
        int c = c0 + ty + r * 8;
        const float* ip = in + (size_t)(b * 256 + c) * 1024;
        const float* wp = w + c * 9;
        float acc = 0.f;
#pragma unroll
        for (int kh = 0; kh < 3; kh++) {
            int ih = ih0 + kh;
            if (ih < 0 || ih > 31) continue;
#pragma unroll
            for (int kw2 = 0; kw2 < 3; kw2++) {
                int iw = iw0 + kw2;
                if (iw < 0 || iw > 31) continue;
                acc += wp[kh * 3 + kw2] * ip[ih * 32 + iw];
            }
        }
        float sc = gamma[c] * rsqrtf(var[c] + BN_EPS);
        float sh = beta[c] - mean[c] * sc;
        t[ty + r * 8][tx] = acc * sc + sh;
    }
    __syncthreads();
    size_t ob = (size_t)z * HW * 256;
#pragma unroll
    for (int r = 0; r < 4; r++) {
        float v = t[tx][ty + r * 8];
        __nv_bfloat16 hh = __float2bfloat16(v);
        size_t o = ob + (size_t)(hw0 + ty + r * 8) * 256 + c0 + tx;
        hi[o] = hh;
        lo[o] = __float2bfloat16(v - __bfloat162float(hh));
    }
}

// ==================== merged weight split ====================
__global__ void wsplit_all(const float* __restrict__ qw, const float* __restrict__ kvw,
                           const float* __restrict__ ow,
                           __nv_bfloat16* __restrict__ qhi, __nv_bfloat16* __restrict__ qlo,
                           __nv_bfloat16* __restrict__ kvhi, __nv_bfloat16* __restrict__ kvlo,
                           __nv_bfloat16* __restrict__ ohi, __nv_bfloat16* __restrict__ olo) {
    int i = blockIdx.x * 256 + threadIdx.x;
    const float* in; __nv_bfloat16 *hi, *lo; int j; float sc = 1.f;
    if (i < 131072)      { in = qw;  hi = qhi;  lo = qlo;  j = i;          sc = 0.125f; }
    else if (i < 393216) { in = kvw; hi = kvhi; lo = kvlo; j = i - 131072; }
    else                 { in = ow;  hi = ohi;  lo = olo;  j = i - 393216; }
    float v = in[j] * sc;
    __nv_bfloat16 h = __float2bfloat16(v);
    hi[j] = h;
    lo[j] = __float2bfloat16(v - __bfloat162float(h));
}

// ==================== cp.async bf16-split GEMM core ====================
#define SMS 40
#define OPB (128 * SMS * 2)
#define GEMM_SMEM (2 * 4 * OPB)

__device__ __forceinline__ void gemm_issue(
    uint32_t smb, int stage,
    const __nv_bfloat16* Ah, const __nv_bfloat16* Al,
    const __nv_bfloat16* Bh, const __nv_bfloat16* Bl,
    int m0, int n0, int K, int k0, int rid, int cid) {
    uint32_t sb = smb + (uint32_t)stage * 4 * OPB;
    uint32_t s0 = (uint32_t)(rid * SMS + cid) * 2;
    uint32_t s1 = (uint32_t)((rid + 64) * SMS + cid) * 2;
    cpa16(sb + s0,           &Ah[(size_t)(m0 + rid) * K + k0 + cid]);
    cpa16(sb + s1,           &Ah[(size_t)(m0 + rid + 64) * K + k0 + cid]);
    cpa16(sb + OPB + s0,     &Al[(size_t)(m0 + rid) * K + k0 + cid]);
    cpa16(sb + OPB + s1,     &Al[(size_t)(m0 + rid + 64) * K + k0 + cid]);
    cpa16(sb + 2 * OPB + s0, &Bh[(size_t)(n0 + rid) * K + k0 + cid]);
    cpa16(sb + 2 * OPB + s1, &Bh[(size_t)(n0 + rid + 64) * K + k0 + cid]);
    cpa16(sb + 3 * OPB + s0, &Bl[(size_t)(n0 + rid) * K + k0 + cid]);
    cpa16(sb + 3 * OPB + s1, &Bl[(size_t)(n0 + rid + 64) * K + k0 + cid]);
}

template <bool SPLIT>
__device__ __forceinline__ void gemm_core(
    uint32_t smb,
    const __nv_bfloat16* Ah, const __nv_bfloat16* Al,
    const __nv_bfloat16* Bh, const __nv_bfloat16* Bl,
    float* Cf, __nv_bfloat16* Chi, __nv_bfloat16* Clo,
    const float* bias, int N, int K, int m0, int n0) {
    const int tid = threadIdx.x, lane = tid & 31, wid = tid >> 5;
    const int warp_m = wid & 3, warp_n = wid >> 2;

    float acc[2][8][4];
#pragma unroll
    for (int i = 0; i < 2; i++)
#pragma unroll
        for (int j = 0; j < 8; j++)
#pragma unroll
            for (int k = 0; k < 4; k++) acc[i][j][k] = 0.f;

    const int rid = tid >> 2;
    const int cid = (tid & 3) * 8;
    const int a_row = warp_m * 32 + (lane & 15);
    const int a_colx = (lane >> 4) << 3;
    const int b_row = warp_n * 64 + (lane & 7) + ((lane >> 4) << 3);
    const int b_colx = ((lane >> 3) & 1) << 3;

    const int nk = K / 32;
    gemm_issue(smb, 0, Ah, Al, Bh, Bl, m0, n0, K, 0, rid, cid);
    CP_COMMIT();

    for (int i = 0; i < nk; i++) {
        const int stage = i & 1;
        if (i + 1 < nk) {
            gemm_issue(smb, stage ^ 1, Ah, Al, Bh, Bl, m0, n0, K, (i + 1) * 32, rid, cid);
            CP_COMMIT();
            CP_WAIT1();
        } else {
            CP_WAIT0();
        }
        __syncthreads();

        const uint32_t base = smb + (uint32_t)stage * 4 * OPB;
#pragma unroll
        for (int ks = 0; ks < 2; ks++) {
            const int kc = ks * 16;
            uint32_t ah[2][4], al[2][4];
#pragma unroll
            for (int mt = 0; mt < 2; mt++) {
                uint32_t off = (uint32_t)((a_row + mt * 16) * SMS + kc + a_colx) * 2;
                ldm_x4(ah[mt], base + off);
                ldm_x4(al[mt], base + OPB + off);
            }
#pragma unroll
            for (int ng = 0; ng < 4; ng++) {
                uint32_t bh[4], bl[4];
                uint32_t off = (uint32_t)((b_row + ng * 16) * SMS + kc + b_colx) * 2;
                ldm_x4(bh, base + 2 * OPB + off);
                ldm_x4(bl, base + 3 * OPB + off);
                // term-major ordering: same-accumulator dependency gap = 3
#pragma unroll
                for (int mt = 0; mt < 2; mt++)
#pragma unroll
                    for (int nt = 0; nt < 2; nt++)
                        mma16816(acc[mt][ng * 2 + nt], ah[mt], &bh[nt * 2]);
#pragma unroll
                for (int mt = 0; mt < 2; mt++)
#pragma unroll
                    for (int nt = 0; nt < 2; nt++)
                        mma16816(acc[mt][ng * 2 + nt], ah[mt], &bl[nt * 2]);
#pragma unroll
                for (int mt = 0; mt < 2; mt++)
#pragma unroll
                    for (int nt = 0; nt < 2; nt++)
                        mma16816(acc[mt][ng * 2 + nt], al[mt], &bh[nt * 2]);
            }
        }
        __syncthreads();
    }

#pragma unroll
    for (int mt = 0; mt < 2; mt++) {
        int mrow0 = m0 + warp_m * 32 + mt * 16 + (lane >> 2);
        int mrow1 = mrow0 + 8;
        float bv0 = (!SPLIT && bias) ? bias[mrow0] : 0.f;
        float bv1 = (!SPLIT && bias) ? bias[mrow1] : 0.f;
#pragma unroll
        for (int j = 0; j < 8; j++) {
            int n = n0 + warp_n * 64 + j * 8 + (lane & 3) * 2;
            float* c = acc[mt][j];
            if (SPLIT) {
                uint32_t h0, l0, h1, l1;
                split2(c[0], c[1], h0, l0);
                split2(c[2], c[3], h1, l1);
                size_t o0 = (size_t)mrow0 * N + n;
                size_t o1 = (size_t)mrow1 * N + n;
                *(uint32_t*)&Chi[o0] = h0; *(uint32_t*)&Clo[o0] = l0;
                *(uint32_t*)&Chi[o1] = h1; *(uint32_t*)&Clo[o1] = l1;
            } else {
                *(float2*)&Cf[(size_t)mrow0 * N + n] = make_float2(c[0] + bv0, c[1] + bv0);
                *(float2*)&Cf[(size_t)mrow1 * N + n] = make_float2(c[2] + bv1, c[3] + bv1);
            }
        }
    }
}

// ---- merged q + kv pointwise GEMMs.  grid (48, 16) ----
__global__ void __launch_bounds__(256)
gemm_dual(const __nv_bfloat16* __restrict__ qAh, const __nv_bfloat16* __restrict__ qAl,
          const __nv_bfloat16* __restrict__ qBh, const __nv_bfloat16* __restrict__ qBl,
          __nv_bfloat16* __restrict__ qChi, __nv_bfloat16* __restrict__ qClo,
          const __nv_bfloat16* __restrict__ kAh, const __nv_bfloat16* __restrict__ kAl,
          const __nv_bfloat16* __restrict__ kBh, const __nv_bfloat16* __restrict__ kBl,
          __nv_bfloat16* __restrict__ kChi, __nv_bfloat16* __restrict__ kClo) {
    extern __shared__ __nv_bfloat16 gsm[];
    const uint32_t smb = smem_u32(gsm);
    const int bx = blockIdx.x, z = blockIdx.y;
    if (bx < 32) {
        int m0 = (bx >> 2) * 128, n0 = (bx & 3) * 128;
        gemm_core<true>(smb,
            qAh + (size_t)z * 1024 * 256, qAl + (size_t)z * 1024 * 256,
            qBh, qBl,
            nullptr, qChi + (size_t)z * 1024 * 512, qClo + (size_t)z * 1024 * 512,
            nullptr, 512, 256, m0, n0);
    } else {
        int bk = bx - 32;
        int m0 = (bk >> 3) * 128, n0 = (bk & 7) * 128;
        gemm_core<true>(smb,
            kAh + (size_t)z * 256 * 256, kAl + (size_t)z * 256 * 256,
            kBh, kBl,
            nullptr, kChi + (size_t)z * 256 * 1024, kClo + (size_t)z * 256 * 1024,
            nullptr, 1024, 256, m0, n0);
    }
}

// ---- out projection GEMM.  grid (8, 2, 16) ----
__global__ void __launch_bounds__(256)
gemm_out(const __nv_bfloat16* __restrict__ Ah, const __nv_bfloat16* __restrict__ Al,
         const __nv_bfloat16* __restrict__ Bh, const __nv_bfloat16* __restrict__ Bl,
         float* __restrict__ Cf, const float* __restrict__ bias) {
    extern __shared__ __nv_bfloat16 gsm[];
    const uint32_t smb = smem_u32(gsm);
    const int z = blockIdx.z;
    int m0 = blockIdx.y * 128, n0 = blockIdx.x * 128;
    gemm_core<false>(smb,
        Ah, Al,
        Bh + (size_t)z * 1024 * 512, Bl + (size_t)z * 1024 * 512,
        Cf + (size_t)z * 256 * 1024, nullptr, nullptr,
        bias, 1024, 512, m0, n0);
}

// ==================== persistent-KV attention ====================
#define ATT_S 72
#define AQBUF(s) ((s) * (2 * 128 * ATT_S))
#define AQL_OFF (128 * ATT_S)
#define AKH (4 * 128 * ATT_S)
#define AKL (AKH + 256 * ATT_S)
#define AVH (AKH + 2 * 256 * ATT_S)
#define AVL (AKH + 3 * 256 * ATT_S)
#define ATT_SMEM ((4 * 128 + 4 * 256) * ATT_S * 2)   // 221184 B

__device__ __forceinline__ void att_stage_q(uint32_t smb, int buf,
                                            const __nv_bfloat16* qhi, const __nv_bfloat16* qlo,
                                            size_t qb, int tid) {
    uint32_t base = smb + (uint32_t)AQBUF(buf) * 2;
    for (int i = tid; i < 1024; i += 256) {
        int row = i >> 3, ch = (i & 7) * 8;
        uint32_t so = (uint32_t)(row * ATT_S + ch) * 2;
        cpa16(base + so,               &qhi[qb + (size_t)row * 512 + ch]);
        cpa16(base + AQL_OFF * 2 + so, &qlo[qb + (size_t)row * 512 + ch]);
    }
}

__global__ void __launch_bounds__(256, 1)
attn_mma(const __nv_bfloat16* __restrict__ qhi, const __nv_bfloat16* __restrict__ qlo,
         const __nv_bfloat16* __restrict__ kvhi, const __nv_bfloat16* __restrict__ kvlo,
         __nv_bfloat16* __restrict__ aohi, __nv_bfloat16* __restrict__ aolo) {
    extern __shared__ __nv_bfloat16 sm[];
    const int tid = threadIdx.x, lane = tid & 31, wid = tid >> 5;
    const int h = blockIdx.x, z = blockIdx.y;
    const int zk = ((z >> 3) ^ 1) * 8 + (z & 7);
    const uint32_t smb = smem_u32(sm);

    {
        size_t kb = (size_t)zk * 256 * 1024 + h * 64;
        size_t vb = kb + 512;
        for (int i = tid; i < 2048; i += 256) {
            int row = i >> 3, ch = (i & 7) * 8;
            uint32_t so = (uint32_t)(row * ATT_S + ch) * 2;
            cpa16(smb + AKH * 2 + so, &kvhi[kb + (size_t)row * 1024 + ch]);
            cpa16(smb + AKL * 2 + so, &kvlo[kb + (size_t)row * 1024 + ch]);
            cpa16(smb + AVH * 2 + so, &kvhi[vb + (size_t)row * 1024 + ch]);
            cpa16(smb + AVL * 2 + so, &kvlo[vb + (size_t)row * 1024 + ch]);
        }
        att_stage_q(smb, 0, qhi, qlo, ((size_t)z * 1024) * 512 + h * 64, tid);
        CP_COMMIT();
        CP_WAIT0();
        __syncthreads();
    }

    const int r0 = wid * 16;
    const int a_row = r0 + (lane & 15);
    const int a_cx = (lane >> 4) << 3;
    const int b_rx = (lane & 7) + ((lane >> 4) << 3);
    const int b_cx = ((lane >> 3) & 1) << 3;
    const int v_rx = (lane & 7) + (((lane >> 3) & 1) << 3);
    const int v_cx = (lane >> 4) << 3;

    for (int qt = 0; qt < 8; qt++) {
        if (qt < 7) {
            att_stage_q(smb, (qt + 1) & 1, qhi, qlo,
                        ((size_t)z * 1024 + (qt + 1) * 128) * 512 + h * 64, tid);
            CP_COMMIT();
        }
        const uint32_t qbase = smb + (uint32_t)AQBUF(qt & 1) * 2;

        // ---- S = Q K^T  (term-major, jt-pairs: gap-3 dependency spacing) ----
        float c[32][4];
#pragma unroll
        for (int t = 0; t < 32; t++)
#pragma unroll
            for (int k = 0; k < 4; k++) c[t][k] = 0.f;

#pragma unroll
        for (int kt = 0; kt < 4; kt++) {
            uint32_t aH[4], aL[4];
            uint32_t aoff = (uint32_t)(a_row * ATT_S + kt * 16 + a_cx) * 2;
            ldm_x4(aH, qbase + aoff);
            ldm_x4(aL, qbase + AQL_OFF * 2 + aoff);
#pragma unroll
            for (int jt = 0; jt < 16; jt += 2) {
                uint32_t bH0[4], bL0[4], bH1[4], bL1[4];
                uint32_t bo0 = (uint32_t)((jt * 16 + b_rx) * ATT_S + kt * 16 + b_cx) * 2;
                uint32_t bo1 = (uint32_t)(((jt + 1) * 16 + b_rx) * ATT_S + kt * 16 + b_cx) * 2;
                ldm_x4(bH0, smb + AKH * 2 + bo0);
                ldm_x4(bL0, smb + AKL * 2 + bo0);
                ldm_x4(bH1, smb + AKH * 2 + bo1);
                ldm_x4(bL1, smb + AKL * 2 + bo1);
                float *c0 = c[jt * 2], *c1 = c[jt * 2 + 1];
                float *c2 = c[jt * 2 + 2], *c3 = c[jt * 2 + 3];
                mma16816(c0, aH, &bH0[0]); mma16816(c1, aH, &bH0[2]);
                mma16816(c2, aH, &bH1[0]); mma16816(c3, aH, &bH1[2]);
                mma16816(c0, aH, &bL0[0]); mma16816(c1, aH, &bL0[2]);
                mma16816(c2, aH, &bL1[0]); mma16816(c3, aH, &bL1[2]);
                mma16816(c0, aL, &bH0[0]); mma16816(c1, aL, &bH0[2]);
                mma16816(c2, aL, &bH1[0]); mma16816(c3, aL, &bH1[2]);
            }
        }

        // ---- softmax ----
        {
            float m0 = -1e30f, m1 = -1e30f;
#pragma unroll
            for (int t = 0; t < 32; t++) {
                m0 = fmaxf(m0, fmaxf(c[t][0], c[t][1]));
                m1 = fmaxf(m1, fmaxf(c[t][2], c[t][3]));
            }
            m0 = fmaxf(m0, __shfl_xor_sync(0xffffffffu, m0, 1));
            m0 = fmaxf(m0, __shfl_xor_sync(0xffffffffu, m0, 2));
            m1 = fmaxf(m1, __shfl_xor_sync(0xffffffffu, m1, 1));
            m1 = fmaxf(m1, __shfl_xor_sync(0xffffffffu, m1, 2));
            float s0 = 0.f, s1 = 0.f;
#pragma unroll
            for (int t = 0; t < 32; t++) {
                c[t][0] = __expf(c[t][0] - m0); s0 += c[t][0];
                c[t][1] = __expf(c[t][1] - m0); s0 += c[t][1];
                c[t][2] = __expf(c[t][2] - m1); s1 += c[t][2];
                c[t][3] = __expf(c[t][3] - m1); s1 += c[t][3];
            }
            s0 += __shfl_xor_sync(0xffffffffu, s0, 1);
            s0 += __shfl_xor_sync(0xffffffffu, s0, 2);
            s1 += __shfl_xor_sync(0xffffffffu, s1, 1);
            s1 += __shfl_xor_sync(0xffffffffu, s1, 2);
            float i0 = 1.f / s0, i1 = 1.f / s1;
#pragma unroll
            for (int t = 0; t < 32; t++) {
                c[t][0] *= i0; c[t][1] *= i0; c[t][2] *= i1; c[t][3] *= i1;
            }
        }

        // ---- O = P V  (term-major, db-pairs: gap-3) ----
        float o[8][4];
#pragma unroll
        for (int j = 0; j < 8; j++)
#pragma unroll
            for (int k = 0; k < 4; k++) o[j][k] = 0.f;

#pragma unroll
        for (int kt = 0; kt < 16; kt++) {
            uint32_t aH[4], aL[4];
            split2(c[2 * kt][0], c[2 * kt][1], aH[0], aL[0]);
            split2(c[2 * kt][2], c[2 * kt][3], aH[1], aL[1]);
            split2(c[2 * kt + 1][0], c[2 * kt + 1][1], aH[2], aL[2]);
            split2(c[2 * kt + 1][2], c[2 * kt + 1][3], aH[3], aL[3]);
#pragma unroll
            for (int db = 0; db < 4; db += 2) {
                uint32_t bH0[4], bL0[4], bH1[4], bL1[4];
                uint32_t bo0 = (uint32_t)((kt * 16 + v_rx) * ATT_S + db * 16 + v_cx) * 2;
                uint32_t bo1 = (uint32_t)((kt * 16 + v_rx) * ATT_S + (db + 1) * 16 + v_cx) * 2;
                ldm_x4_t(bH0, smb + AVH * 2 + bo0);
                ldm_x4_t(bL0, smb + AVL * 2 + bo0);
                ldm_x4_t(bH1, smb + AVH * 2 + bo1);
                ldm_x4_t(bL1, smb + AVL * 2 + bo1);
                float *o0 = o[db * 2], *o1 = o[db * 2 + 1];
                float *o2 = o[db * 2 + 2], *o3 = o[db * 2 + 3];
                mma16816(o0, aH, &bH0[0]); mma16816(o1, aH, &bH0[2]);
                mma16816(o2, aH, &bH1[0]); mma16816(o3, aH, &bH1[2]);
                mma16816(o0, aH, &bL0[0]); mma16816(o1, aH, &bL0[2]);
                mma16816(o2, aH, &bL1[0]); mma16816(o3, aH, &bL1[2]);
                mma16816(o0, aL, &bH0[0]); mma16816(o1, aL, &bH0[2]);
                mma16816(o2, aL, &bH1[0]); mma16816(o3, aL, &bH1[2]);
            }
        }

        // ---- store ----
        {
            int row0 = qt * 128 + r0 + (lane >> 2);
            int row1 = row0 + 8;
            size_t b0 = ((size_t)z * 1024 + row0) * 512 + h * 64 + (lane & 3) * 2;
            size_t b1 = ((size_t)z * 1024 + row1) * 512 + h * 64 + (lane & 3) * 2;
#pragma unroll
            for (int nt = 0; nt < 8; nt++) {
                uint32_t h0, l0, h1, l1;
                split2(o[nt][0], o[nt][1], h0, l0);
                split2(o[nt][2], o[nt][3], h1, l1);
                *(uint32_t*)&aohi[b0 + nt * 8] = h0;
                *(uint32_t*)&aolo[b0 + nt * 8] = l0;
                *(uint32_t*)&aohi[b1 + nt * 8] = h1;
                *(uint32_t*)&aolo[b1 + nt * 8] = l1;
            }
        }
        if (qt < 7) {
            CP_WAIT0();
            __syncthreads();
        }
    }
}

// ==================== launch ====================
extern "C" void kernel_launch(void* const* d_in, const int* in_sizes, int n_in,
                              void* d_out, int out_size) {
    const float* x        = (const float*)d_in[0];
    const float* y        = (const float*)d_in[1];
    const float* q_dw_w   = (const float*)d_in[2];
    const float* q_bn_g   = (const float*)d_in[3];
    const float* q_bn_b   = (const float*)d_in[4];
    const float* q_bn_m   = (const float*)d_in[5];
    const float* q_bn_v   = (const float*)d_in[6];
    const float* q_pw_w   = (const float*)d_in[7];
    const float* kv_dw_w  = (const float*)d_in[8];
    const float* kv_bn_g  = (const float*)d_in[9];
    const float* kv_bn_b  = (const float*)d_in[10];
    const float* kv_bn_m  = (const float*)d_in[11];
    const float* kv_bn_v  = (const float*)d_in[12];
    const float* kv_pw_w  = (const float*)d_in[13];
    const float* out_w    = (const float*)d_in[14];
    const float* out_b    = (const float*)d_in[15];
    float* out = (float*)d_out;

    __nv_bfloat16 *p_hqT_hi, *p_hqT_lo, *p_hkvT_hi, *p_hkvT_lo;
    __nv_bfloat16 *p_wq_hi, *p_wq_lo, *p_wkv_hi, *p_wkv_lo, *p_wo_hi, *p_wo_lo;
    __nv_bfloat16 *p_qs_hi, *p_qs_lo, *p_kvs_hi, *p_kvs_lo, *p_ao_hi, *p_ao_lo;
    cudaGetSymbolAddress((void**)&p_hqT_hi,  g_hqT_hi);
    cudaGetSymbolAddress((void**)&p_hqT_lo,  g_hqT_lo);
    cudaGetSymbolAddress((void**)&p_hkvT_hi, g_hkvT_hi);
    cudaGetSymbolAddress((void**)&p_hkvT_lo, g_hkvT_lo);
    cudaGetSymbolAddress((void**)&p_wq_hi,  g_wq_hi);
    cudaGetSymbolAddress((void**)&p_wq_lo,  g_wq_lo);
    cudaGetSymbolAddress((void**)&p_wkv_hi, g_wkv_hi);
    cudaGetSymbolAddress((void**)&p_wkv_lo, g_wkv_lo);
    cudaGetSymbolAddress((void**)&p_wo_hi,  g_wo_hi);
    cudaGetSymbolAddress((void**)&p_wo_lo,  g_wo_lo);
    cudaGetSymbolAddress((void**)&p_qs_hi,  g_qs_hi);
    cudaGetSymbolAddress((void**)&p_qs_lo,  g_qs_lo);
    cudaGetSymbolAddress((void**)&p_kvs_hi, g_kvs_hi);
    cudaGetSymbolAddress((void**)&p_kvs_lo, g_kvs_lo);
    cudaGetSymbolAddress((void**)&p_ao_hi,  g_ao_hi);
    cudaGetSymbolAddress((void**)&p_ao_lo,  g_ao_lo);

    cudaFuncSetAttribute(attn_mma,
                         cudaFuncAttributeMaxDynamicSharedMemorySize, ATT_SMEM);
    cudaFuncSetAttribute(gemm_dual,
                         cudaFuncAttributeMaxDynamicSharedMemorySize, GEMM_SMEM);
    cudaFuncSetAttribute(gemm_out,
                         cudaFuncAttributeMaxDynamicSharedMemorySize, GEMM_SMEM);

    {
        dim3 blk(32, 8);
        dim3 grid(32, 8, 32);
        dw_bn_split2<<<grid, blk>>>(x, y,
                                    q_dw_w, q_bn_g, q_bn_b, q_bn_m, q_bn_v,
                                    kv_dw_w, kv_bn_g, kv_bn_b, kv_bn_m, kv_bn_v,
                                    p_hqT_hi, p_hqT_lo, p_hkvT_hi, p_hkvT_lo);
    }
    wsplit_all<<<2048, 256>>>(q_pw_w, kv_pw_w, out_w,
                              p_wq_hi, p_wq_lo, p_wkv_hi, p_wkv_lo, p_wo_hi, p_wo_lo);
    {
        dim3 grid(48, 16);
        gemm_dual<<<grid, 256, GEMM_SMEM>>>(p_hqT_hi, p_hqT_lo, p_wq_hi, p_wq_lo,
                                            p_qs_hi, p_qs_lo,
                                            p_hkvT_hi, p_hkvT_lo, p_wkv_hi, p_wkv_lo,
                                            p_kvs_hi, p_kvs_lo);
    }
    {
        dim3 grid(8, 16);
        attn_mma<<<grid, 256, ATT_SMEM>>>(p_qs_hi, p_qs_lo, p_kvs_hi, p_kvs_lo,
                                          p_ao_hi, p_ao_lo);
    }
    {
        dim3 grid(8, 2, 16);
        gemm_out<<<grid, 256, GEMM_SMEM>>>(p_wo_hi, p_wo_lo, p_ao_hi, p_ao_lo,
                                           out, out_b);
    }
}

// round 9
// speedup vs baseline: 2.4780x; 1.0340x over previous
#include <cuda_runtime.h>
#include <cuda_bf16.h>
#include <math.h>
#include <cstdint>

#define BN_EPS 1e-5f

// ==================== PTX helpers (baseline, sm_103-safe) ====================
__device__ __forceinline__ uint32_t smem_u32(const void* p) {
    uint32_t a;
    asm("{ .reg .u64 t; cvta.to.shared.u64 t, %1; cvt.u32.u64 %0, t; }" : "=r"(a) : "l"(p));
    return a;
}
__device__ __forceinline__ void ldm_x4(uint32_t* r, uint32_t addr) {
    asm volatile("ldmatrix.sync.aligned.m8n8.x4.shared.b16 {%0,%1,%2,%3}, [%4];"
                 : "=r"(r[0]), "=r"(r[1]), "=r"(r[2]), "=r"(r[3]) : "r"(addr));
}
__device__ __forceinline__ void ldm_x4_t(uint32_t* r, uint32_t addr) {
    asm volatile("ldmatrix.sync.aligned.m8n8.x4.trans.shared.b16 {%0,%1,%2,%3}, [%4];"
                 : "=r"(r[0]), "=r"(r[1]), "=r"(r[2]), "=r"(r[3]) : "r"(addr));
}
__device__ __forceinline__ void mma16816(float* d, const uint32_t* a, const uint32_t* b) {
    asm volatile("mma.sync.aligned.m16n8k16.row.col.f32.bf16.bf16.f32 "
        "{%0,%1,%2,%3}, {%4,%5,%6,%7}, {%8,%9}, {%0,%1,%2,%3};"
        : "+f"(d[0]), "+f"(d[1]), "+f"(d[2]), "+f"(d[3])
        : "r"(a[0]), "r"(a[1]), "r"(a[2]), "r"(a[3]), "r"(b[0]), "r"(b[1]));
}
__device__ __forceinline__ void split2(float x, float y, uint32_t &hi, uint32_t &lo) {
    asm("cvt.rn.bf16x2.f32 %0, %1, %2;" : "=r"(hi) : "f"(y), "f"(x));
    float xh = __uint_as_float(hi << 16);
    float yh = __uint_as_float(hi & 0xffff0000u);
    asm("cvt.rn.bf16x2.f32 %0, %1, %2;" : "=r"(lo) : "f"(y - yh), "f"(x - xh));
}
__device__ __forceinline__ void cpa16(uint32_t saddr, const void* g) {
    asm volatile("cp.async.cg.shared.global [%0], [%1], 16;" :: "r"(saddr), "l"(g));
}
#define CP_COMMIT() asm volatile("cp.async.commit_group;" ::: "memory")
#define CP_WAIT1()  asm volatile("cp.async.wait_group 1;" ::: "memory")
#define CP_WAIT0()  asm volatile("cp.async.wait_group 0;" ::: "memory")

// ==================== scratch ====================
__device__ __nv_bfloat16 g_hqT_hi [16u * 1024 * 256];
__device__ __nv_bfloat16 g_hqT_lo [16u * 1024 * 256];
__device__ __nv_bfloat16 g_hkvT_hi[16u * 256 * 256];
__device__ __nv_bfloat16 g_hkvT_lo[16u * 256 * 256];
__device__ __nv_bfloat16 g_wq_hi [512 * 256],  g_wq_lo [512 * 256];
__device__ __nv_bfloat16 g_wkv_hi[1024 * 256], g_wkv_lo[1024 * 256];
__device__ __nv_bfloat16 g_wo_hi [256 * 512],  g_wo_lo [256 * 512];
__device__ __nv_bfloat16 g_qs_hi [16u * 1024 * 512], g_qs_lo [16u * 1024 * 512];
__device__ __nv_bfloat16 g_kvs_hi[16u * 256 * 1024], g_kvs_lo[16u * 256 * 1024];
__device__ __nv_bfloat16 g_ao_hi [16u * 1024 * 512], g_ao_lo [16u * 1024 * 512];

// ==================== merged dw conv + BN + transpose + split ====================
__global__ void dw_bn_split2(const float* __restrict__ x, const float* __restrict__ y,
                             const float* __restrict__ qw, const float* __restrict__ qg,
                             const float* __restrict__ qb, const float* __restrict__ qm,
                             const float* __restrict__ qv,
                             const float* __restrict__ kw, const float* __restrict__ kg,
                             const float* __restrict__ kb, const float* __restrict__ km,
                             const float* __restrict__ kvv,
                             __nv_bfloat16* __restrict__ qhi, __nv_bfloat16* __restrict__ qlo,
                             __nv_bfloat16* __restrict__ khi, __nv_bfloat16* __restrict__ klo) {
    const int zz = blockIdx.z;
    const bool isQ = (zz < 16);
    if (!isQ && blockIdx.x >= 8) return;
    __shared__ float t[32][33];
    const int z = isQ ? zz : zz - 16;
    const int b = z & 7;
    const int HO = isQ ? 32 : 16;
    const int stride = isQ ? 1 : 2;
    const float* in = (z >= 8) ? y : x;
    const float* w     = isQ ? qw : kw;
    const float* gamma = isQ ? qg : kg;
    const float* beta  = isQ ? qb : kb;
    const float* mean  = isQ ? qm : km;
    const float* var   = isQ ? qv : kvv;
    __nv_bfloat16* hi = isQ ? qhi : khi;
    __nv_bfloat16* lo = isQ ? qlo : klo;

    const int HW = HO * HO;
    const int hw0 = blockIdx.x * 32, c0 = blockIdx.y * 32;
    const int tx = threadIdx.x, ty = threadIdx.y;
    const int hw = hw0 + tx;
    const int oh = hw / HO, ow = hw % HO;
    const int ih0 = oh * stride - 1, iw0 = ow * stride - 1;
#pragma unroll
    for (int r = 0; r < 4; r++) {
        int c = c0 + ty + r * 8;
        const float* ip = in + (size_t)(b * 256 + c) * 1024;
        const float* wp = w + c * 9;
        float acc = 0.f;
#pragma unroll
        for (int kh = 0; kh < 3; kh++) {
            int ih = ih0 + kh;
            if (ih < 0 || ih > 31) continue;
#pragma unroll
            for (int kw2 = 0; kw2 < 3; kw2++) {
                int iw = iw0 + kw2;
                if (iw < 0 || iw > 31) continue;
                acc += wp[kh * 3 + kw2] * ip[ih * 32 + iw];
            }
        }
        float sc = gamma[c] * rsqrtf(var[c] + BN_EPS);
        float sh = beta[c] - mean[c] * sc;
        t[ty + r * 8][tx] = acc * sc + sh;
    }
    __syncthreads();
    size_t ob = (size_t)z * HW * 256;
#pragma unroll
    for (int r = 0; r < 4; r++) {
        float v = t[tx][ty + r * 8];
        __nv_bfloat16 hh = __float2bfloat16(v);
        size_t o = ob + (size_t)(hw0 + ty + r * 8) * 256 + c0 + tx;
        hi[o] = hh;
        lo[o] = __float2bfloat16(v - __bfloat162float(hh));
    }
}

// ==================== merged weight split ====================
__global__ void wsplit_all(const float* __restrict__ qw, const float* __restrict__ kvw,
                           const float* __restrict__ ow,
                           __nv_bfloat16* __restrict__ qhi, __nv_bfloat16* __restrict__ qlo,
                           __nv_bfloat16* __restrict__ kvhi, __nv_bfloat16* __restrict__ kvlo,
                           __nv_bfloat16* __restrict__ ohi, __nv_bfloat16* __restrict__ olo) {
    int i = blockIdx.x * 256 + threadIdx.x;
    const float* in; __nv_bfloat16 *hi, *lo; int j; float sc = 1.f;
    if (i < 131072)      { in = qw;  hi = qhi;  lo = qlo;  j = i;          sc = 0.125f; }
    else if (i < 393216) { in = kvw; hi = kvhi; lo = kvlo; j = i - 131072; }
    else                 { in = ow;  hi = ohi;  lo = olo;  j = i - 393216; }
    float v = in[j] * sc;
    __nv_bfloat16 h = __float2bfloat16(v);
    hi[j] = h;
    lo[j] = __float2bfloat16(v - __bfloat162float(h));
}

// ==================== cp.async bf16-split GEMM core ====================
#define SMS 40
#define OPB (128 * SMS * 2)
#define GEMM_SMEM (2 * 4 * OPB)

__device__ __forceinline__ void gemm_issue(
    uint32_t smb, int stage,
    const __nv_bfloat16* Ah, const __nv_bfloat16* Al,
    const __nv_bfloat16* Bh, const __nv_bfloat16* Bl,
    int m0, int n0, int K, int k0, int rid, int cid) {
    uint32_t sb = smb + (uint32_t)stage * 4 * OPB;
    uint32_t s0 = (uint32_t)(rid * SMS + cid) * 2;
    uint32_t s1 = (uint32_t)((rid + 64) * SMS + cid) * 2;
    cpa16(sb + s0,           &Ah[(size_t)(m0 + rid) * K + k0 + cid]);
    cpa16(sb + s1,           &Ah[(size_t)(m0 + rid + 64) * K + k0 + cid]);
    cpa16(sb + OPB + s0,     &Al[(size_t)(m0 + rid) * K + k0 + cid]);
    cpa16(sb + OPB + s1,     &Al[(size_t)(m0 + rid + 64) * K + k0 + cid]);
    cpa16(sb + 2 * OPB + s0, &Bh[(size_t)(n0 + rid) * K + k0 + cid]);
    cpa16(sb + 2 * OPB + s1, &Bh[(size_t)(n0 + rid + 64) * K + k0 + cid]);
    cpa16(sb + 3 * OPB + s0, &Bl[(size_t)(n0 + rid) * K + k0 + cid]);
    cpa16(sb + 3 * OPB + s1, &Bl[(size_t)(n0 + rid + 64) * K + k0 + cid]);
}

template <bool SPLIT>
__device__ __forceinline__ void gemm_core(
    uint32_t smb,
    const __nv_bfloat16* Ah, const __nv_bfloat16* Al,
    const __nv_bfloat16* Bh, const __nv_bfloat16* Bl,
    float* Cf, __nv_bfloat16* Chi, __nv_bfloat16* Clo,
    const float* bias, int N, int K, int m0, int n0) {
    const int tid = threadIdx.x, lane = tid & 31, wid = tid >> 5;
    const int warp_m = wid & 3, warp_n = wid >> 2;

    float acc[2][8][4];
#pragma unroll
    for (int i = 0; i < 2; i++)
#pragma unroll
        for (int j = 0; j < 8; j++)
#pragma unroll
            for (int k = 0; k < 4; k++) acc[i][j][k] = 0.f;

    const int rid = tid >> 2;
    const int cid = (tid & 3) * 8;
    const int a_row = warp_m * 32 + (lane & 15);
    const int a_colx = (lane >> 4) << 3;
    const int b_row = warp_n * 64 + (lane & 7) + ((lane >> 4) << 3);
    const int b_colx = ((lane >> 3) & 1) << 3;

    const int nk = K / 32;
    gemm_issue(smb, 0, Ah, Al, Bh, Bl, m0, n0, K, 0, rid, cid);
    CP_COMMIT();

    for (int i = 0; i < nk; i++) {
        const int stage = i & 1;
        if (i + 1 < nk) {
            gemm_issue(smb, stage ^ 1, Ah, Al, Bh, Bl, m0, n0, K, (i + 1) * 32, rid, cid);
            CP_COMMIT();
            CP_WAIT1();
        } else {
            CP_WAIT0();
        }
        __syncthreads();

        const uint32_t base = smb + (uint32_t)stage * 4 * OPB;
#pragma unroll
        for (int ks = 0; ks < 2; ks++) {
            const int kc = ks * 16;
            uint32_t ah[2][4], al[2][4];
#pragma unroll
            for (int mt = 0; mt < 2; mt++) {
                uint32_t off = (uint32_t)((a_row + mt * 16) * SMS + kc + a_colx) * 2;
                ldm_x4(ah[mt], base + off);
                ldm_x4(al[mt], base + OPB + off);
            }
#pragma unroll
            for (int ng = 0; ng < 4; ng++) {
                uint32_t bh[4], bl[4];
                uint32_t off = (uint32_t)((b_row + ng * 16) * SMS + kc + b_colx) * 2;
                ldm_x4(bh, base + 2 * OPB + off);
                ldm_x4(bl, base + 3 * OPB + off);
#pragma unroll
                for (int mt = 0; mt < 2; mt++)
#pragma unroll
                    for (int nt = 0; nt < 2; nt++)
                        mma16816(acc[mt][ng * 2 + nt], ah[mt], &bh[nt * 2]);
#pragma unroll
                for (int mt = 0; mt < 2; mt++)
#pragma unroll
                    for (int nt = 0; nt < 2; nt++)
                        mma16816(acc[mt][ng * 2 + nt], ah[mt], &bl[nt * 2]);
#pragma unroll
                for (int mt = 0; mt < 2; mt++)
#pragma unroll
                    for (int nt = 0; nt < 2; nt++)
                        mma16816(acc[mt][ng * 2 + nt], al[mt], &bh[nt * 2]);
            }
        }
        __syncthreads();
    }

#pragma unroll
    for (int mt = 0; mt < 2; mt++) {
        int mrow0 = m0 + warp_m * 32 + mt * 16 + (lane >> 2);
        int mrow1 = mrow0 + 8;
        float bv0 = (!SPLIT && bias) ? bias[mrow0] : 0.f;
        float bv1 = (!SPLIT && bias) ? bias[mrow1] : 0.f;
#pragma unroll
        for (int j = 0; j < 8; j++) {
            int n = n0 + warp_n * 64 + j * 8 + (lane & 3) * 2;
            float* c = acc[mt][j];
            if (SPLIT) {
                uint32_t h0, l0, h1, l1;
                split2(c[0], c[1], h0, l0);
                split2(c[2], c[3], h1, l1);
                size_t o0 = (size_t)mrow0 * N + n;
                size_t o1 = (size_t)mrow1 * N + n;
                *(uint32_t*)&Chi[o0] = h0; *(uint32_t*)&Clo[o0] = l0;
                *(uint32_t*)&Chi[o1] = h1; *(uint32_t*)&Clo[o1] = l1;
            } else {
                *(float2*)&Cf[(size_t)mrow0 * N + n] = make_float2(c[0] + bv0, c[1] + bv0);
                *(float2*)&Cf[(size_t)mrow1 * N + n] = make_float2(c[2] + bv1, c[3] + bv1);
            }
        }
    }
}

// ---- merged q + kv pointwise GEMMs.  grid (48, 16) ----
__global__ void __launch_bounds__(256, 2)
gemm_dual(const __nv_bfloat16* __restrict__ qAh, const __nv_bfloat16* __restrict__ qAl,
          const __nv_bfloat16* __restrict__ qBh, const __nv_bfloat16* __restrict__ qBl,
          __nv_bfloat16* __restrict__ qChi, __nv_bfloat16* __restrict__ qClo,
          const __nv_bfloat16* __restrict__ kAh, const __nv_bfloat16* __restrict__ kAl,
          const __nv_bfloat16* __restrict__ kBh, const __nv_bfloat16* __restrict__ kBl,
          __nv_bfloat16* __restrict__ kChi, __nv_bfloat16* __restrict__ kClo) {
    extern __shared__ __nv_bfloat16 gsm[];
    const uint32_t smb = smem_u32(gsm);
    const int bx = blockIdx.x, z = blockIdx.y;
    if (bx < 32) {
        int m0 = (bx >> 2) * 128, n0 = (bx & 3) * 128;
        gemm_core<true>(smb,
            qAh + (size_t)z * 1024 * 256, qAl + (size_t)z * 1024 * 256,
            qBh, qBl,
            nullptr, qChi + (size_t)z * 1024 * 512, qClo + (size_t)z * 1024 * 512,
            nullptr, 512, 256, m0, n0);
    } else {
        int bk = bx - 32;
        int m0 = (bk >> 3) * 128, n0 = (bk & 7) * 128;
        gemm_core<true>(smb,
            kAh + (size_t)z * 256 * 256, kAl + (size_t)z * 256 * 256,
            kBh, kBl,
            nullptr, kChi + (size_t)z * 256 * 1024, kClo + (size_t)z * 256 * 1024,
            nullptr, 1024, 256, m0, n0);
    }
}

// ---- out projection GEMM.  grid (8, 2, 16) ----
__global__ void __launch_bounds__(256, 2)
gemm_out(const __nv_bfloat16* __restrict__ Ah, const __nv_bfloat16* __restrict__ Al,
         const __nv_bfloat16* __restrict__ Bh, const __nv_bfloat16* __restrict__ Bl,
         float* __restrict__ Cf, const float* __restrict__ bias) {
    extern __shared__ __nv_bfloat16 gsm[];
    const uint32_t smb = smem_u32(gsm);
    const int z = blockIdx.z;
    int m0 = blockIdx.y * 128, n0 = blockIdx.x * 128;
    gemm_core<false>(smb,
        Ah, Al,
        Bh + (size_t)z * 1024 * 512, Bl + (size_t)z * 1024 * 512,
        Cf + (size_t)z * 256 * 1024, nullptr, nullptr,
        bias, 1024, 512, m0, n0);
}

// ==================== persistent-KV attention, independent warps ====================
// grid (8 heads, 16 z), 256 threads. K/V staged once (block-wide).
// Each warp then runs its own 16-row q-tiles with per-warp cp.async Q staging —
// NO block barriers in the main loop (warps drift => softmax overlaps mma).
#define ATT_S 72
#define AKH 0
#define AKL (AKH + 256 * ATT_S)
#define AVH (AKH + 2 * 256 * ATT_S)
#define AVL (AKH + 3 * 256 * ATT_S)
#define AQW (4 * 256 * ATT_S)                         // per-warp Q slots after K/V
#define QSLOT (2 * 16 * ATT_S)                        // halves per (warp,buf): hi+lo
#define ATT_SMEM ((4 * 256 + 8 * 2 * 2 * 16) * ATT_S * 2)   // 221184 B

// stage one warp's 16x64 Q tile (hi+lo) into its smem slot
__device__ __forceinline__ void att_stage_qw(uint32_t smb, int wid, int buf,
                                             const __nv_bfloat16* qhi,
                                             const __nv_bfloat16* qlo,
                                             size_t qb, int lane) {
    uint32_t base = smb + (uint32_t)(AQW + (wid * 2 + buf) * QSLOT) * 2;
#pragma unroll
    for (int j = 0; j < 4; j++) {
        int idx = j * 32 + lane;            // 0..127
        int row = idx >> 3, ch = (idx & 7) * 8;
        uint32_t so = (uint32_t)(row * ATT_S + ch) * 2;
        cpa16(base + so,                    &qhi[qb + (size_t)row * 512 + ch]);
        cpa16(base + 16 * ATT_S * 2 + so,   &qlo[qb + (size_t)row * 512 + ch]);
    }
}

__global__ void __launch_bounds__(256, 1)
attn_mma(const __nv_bfloat16* __restrict__ qhi, const __nv_bfloat16* __restrict__ qlo,
         const __nv_bfloat16* __restrict__ kvhi, const __nv_bfloat16* __restrict__ kvlo,
         __nv_bfloat16* __restrict__ aohi, __nv_bfloat16* __restrict__ aolo) {
    extern __shared__ __nv_bfloat16 sm[];
    const int tid = threadIdx.x, lane = tid & 31, wid = tid >> 5;
    const int h = blockIdx.x, z = blockIdx.y;
    const int zk = ((z >> 3) ^ 1) * 8 + (z & 7);
    const uint32_t smb = smem_u32(sm);

    // ---- stage K/V (block-wide) + warp's Q tile 0 ----
    {
        size_t kb = (size_t)zk * 256 * 1024 + h * 64;
        size_t vb = kb + 512;
        for (int i = tid; i < 2048; i += 256) {
            int row = i >> 3, ch = (i & 7) * 8;
            uint32_t so = (uint32_t)(row * ATT_S + ch) * 2;
            cpa16(smb + AKH * 2 + so, &kvhi[kb + (size_t)row * 1024 + ch]);
            cpa16(smb + AKL * 2 + so, &kvlo[kb + (size_t)row * 1024 + ch]);
            cpa16(smb + AVH * 2 + so, &kvhi[vb + (size_t)row * 1024 + ch]);
            cpa16(smb + AVL * 2 + so, &kvlo[vb + (size_t)row * 1024 + ch]);
        }
        att_stage_qw(smb, wid, 0, qhi, qlo,
                     ((size_t)z * 1024 + wid * 16) * 512 + h * 64, lane);
        CP_COMMIT();
        CP_WAIT0();
        __syncthreads();   // K/V visible to all warps; last block sync
    }

    const int a_row = lane & 15;
    const int a_cx = (lane >> 4) << 3;
    const int b_rx = (lane & 7) + ((lane >> 4) << 3);
    const int b_cx = ((lane >> 3) & 1) << 3;
    const int v_rx = (lane & 7) + (((lane >> 3) & 1) << 3);
    const int v_cx = (lane >> 4) << 3;

    for (int i = 0; i < 8; i++) {
        const int r0g = i * 128 + wid * 16;      // this warp's global q-row base
        const uint32_t qbase = smb + (uint32_t)(AQW + (wid * 2 + (i & 1)) * QSLOT) * 2;

        // ---- S = Q K^T ----
        float c[32][4];
#pragma unroll
        for (int t = 0; t < 32; t++)
#pragma unroll
            for (int k = 0; k < 4; k++) c[t][k] = 0.f;

#pragma unroll
        for (int kt = 0; kt < 4; kt++) {
            uint32_t aH[4], aL[4];
            uint32_t aoff = (uint32_t)(a_row * ATT_S + kt * 16 + a_cx) * 2;
            ldm_x4(aH, qbase + aoff);
            ldm_x4(aL, qbase + 16 * ATT_S * 2 + aoff);
#pragma unroll
            for (int jt = 0; jt < 16; jt += 2) {
                uint32_t bH0[4], bL0[4], bH1[4], bL1[4];
                uint32_t bo0 = (uint32_t)((jt * 16 + b_rx) * ATT_S + kt * 16 + b_cx) * 2;
                uint32_t bo1 = (uint32_t)(((jt + 1) * 16 + b_rx) * ATT_S + kt * 16 + b_cx) * 2;
                ldm_x4(bH0, smb + AKH * 2 + bo0);
                ldm_x4(bL0, smb + AKL * 2 + bo0);
                ldm_x4(bH1, smb + AKH * 2 + bo1);
                ldm_x4(bL1, smb + AKL * 2 + bo1);
                float *c0 = c[jt * 2], *c1 = c[jt * 2 + 1];
                float *c2 = c[jt * 2 + 2], *c3 = c[jt * 2 + 3];
                mma16816(c0, aH, &bH0[0]); mma16816(c1, aH, &bH0[2]);
                mma16816(c2, aH, &bH1[0]); mma16816(c3, aH, &bH1[2]);
                mma16816(c0, aH, &bL0[0]); mma16816(c1, aH, &bL0[2]);
                mma16816(c2, aH, &bL1[0]); mma16816(c3, aH, &bL1[2]);
                mma16816(c0, aL, &bH0[0]); mma16816(c1, aL, &bH0[2]);
                mma16816(c2, aL, &bH1[0]); mma16816(c3, aL, &bH1[2]);
            }
        }

        // ---- kick off next tile's Q staging (latency hides behind softmax+PV) ----
        if (i < 7) {
            att_stage_qw(smb, wid, (i + 1) & 1, qhi, qlo,
                         ((size_t)z * 1024 + (i + 1) * 128 + wid * 16) * 512 + h * 64, lane);
            CP_COMMIT();
        }

        // ---- softmax ----
        {
            float m0 = -1e30f, m1 = -1e30f;
#pragma unroll
            for (int t = 0; t < 32; t++) {
                m0 = fmaxf(m0, fmaxf(c[t][0], c[t][1]));
                m1 = fmaxf(m1, fmaxf(c[t][2], c[t][3]));
            }
            m0 = fmaxf(m0, __shfl_xor_sync(0xffffffffu, m0, 1));
            m0 = fmaxf(m0, __shfl_xor_sync(0xffffffffu, m0, 2));
            m1 = fmaxf(m1, __shfl_xor_sync(0xffffffffu, m1, 1));
            m1 = fmaxf(m1, __shfl_xor_sync(0xffffffffu, m1, 2));
            float s0 = 0.f, s1 = 0.f;
#pragma unroll
            for (int t = 0; t < 32; t++) {
                c[t][0] = __expf(c[t][0] - m0); s0 += c[t][0];
                c[t][1] = __expf(c[t][1] - m0); s0 += c[t][1];
                c[t][2] = __expf(c[t][2] - m1); s1 += c[t][2];
                c[t][3] = __expf(c[t][3] - m1); s1 += c[t][3];
            }
            s0 += __shfl_xor_sync(0xffffffffu, s0, 1);
            s0 += __shfl_xor_sync(0xffffffffu, s0, 2);
            s1 += __shfl_xor_sync(0xffffffffu, s1, 1);
            s1 += __shfl_xor_sync(0xffffffffu, s1, 2);
            float i0 = 1.f / s0, i1 = 1.f / s1;
#pragma unroll
            for (int t = 0; t < 32; t++) {
                c[t][0] *= i0; c[t][1] *= i0; c[t][2] *= i1; c[t][3] *= i1;
            }
        }

        // ---- O = P V ----
        float o[8][4];
#pragma unroll
        for (int j = 0; j < 8; j++)
#pragma unroll
            for (int k = 0; k < 4; k++) o[j][k] = 0.f;

#pragma unroll
        for (int kt = 0; kt < 16; kt++) {
            uint32_t aH[4], aL[4];
            split2(c[2 * kt][0], c[2 * kt][1], aH[0], aL[0]);
            split2(c[2 * kt][2], c[2 * kt][3], aH[1], aL[1]);
            split2(c[2 * kt + 1][0], c[2 * kt + 1][1], aH[2], aL[2]);
            split2(c[2 * kt + 1][2], c[2 * kt + 1][3], aH[3], aL[3]);
#pragma unroll
            for (int db = 0; db < 4; db += 2) {
                uint32_t bH0[4], bL0[4], bH1[4], bL1[4];
                uint32_t bo0 = (uint32_t)((kt * 16 + v_rx) * ATT_S + db * 16 + v_cx) * 2;
                uint32_t bo1 = (uint32_t)((kt * 16 + v_rx) * ATT_S + (db + 1) * 16 + v_cx) * 2;
                ldm_x4_t(bH0, smb + AVH * 2 + bo0);
                ldm_x4_t(bL0, smb + AVL * 2 + bo0);
                ldm_x4_t(bH1, smb + AVH * 2 + bo1);
                ldm_x4_t(bL1, smb + AVL * 2 + bo1);
                float *o0 = o[db * 2], *o1 = o[db * 2 + 1];
                float *o2 = o[db * 2 + 2], *o3 = o[db * 2 + 3];
                mma16816(o0, aH, &bH0[0]); mma16816(o1, aH, &bH0[2]);
                mma16816(o2, aH, &bH1[0]); mma16816(o3, aH, &bH1[2]);
                mma16816(o0, aH, &bL0[0]); mma16816(o1, aH, &bL0[2]);
                mma16816(o2, aH, &bL1[0]); mma16816(o3, aH, &bL1[2]);
                mma16816(o0, aL, &bH0[0]); mma16816(o1, aL, &bH0[2]);
                mma16816(o2, aL, &bH1[0]); mma16816(o3, aL, &bH1[2]);
            }
        }

        // ---- store bf16 hi/lo at [z][pos][512] ----
        {
            int row0 = r0g + (lane >> 2);
            int row1 = row0 + 8;
            size_t b0 = ((size_t)z * 1024 + row0) * 512 + h * 64 + (lane & 3) * 2;
            size_t b1 = ((size_t)z * 1024 + row1) * 512 + h * 64 + (lane & 3) * 2;
#pragma unroll
            for (int nt = 0; nt < 8; nt++) {
                uint32_t h0, l0, h1, l1;
                split2(o[nt][0], o[nt][1], h0, l0);
                split2(o[nt][2], o[nt][3], h1, l1);
                *(uint32_t*)&aohi[b0 + nt * 8] = h0;
                *(uint32_t*)&aolo[b0 + nt * 8] = l0;
                *(uint32_t*)&aohi[b1 + nt * 8] = h1;
                *(uint32_t*)&aolo[b1 + nt * 8] = l1;
            }
        }
        if (i < 7) CP_WAIT0();   // per-warp: next Q tile ready
    }
}

// ==================== launch ====================
extern "C" void kernel_launch(void* const* d_in, const int* in_sizes, int n_in,
                              void* d_out, int out_size) {
    const float* x        = (const float*)d_in[0];
    const float* y        = (const float*)d_in[1];
    const float* q_dw_w   = (const float*)d_in[2];
    const float* q_bn_g   = (const float*)d_in[3];
    const float* q_bn_b   = (const float*)d_in[4];
    const float* q_bn_m   = (const float*)d_in[5];
    const float* q_bn_v   = (const float*)d_in[6];
    const float* q_pw_w   = (const float*)d_in[7];
    const float* kv_dw_w  = (const float*)d_in[8];
    const float* kv_bn_g  = (const float*)d_in[9];
    const float* kv_bn_b  = (const float*)d_in[10];
    const float* kv_bn_m  = (const float*)d_in[11];
    const float* kv_bn_v  = (const float*)d_in[12];
    const float* kv_pw_w  = (const float*)d_in[13];
    const float* out_w    = (const float*)d_in[14];
    const float* out_b    = (const float*)d_in[15];
    float* out = (float*)d_out;

    __nv_bfloat16 *p_hqT_hi, *p_hqT_lo, *p_hkvT_hi, *p_hkvT_lo;
    __nv_bfloat16 *p_wq_hi, *p_wq_lo, *p_wkv_hi, *p_wkv_lo, *p_wo_hi, *p_wo_lo;
    __nv_bfloat16 *p_qs_hi, *p_qs_lo, *p_kvs_hi, *p_kvs_lo, *p_ao_hi, *p_ao_lo;
    cudaGetSymbolAddress((void**)&p_hqT_hi,  g_hqT_hi);
    cudaGetSymbolAddress((void**)&p_hqT_lo,  g_hqT_lo);
    cudaGetSymbolAddress((void**)&p_hkvT_hi, g_hkvT_hi);
    cudaGetSymbolAddress((void**)&p_hkvT_lo, g_hkvT_lo);
    cudaGetSymbolAddress((void**)&p_wq_hi,  g_wq_hi);
    cudaGetSymbolAddress((void**)&p_wq_lo,  g_wq_lo);
    cudaGetSymbolAddress((void**)&p_wkv_hi, g_wkv_hi);
    cudaGetSymbolAddress((void**)&p_wkv_lo, g_wkv_lo);
    cudaGetSymbolAddress((void**)&p_wo_hi,  g_wo_hi);
    cudaGetSymbolAddress((void**)&p_wo_lo,  g_wo_lo);
    cudaGetSymbolAddress((void**)&p_qs_hi,  g_qs_hi);
    cudaGetSymbolAddress((void**)&p_qs_lo,  g_qs_lo);
    cudaGetSymbolAddress((void**)&p_kvs_hi, g_kvs_hi);
    cudaGetSymbolAddress((void**)&p_kvs_lo, g_kvs_lo);
    cudaGetSymbolAddress((void**)&p_ao_hi,  g_ao_hi);
    cudaGetSymbolAddress((void**)&p_ao_lo,  g_ao_lo);

    cudaFuncSetAttribute(attn_mma,
                         cudaFuncAttributeMaxDynamicSharedMemorySize, ATT_SMEM);
    cudaFuncSetAttribute(gemm_dual,
                         cudaFuncAttributeMaxDynamicSharedMemorySize, GEMM_SMEM);
    cudaFuncSetAttribute(gemm_out,
                         cudaFuncAttributeMaxDynamicSharedMemorySize, GEMM_SMEM);

    {
        dim3 blk(32, 8);
        dim3 grid(32, 8, 32);
        dw_bn_split2<<<grid, blk>>>(x, y,
                                    q_dw_w, q_bn_g, q_bn_b, q_bn_m, q_bn_v,
                                    kv_dw_w, kv_bn_g, kv_bn_b, kv_bn_m, kv_bn_v,
                                    p_hqT_hi, p_hqT_lo, p_hkvT_hi, p_hkvT_lo);
    }
    wsplit_all<<<2048, 256>>>(q_pw_w, kv_pw_w, out_w,
                              p_wq_hi, p_wq_lo, p_wkv_hi, p_wkv_lo, p_wo_hi, p_wo_lo);
    {
        dim3 grid(48, 16);
        gemm_dual<<<grid, 256, GEMM_SMEM>>>(p_hqT_hi, p_hqT_lo, p_wq_hi, p_wq_lo,
                                            p_qs_hi, p_qs_lo,
                                            p_hkvT_hi, p_hkvT_lo, p_wkv_hi, p_wkv_lo,
                                            p_kvs_hi, p_kvs_lo);
    }
    {
        dim3 grid(8, 16);
        attn_mma<<<grid, 256, ATT_SMEM>>>(p_qs_hi, p_qs_lo, p_kvs_hi, p_kvs_lo,
                                          p_ao_hi, p_ao_lo);
    }
    {
        dim3 grid(8, 2, 16);
        gemm_out<<<grid, 256, GEMM_SMEM>>>(p_wo_hi, p_wo_lo, p_ao_hi, p_ao_lo,
                                           out, out_b);
    }
}

// round 10
// speedup vs baseline: 2.5922x; 1.0461x over previous
#include <cuda_runtime.h>
#include <cuda_bf16.h>
#include <math.h>
#include <cstdint>

#define BN_EPS 1e-5f

// ==================== PTX helpers (baseline, sm_103-safe) ====================
__device__ __forceinline__ uint32_t smem_u32(const void* p) {
    uint32_t a;
    asm("{ .reg .u64 t; cvta.to.shared.u64 t, %1; cvt.u32.u64 %0, t; }" : "=r"(a) : "l"(p));
    return a;
}
__device__ __forceinline__ void ldm_x4(uint32_t* r, uint32_t addr) {
    asm volatile("ldmatrix.sync.aligned.m8n8.x4.shared.b16 {%0,%1,%2,%3}, [%4];"
                 : "=r"(r[0]), "=r"(r[1]), "=r"(r[2]), "=r"(r[3]) : "r"(addr));
}
__device__ __forceinline__ void ldm_x4_t(uint32_t* r, uint32_t addr) {
    asm volatile("ldmatrix.sync.aligned.m8n8.x4.trans.shared.b16 {%0,%1,%2,%3}, [%4];"
                 : "=r"(r[0]), "=r"(r[1]), "=r"(r[2]), "=r"(r[3]) : "r"(addr));
}
__device__ __forceinline__ void mma16816(float* d, const uint32_t* a, const uint32_t* b) {
    asm volatile("mma.sync.aligned.m16n8k16.row.col.f32.bf16.bf16.f32 "
        "{%0,%1,%2,%3}, {%4,%5,%6,%7}, {%8,%9}, {%0,%1,%2,%3};"
        : "+f"(d[0]), "+f"(d[1]), "+f"(d[2]), "+f"(d[3])
        : "r"(a[0]), "r"(a[1]), "r"(a[2]), "r"(a[3]), "r"(b[0]), "r"(b[1]));
}
__device__ __forceinline__ void split2(float x, float y, uint32_t &hi, uint32_t &lo) {
    asm("cvt.rn.bf16x2.f32 %0, %1, %2;" : "=r"(hi) : "f"(y), "f"(x));
    float xh = __uint_as_float(hi << 16);
    float yh = __uint_as_float(hi & 0xffff0000u);
    asm("cvt.rn.bf16x2.f32 %0, %1, %2;" : "=r"(lo) : "f"(y - yh), "f"(x - xh));
}
__device__ __forceinline__ void cpa16(uint32_t saddr, const void* g) {
    asm volatile("cp.async.cg.shared.global [%0], [%1], 16;" :: "r"(saddr), "l"(g));
}
#define CP_COMMIT() asm volatile("cp.async.commit_group;" ::: "memory")
#define CP_WAIT1()  asm volatile("cp.async.wait_group 1;" ::: "memory")
#define CP_WAIT0()  asm volatile("cp.async.wait_group 0;" ::: "memory")

// ==================== scratch ====================
__device__ __nv_bfloat16 g_hqT_hi [16u * 1024 * 256];
__device__ __nv_bfloat16 g_hqT_lo [16u * 1024 * 256];
__device__ __nv_bfloat16 g_hkvT_hi[16u * 256 * 256];
__device__ __nv_bfloat16 g_hkvT_lo[16u * 256 * 256];
__device__ __nv_bfloat16 g_wq_hi [512 * 256],  g_wq_lo [512 * 256];
__device__ __nv_bfloat16 g_wkv_hi[1024 * 256], g_wkv_lo[1024 * 256];
__device__ __nv_bfloat16 g_wo_hi [256 * 512],  g_wo_lo [256 * 512];
__device__ __nv_bfloat16 g_qs_hi [16u * 1024 * 512], g_qs_lo [16u * 1024 * 512];
__device__ __nv_bfloat16 g_kvs_hi[16u * 256 * 1024], g_kvs_lo[16u * 256 * 1024];
__device__ __nv_bfloat16 g_ao_hi [16u * 1024 * 512], g_ao_lo [16u * 1024 * 512];

// ==================== merged dw conv + BN + transpose + split  (+ weight splits) ====================
// grid (32, 8, 33) block (32,8): z<16 q-path, 16<=z<32 kv-path, z==32 weight splits
__global__ void dw_bn_split2(const float* __restrict__ x, const float* __restrict__ y,
                             const float* __restrict__ qw, const float* __restrict__ qg,
                             const float* __restrict__ qb, const float* __restrict__ qm,
                             const float* __restrict__ qv,
                             const float* __restrict__ kw, const float* __restrict__ kg,
                             const float* __restrict__ kb, const float* __restrict__ km,
                             const float* __restrict__ kvv,
                             __nv_bfloat16* __restrict__ qhi, __nv_bfloat16* __restrict__ qlo,
                             __nv_bfloat16* __restrict__ khi, __nv_bfloat16* __restrict__ klo,
                             const float* __restrict__ qpw, const float* __restrict__ kvpw,
                             const float* __restrict__ ow,
                             __nv_bfloat16* __restrict__ wqhi, __nv_bfloat16* __restrict__ wqlo,
                             __nv_bfloat16* __restrict__ wkvhi, __nv_bfloat16* __restrict__ wkvlo,
                             __nv_bfloat16* __restrict__ wohi, __nv_bfloat16* __restrict__ wolo) {
    const int zz = blockIdx.z;
    const int tidf = threadIdx.y * 32 + threadIdx.x;
    if (zz == 32) {
        // weight splits: 256 blocks x 256 threads x 8 elems = 524288
        int bid = blockIdx.x * 8 + blockIdx.y;
        int i = (bid * 256 + tidf) * 8;
        const float* in; __nv_bfloat16 *hi, *lo; int j; float sc = 1.f;
        if (i < 131072)      { in = qpw;  hi = wqhi;  lo = wqlo;  j = i;          sc = 0.125f; }
        else if (i < 393216) { in = kvpw; hi = wkvhi; lo = wkvlo; j = i - 131072; }
        else                 { in = ow;   hi = wohi;  lo = wolo;  j = i - 393216; }
        float4 v0 = *(const float4*)&in[j];
        float4 v1 = *(const float4*)&in[j + 4];
        float f[8] = {v0.x, v0.y, v0.z, v0.w, v1.x, v1.y, v1.z, v1.w};
        __nv_bfloat16 hb[8], lb[8];
#pragma unroll
        for (int k = 0; k < 8; k++) {
            float v = f[k] * sc;
            hb[k] = __float2bfloat16(v);
            lb[k] = __float2bfloat16(v - __bfloat162float(hb[k]));
        }
        *(uint4*)&hi[j] = *(uint4*)hb;
        *(uint4*)&lo[j] = *(uint4*)lb;
        return;
    }
    const bool isQ = (zz < 16);
    if (!isQ && blockIdx.x >= 8) return;
    __shared__ float t[32][33];
    const int z = isQ ? zz : zz - 16;
    const int b = z & 7;
    const int HO = isQ ? 32 : 16;
    const int stride = isQ ? 1 : 2;
    const float* in = (z >= 8) ? y : x;
    const float* w     = isQ ? qw : kw;
    const float* gamma = isQ ? qg : kg;
    const float* beta  = isQ ? qb : kb;
    const float* mean  = isQ ? qm : km;
    const float* var   = isQ ? qv : kvv;
    __nv_bfloat16* hi = isQ ? qhi : khi;
    __nv_bfloat16* lo = isQ ? qlo : klo;

    const int HW = HO * HO;
    const int hw0 = blockIdx.x * 32, c0 = blockIdx.y * 32;
    const int tx = threadIdx.x, ty = threadIdx.y;
    const int hw = hw0 + tx;
    const int oh = hw / HO, ow2 = hw % HO;
    const int ih0 = oh * stride - 1, iw0 = ow2 * stride - 1;
#pragma unroll
    for (int r = 0; r < 4; r++) {
        int c = c0 + ty + r * 8;
        const float* ip = in + (size_t)(b * 256 + c) * 1024;
        const float* wp = w + c * 9;
        float acc = 0.f;
#pragma unroll
        for (int kh = 0; kh < 3; kh++) {
            int ih = ih0 + kh;
            if (ih < 0 || ih > 31) continue;
#pragma unroll
            for (int kw2 = 0; kw2 < 3; kw2++) {
                int iw = iw0 + kw2;
                if (iw < 0 || iw > 31) continue;
                acc += wp[kh * 3 + kw2] * ip[ih * 32 + iw];
            }
        }
        float sc = gamma[c] * rsqrtf(var[c] + BN_EPS);
        float sh = beta[c] - mean[c] * sc;
        t[ty + r * 8][tx] = acc * sc + sh;
    }
    __syncthreads();
    size_t ob = (size_t)z * HW * 256;
#pragma unroll
    for (int r = 0; r < 4; r++) {
        float v = t[tx][ty + r * 8];
        __nv_bfloat16 hh = __float2bfloat16(v);
        size_t o = ob + (size_t)(hw0 + ty + r * 8) * 256 + c0 + tx;
        hi[o] = hh;
        lo[o] = __float2bfloat16(v - __bfloat162float(hh));
    }
}

// ==================== cp.async bf16-split GEMM core ====================
#define SMS 40
#define OPB (128 * SMS * 2)
#define GEMM_SMEM (2 * 4 * OPB)

__device__ __forceinline__ void gemm_issue(
    uint32_t smb, int stage,
    const __nv_bfloat16* Ah, const __nv_bfloat16* Al,
    const __nv_bfloat16* Bh, const __nv_bfloat16* Bl,
    int m0, int n0, int K, int k0, int rid, int cid) {
    uint32_t sb = smb + (uint32_t)stage * 4 * OPB;
    uint32_t s0 = (uint32_t)(rid * SMS + cid) * 2;
    uint32_t s1 = (uint32_t)((rid + 64) * SMS + cid) * 2;
    cpa16(sb + s0,           &Ah[(size_t)(m0 + rid) * K + k0 + cid]);
    cpa16(sb + s1,           &Ah[(size_t)(m0 + rid + 64) * K + k0 + cid]);
    cpa16(sb + OPB + s0,     &Al[(size_t)(m0 + rid) * K + k0 + cid]);
    cpa16(sb + OPB + s1,     &Al[(size_t)(m0 + rid + 64) * K + k0 + cid]);
    cpa16(sb + 2 * OPB + s0, &Bh[(size_t)(n0 + rid) * K + k0 + cid]);
    cpa16(sb + 2 * OPB + s1, &Bh[(size_t)(n0 + rid + 64) * K + k0 + cid]);
    cpa16(sb + 3 * OPB + s0, &Bl[(size_t)(n0 + rid) * K + k0 + cid]);
    cpa16(sb + 3 * OPB + s1, &Bl[(size_t)(n0 + rid + 64) * K + k0 + cid]);
}

template <bool SPLIT>
__device__ __forceinline__ void gemm_core(
    uint32_t smb,
    const __nv_bfloat16* Ah, const __nv_bfloat16* Al,
    const __nv_bfloat16* Bh, const __nv_bfloat16* Bl,
    float* Cf, __nv_bfloat16* Chi, __nv_bfloat16* Clo,
    const float* bias, int N, int K, int m0, int n0) {
    const int tid = threadIdx.x, lane = tid & 31, wid = tid >> 5;
    const int warp_m = wid & 3, warp_n = wid >> 2;

    float acc[2][8][4];
#pragma unroll
    for (int i = 0; i < 2; i++)
#pragma unroll
        for (int j = 0; j < 8; j++)
#pragma unroll
            for (int k = 0; k < 4; k++) acc[i][j][k] = 0.f;

    const int rid = tid >> 2;
    const int cid = (tid & 3) * 8;
    const int a_row = warp_m * 32 + (lane & 15);
    const int a_colx = (lane >> 4) << 3;
    const int b_row = warp_n * 64 + (lane & 7) + ((lane >> 4) << 3);
    const int b_colx = ((lane >> 3) & 1) << 3;

    const int nk = K / 32;
    gemm_issue(smb, 0, Ah, Al, Bh, Bl, m0, n0, K, 0, rid, cid);
    CP_COMMIT();

    for (int i = 0; i < nk; i++) {
        const int stage = i & 1;
        if (i + 1 < nk) {
            gemm_issue(smb, stage ^ 1, Ah, Al, Bh, Bl, m0, n0, K, (i + 1) * 32, rid, cid);
            CP_COMMIT();
            CP_WAIT1();
        } else {
            CP_WAIT0();
        }
        __syncthreads();

        const uint32_t base = smb + (uint32_t)stage * 4 * OPB;
#pragma unroll
        for (int ks = 0; ks < 2; ks++) {
            const int kc = ks * 16;
            uint32_t ah[2][4], al[2][4];
#pragma unroll
            for (int mt = 0; mt < 2; mt++) {
                uint32_t off = (uint32_t)((a_row + mt * 16) * SMS + kc + a_colx) * 2;
                ldm_x4(ah[mt], base + off);
                ldm_x4(al[mt], base + OPB + off);
            }
#pragma unroll
            for (int ng = 0; ng < 4; ng++) {
                uint32_t bh[4], bl[4];
                uint32_t off = (uint32_t)((b_row + ng * 16) * SMS + kc + b_colx) * 2;
                ldm_x4(bh, base + 2 * OPB + off);
                ldm_x4(bl, base + 3 * OPB + off);
#pragma unroll
                for (int mt = 0; mt < 2; mt++)
#pragma unroll
                    for (int nt = 0; nt < 2; nt++)
                        mma16816(acc[mt][ng * 2 + nt], ah[mt], &bh[nt * 2]);
#pragma unroll
                for (int mt = 0; mt < 2; mt++)
#pragma unroll
                    for (int nt = 0; nt < 2; nt++)
                        mma16816(acc[mt][ng * 2 + nt], ah[mt], &bl[nt * 2]);
#pragma unroll
                for (int mt = 0; mt < 2; mt++)
#pragma unroll
                    for (int nt = 0; nt < 2; nt++)
                        mma16816(acc[mt][ng * 2 + nt], al[mt], &bh[nt * 2]);
            }
        }
        __syncthreads();
    }

#pragma unroll
    for (int mt = 0; mt < 2; mt++) {
        int mrow0 = m0 + warp_m * 32 + mt * 16 + (lane >> 2);
        int mrow1 = mrow0 + 8;
        float bv0 = (!SPLIT && bias) ? bias[mrow0] : 0.f;
        float bv1 = (!SPLIT && bias) ? bias[mrow1] : 0.f;
#pragma unroll
        for (int j = 0; j < 8; j++) {
            int n = n0 + warp_n * 64 + j * 8 + (lane & 3) * 2;
            float* c = acc[mt][j];
            if (SPLIT) {
                uint32_t h0, l0, h1, l1;
                split2(c[0], c[1], h0, l0);
                split2(c[2], c[3], h1, l1);
                size_t o0 = (size_t)mrow0 * N + n;
                size_t o1 = (size_t)mrow1 * N + n;
                *(uint32_t*)&Chi[o0] = h0; *(uint32_t*)&Clo[o0] = l0;
                *(uint32_t*)&Chi[o1] = h1; *(uint32_t*)&Clo[o1] = l1;
            } else {
                *(float2*)&Cf[(size_t)mrow0 * N + n] = make_float2(c[0] + bv0, c[1] + bv0);
                *(float2*)&Cf[(size_t)mrow1 * N + n] = make_float2(c[2] + bv1, c[3] + bv1);
            }
        }
    }
}

// ---- merged q + kv pointwise GEMMs.  grid (48, 16) ----
__global__ void __launch_bounds__(256, 2)
gemm_dual(const __nv_bfloat16* __restrict__ qAh, const __nv_bfloat16* __restrict__ qAl,
          const __nv_bfloat16* __restrict__ qBh, const __nv_bfloat16* __restrict__ qBl,
          __nv_bfloat16* __restrict__ qChi, __nv_bfloat16* __restrict__ qClo,
          const __nv_bfloat16* __restrict__ kAh, const __nv_bfloat16* __restrict__ kAl,
          const __nv_bfloat16* __restrict__ kBh, const __nv_bfloat16* __restrict__ kBl,
          __nv_bfloat16* __restrict__ kChi, __nv_bfloat16* __restrict__ kClo) {
    extern __shared__ __nv_bfloat16 gsm[];
    const uint32_t smb = smem_u32(gsm);
    const int bx = blockIdx.x, z = blockIdx.y;
    if (bx < 32) {
        int m0 = (bx >> 2) * 128, n0 = (bx & 3) * 128;
        gemm_core<true>(smb,
            qAh + (size_t)z * 1024 * 256, qAl + (size_t)z * 1024 * 256,
            qBh, qBl,
            nullptr, qChi + (size_t)z * 1024 * 512, qClo + (size_t)z * 1024 * 512,
            nullptr, 512, 256, m0, n0);
    } else {
        int bk = bx - 32;
        int m0 = (bk >> 3) * 128, n0 = (bk & 7) * 128;
        gemm_core<true>(smb,
            kAh + (size_t)z * 256 * 256, kAl + (size_t)z * 256 * 256,
            kBh, kBl,
            nullptr, kChi + (size_t)z * 256 * 1024, kClo + (size_t)z * 256 * 1024,
            nullptr, 1024, 256, m0, n0);
    }
}

// ---- out projection GEMM.  grid (8, 2, 16) ----
__global__ void __launch_bounds__(256, 2)
gemm_out(const __nv_bfloat16* __restrict__ Ah, const __nv_bfloat16* __restrict__ Al,
         const __nv_bfloat16* __restrict__ Bh, const __nv_bfloat16* __restrict__ Bl,
         float* __restrict__ Cf, const float* __restrict__ bias) {
    extern __shared__ __nv_bfloat16 gsm[];
    const uint32_t smb = smem_u32(gsm);
    const int z = blockIdx.z;
    int m0 = blockIdx.y * 128, n0 = blockIdx.x * 128;
    gemm_core<false>(smb,
        Ah, Al,
        Bh + (size_t)z * 1024 * 512, Bl + (size_t)z * 1024 * 512,
        Cf + (size_t)z * 256 * 1024, nullptr, nullptr,
        bias, 1024, 512, m0, n0);
}

// ==================== attention: 16 warps, online softmax over 64-kv chunks ====================
// grid (8 heads, 16 z), 512 threads. Warp w handles tiles {i*16+w}, i=0..3 (16 rows each).
#define ATT_S 72
#define AKH 0
#define AKL (AKH + 256 * ATT_S)
#define AVH (AKH + 2 * 256 * ATT_S)
#define AVL (AKH + 3 * 256 * ATT_S)
#define AQW (4 * 256 * ATT_S)
#define QSLOT (2 * 16 * ATT_S)    // per warp: hi then lo, single-buffered
#define ATT_SMEM ((4 * 256 + 16 * 2 * 16) * ATT_S * 2)   // 221184 B

__device__ __forceinline__ void att_stage_qw(uint32_t smb, int wid,
                                             const __nv_bfloat16* qhi,
                                             const __nv_bfloat16* qlo,
                                             size_t qb, int lane) {
    uint32_t base = smb + (uint32_t)(AQW + wid * QSLOT) * 2;
#pragma unroll
    for (int j = 0; j < 4; j++) {
        int idx = j * 32 + lane;            // 0..127
        int row = idx >> 3, ch = (idx & 7) * 8;
        uint32_t so = (uint32_t)(row * ATT_S + ch) * 2;
        cpa16(base + so,                  &qhi[qb + (size_t)row * 512 + ch]);
        cpa16(base + 16 * ATT_S * 2 + so, &qlo[qb + (size_t)row * 512 + ch]);
    }
}

__global__ void __launch_bounds__(512, 1)
attn_mma(const __nv_bfloat16* __restrict__ qhi, const __nv_bfloat16* __restrict__ qlo,
         const __nv_bfloat16* __restrict__ kvhi, const __nv_bfloat16* __restrict__ kvlo,
         __nv_bfloat16* __restrict__ aohi, __nv_bfloat16* __restrict__ aolo) {
    extern __shared__ __nv_bfloat16 sm[];
    const int tid = threadIdx.x, lane = tid & 31, wid = tid >> 5;
    const int h = blockIdx.x, z = blockIdx.y;
    const int zk = ((z >> 3) ^ 1) * 8 + (z & 7);
    const uint32_t smb = smem_u32(sm);

    // ---- stage K/V (block-wide) + each warp's first Q tile ----
    {
        size_t kb = (size_t)zk * 256 * 1024 + h * 64;
        size_t vb = kb + 512;
        for (int i = tid; i < 2048; i += 512) {
            int row = i >> 3, ch = (i & 7) * 8;
            uint32_t so = (uint32_t)(row * ATT_S + ch) * 2;
            cpa16(smb + AKH * 2 + so, &kvhi[kb + (size_t)row * 1024 + ch]);
            cpa16(smb + AKL * 2 + so, &kvlo[kb + (size_t)row * 1024 + ch]);
            cpa16(smb + AVH * 2 + so, &kvhi[vb + (size_t)row * 1024 + ch]);
            cpa16(smb + AVL * 2 + so, &kvlo[vb + (size_t)row * 1024 + ch]);
        }
        att_stage_qw(smb, wid, qhi, qlo,
                     ((size_t)z * 1024 + wid * 16) * 512 + h * 64, lane);
        CP_COMMIT();
        CP_WAIT0();
        __syncthreads();
    }

    const int a_row = lane & 15;
    const int a_cx = (lane >> 4) << 3;
    const int b_rx = (lane & 7) + ((lane >> 4) << 3);
    const int b_cx = ((lane >> 3) & 1) << 3;
    const int v_rx = (lane & 7) + (((lane >> 3) & 1) << 3);
    const int v_cx = (lane >> 4) << 3;
    const uint32_t qbase = smb + (uint32_t)(AQW + wid * QSLOT) * 2;

    for (int i = 0; i < 4; i++) {
        const int trow = (i * 16 + wid) * 16;     // this warp's 16 q-rows

        float o[8][4];
#pragma unroll
        for (int j = 0; j < 8; j++)
#pragma unroll
            for (int k = 0; k < 4; k++) o[j][k] = 0.f;
        float m0 = -1e30f, m1 = -1e30f, s0 = 0.f, s1 = 0.f;

#pragma unroll
        for (int ck = 0; ck < 4; ck++) {          // 64-kv chunks
            // ---- S chunk ----
            float c[8][4];
#pragma unroll
            for (int t = 0; t < 8; t++)
#pragma unroll
                for (int k = 0; k < 4; k++) c[t][k] = 0.f;

#pragma unroll
            for (int kt = 0; kt < 4; kt++) {
                uint32_t aH[4], aL[4];
                uint32_t aoff = (uint32_t)(a_row * ATT_S + kt * 16 + a_cx) * 2;
                ldm_x4(aH, qbase + aoff);
                ldm_x4(aL, qbase + 16 * ATT_S * 2 + aoff);
#pragma unroll
                for (int jp = 0; jp < 2; jp++) {
                    int jt = jp * 2;
                    uint32_t bo0 = (uint32_t)((ck * 64 + jt * 16 + b_rx) * ATT_S + kt * 16 + b_cx) * 2;
                    uint32_t bo1 = (uint32_t)((ck * 64 + (jt + 1) * 16 + b_rx) * ATT_S + kt * 16 + b_cx) * 2;
                    uint32_t bH0[4], bL0[4], bH1[4], bL1[4];
                    ldm_x4(bH0, smb + AKH * 2 + bo0);
                    ldm_x4(bL0, smb + AKL * 2 + bo0);
                    ldm_x4(bH1, smb + AKH * 2 + bo1);
                    ldm_x4(bL1, smb + AKL * 2 + bo1);
                    float *c0 = c[jt * 2], *c1 = c[jt * 2 + 1];
                    float *c2 = c[jt * 2 + 2], *c3 = c[jt * 2 + 3];
                    mma16816(c0, aH, &bH0[0]); mma16816(c1, aH, &bH0[2]);
                    mma16816(c2, aH, &bH1[0]); mma16816(c3, aH, &bH1[2]);
                    mma16816(c0, aH, &bL0[0]); mma16816(c1, aH, &bL0[2]);
                    mma16816(c2, aH, &bL1[0]); mma16816(c3, aH, &bL1[2]);
                    mma16816(c0, aL, &bH0[0]); mma16816(c1, aL, &bH0[2]);
                    mma16816(c2, aL, &bH1[0]); mma16816(c3, aL, &bH1[2]);
                }
            }

            // stage next tile's Q right after the LAST use of this tile's Q
            if (ck == 3 && i < 3) {
                att_stage_qw(smb, wid, qhi, qlo,
                             ((size_t)z * 1024 + ((i + 1) * 16 + wid) * 16) * 512 + h * 64, lane);
                CP_COMMIT();
            }

            // ---- online softmax update ----
            {
                float cm0 = -1e30f, cm1 = -1e30f;
#pragma unroll
                for (int t = 0; t < 8; t++) {
                    cm0 = fmaxf(cm0, fmaxf(c[t][0], c[t][1]));
                    cm1 = fmaxf(cm1, fmaxf(c[t][2], c[t][3]));
                }
                cm0 = fmaxf(cm0, __shfl_xor_sync(0xffffffffu, cm0, 1));
                cm0 = fmaxf(cm0, __shfl_xor_sync(0xffffffffu, cm0, 2));
                cm1 = fmaxf(cm1, __shfl_xor_sync(0xffffffffu, cm1, 1));
                cm1 = fmaxf(cm1, __shfl_xor_sync(0xffffffffu, cm1, 2));
                float mn0 = fmaxf(m0, cm0), mn1 = fmaxf(m1, cm1);
                float sc0 = __expf(m0 - mn0), sc1 = __expf(m1 - mn1);
                s0 *= sc0; s1 *= sc1;
#pragma unroll
                for (int j = 0; j < 8; j++) {
                    o[j][0] *= sc0; o[j][1] *= sc0;
                    o[j][2] *= sc1; o[j][3] *= sc1;
                }
#pragma unroll
                for (int t = 0; t < 8; t++) {
                    c[t][0] = __expf(c[t][0] - mn0); s0 += c[t][0];
                    c[t][1] = __expf(c[t][1] - mn0); s0 += c[t][1];
                    c[t][2] = __expf(c[t][2] - mn1); s1 += c[t][2];
                    c[t][3] = __expf(c[t][3] - mn1); s1 += c[t][3];
                }
                m0 = mn0; m1 = mn1;
            }

            // ---- PV chunk ----
#pragma unroll
            for (int ktl = 0; ktl < 4; ktl++) {
                uint32_t aH[4], aL[4];
                split2(c[2 * ktl][0], c[2 * ktl][1], aH[0], aL[0]);
                split2(c[2 * ktl][2], c[2 * ktl][3], aH[1], aL[1]);
                split2(c[2 * ktl + 1][0], c[2 * ktl + 1][1], aH[2], aL[2]);
                split2(c[2 * ktl + 1][2], c[2 * ktl + 1][3], aH[3], aL[3]);
#pragma unroll
                for (int db = 0; db < 4; db += 2) {
                    uint32_t bo0 = (uint32_t)((ck * 64 + ktl * 16 + v_rx) * ATT_S + db * 16 + v_cx) * 2;
                    uint32_t bo1 = (uint32_t)((ck * 64 + ktl * 16 + v_rx) * ATT_S + (db + 1) * 16 + v_cx) * 2;
                    uint32_t bH0[4], bL0[4], bH1[4], bL1[4];
                    ldm_x4_t(bH0, smb + AVH * 2 + bo0);
                    ldm_x4_t(bL0, smb + AVL * 2 + bo0);
                    ldm_x4_t(bH1, smb + AVH * 2 + bo1);
                    ldm_x4_t(bL1, smb + AVL * 2 + bo1);
                    float *o0 = o[db * 2], *o1 = o[db * 2 + 1];
                    float *o2 = o[db * 2 + 2], *o3 = o[db * 2 + 3];
                    mma16816(o0, aH, &bH0[0]); mma16816(o1, aH, &bH0[2]);
                    mma16816(o2, aH, &bH1[0]); mma16816(o3, aH, &bH1[2]);
                    mma16816(o0, aH, &bL0[0]); mma16816(o1, aH, &bL0[2]);
                    mma16816(o2, aH, &bL1[0]); mma16816(o3, aH, &bL1[2]);
                    mma16816(o0, aL, &bH0[0]); mma16816(o1, aL, &bH0[2]);
                    mma16816(o2, aL, &bH1[0]); mma16816(o3, aL, &bH1[2]);
                }
            }
        }

        // ---- final row-sum reduce + normalize + store ----
        s0 += __shfl_xor_sync(0xffffffffu, s0, 1);
        s0 += __shfl_xor_sync(0xffffffffu, s0, 2);
        s1 += __shfl_xor_sync(0xffffffffu, s1, 1);
        s1 += __shfl_xor_sync(0xffffffffu, s1, 2);
        float i0 = 1.f / s0, i1 = 1.f / s1;
        {
            int row0 = trow + (lane >> 2);
            int row1 = row0 + 8;
            size_t b0 = ((size_t)z * 1024 + row0) * 512 + h * 64 + (lane & 3) * 2;
            size_t b1 = ((size_t)z * 1024 + row1) * 512 + h * 64 + (lane & 3) * 2;
#pragma unroll
            for (int nt = 0; nt < 8; nt++) {
                uint32_t h0, l0, h1, l1;
                split2(o[nt][0] * i0, o[nt][1] * i0, h0, l0);
                split2(o[nt][2] * i1, o[nt][3] * i1, h1, l1);
                *(uint32_t*)&aohi[b0 + nt * 8] = h0;
                *(uint32_t*)&aolo[b0 + nt * 8] = l0;
                *(uint32_t*)&aohi[b1 + nt * 8] = h1;
                *(uint32_t*)&aolo[b1 + nt * 8] = l1;
            }
        }
        if (i < 3) CP_WAIT0();   // per-warp: next Q tile landed
    }
}

// ==================== launch ====================
extern "C" void kernel_launch(void* const* d_in, const int* in_sizes, int n_in,
                              void* d_out, int out_size) {
    const float* x        = (const float*)d_in[0];
    const float* y        = (const float*)d_in[1];
    const float* q_dw_w   = (const float*)d_in[2];
    const float* q_bn_g   = (const float*)d_in[3];
    const float* q_bn_b   = (const float*)d_in[4];
    const float* q_bn_m   = (const float*)d_in[5];
    const float* q_bn_v   = (const float*)d_in[6];
    const float* q_pw_w   = (const float*)d_in[7];
    const float* kv_dw_w  = (const float*)d_in[8];
    const float* kv_bn_g  = (const float*)d_in[9];
    const float* kv_bn_b  = (const float*)d_in[10];
    const float* kv_bn_m  = (const float*)d_in[11];
    const float* kv_bn_v  = (const float*)d_in[12];
    const float* kv_pw_w  = (const float*)d_in[13];
    const float* out_w    = (const float*)d_in[14];
    const float* out_b    = (const float*)d_in[15];
    float* out = (float*)d_out;

    __nv_bfloat16 *p_hqT_hi, *p_hqT_lo, *p_hkvT_hi, *p_hkvT_lo;
    __nv_bfloat16 *p_wq_hi, *p_wq_lo, *p_wkv_hi, *p_wkv_lo, *p_wo_hi, *p_wo_lo;
    __nv_bfloat16 *p_qs_hi, *p_qs_lo, *p_kvs_hi, *p_kvs_lo, *p_ao_hi, *p_ao_lo;
    cudaGetSymbolAddress((void**)&p_hqT_hi,  g_hqT_hi);
    cudaGetSymbolAddress((void**)&p_hqT_lo,  g_hqT_lo);
    cudaGetSymbolAddress((void**)&p_hkvT_hi, g_hkvT_hi);
    cudaGetSymbolAddress((void**)&p_hkvT_lo, g_hkvT_lo);
    cudaGetSymbolAddress((void**)&p_wq_hi,  g_wq_hi);
    cudaGetSymbolAddress((void**)&p_wq_lo,  g_wq_lo);
    cudaGetSymbolAddress((void**)&p_wkv_hi, g_wkv_hi);
    cudaGetSymbolAddress((void**)&p_wkv_lo, g_wkv_lo);
    cudaGetSymbolAddress((void**)&p_wo_hi,  g_wo_hi);
    cudaGetSymbolAddress((void**)&p_wo_lo,  g_wo_lo);
    cudaGetSymbolAddress((void**)&p_qs_hi,  g_qs_hi);
    cudaGetSymbolAddress((void**)&p_qs_lo,  g_qs_lo);
    cudaGetSymbolAddress((void**)&p_kvs_hi, g_kvs_hi);
    cudaGetSymbolAddress((void**)&p_kvs_lo, g_kvs_lo);
    cudaGetSymbolAddress((void**)&p_ao_hi,  g_ao_hi);
    cudaGetSymbolAddress((void**)&p_ao_lo,  g_ao_lo);

    cudaFuncSetAttribute(attn_mma,
                         cudaFuncAttributeMaxDynamicSharedMemorySize, ATT_SMEM);
    cudaFuncSetAttribute(gemm_dual,
                         cudaFuncAttributeMaxDynamicSharedMemorySize, GEMM_SMEM);
    cudaFuncSetAttribute(gemm_out,
                         cudaFuncAttributeMaxDynamicSharedMemorySize, GEMM_SMEM);

    // 1) merged dw conv + BN + transpose + split, plus weight splits (z==32)
    {
        dim3 blk(32, 8);
        dim3 grid(32, 8, 33);
        dw_bn_split2<<<grid, blk>>>(x, y,
                                    q_dw_w, q_bn_g, q_bn_b, q_bn_m, q_bn_v,
                                    kv_dw_w, kv_bn_g, kv_bn_b, kv_bn_m, kv_bn_v,
                                    p_hqT_hi, p_hqT_lo, p_hkvT_hi, p_hkvT_lo,
                                    q_pw_w, kv_pw_w, out_w,
                                    p_wq_hi, p_wq_lo, p_wkv_hi, p_wkv_lo,
                                    p_wo_hi, p_wo_lo);
    }
    // 2) merged q + kv pointwise GEMMs
    {
        dim3 grid(48, 16);
        gemm_dual<<<grid, 256, GEMM_SMEM>>>(p_hqT_hi, p_hqT_lo, p_wq_hi, p_wq_lo,
                                            p_qs_hi, p_qs_lo,
                                            p_hkvT_hi, p_hkvT_lo, p_wkv_hi, p_wkv_lo,
                                            p_kvs_hi, p_kvs_lo);
    }
    // 3) attention (512 threads, online softmax)
    {
        dim3 grid(8, 16);
        attn_mma<<<grid, 512, ATT_SMEM>>>(p_qs_hi, p_qs_lo, p_kvs_hi, p_kvs_lo,
                                          p_ao_hi, p_ao_lo);
    }
    // 4) out projection
    {
        dim3 grid(8, 2, 16);
        gemm_out<<<grid, 256, GEMM_SMEM>>>(p_wo_hi, p_wo_lo, p_ao_hi, p_ao_lo,
                                           out, out_b);
    }
}

// round 11
// speedup vs baseline: 2.7123x; 1.0463x over previous
#include <cuda_runtime.h>
#include <cuda_bf16.h>
#include <math.h>
#include <cstdint>

#define BN_EPS 1e-5f

// ==================== PTX helpers (baseline, sm_103-safe) ====================
__device__ __forceinline__ uint32_t smem_u32(const void* p) {
    uint32_t a;
    asm("{ .reg .u64 t; cvta.to.shared.u64 t, %1; cvt.u32.u64 %0, t; }" : "=r"(a) : "l"(p));
    return a;
}
__device__ __forceinline__ void ldm_x4(uint32_t* r, uint32_t addr) {
    asm volatile("ldmatrix.sync.aligned.m8n8.x4.shared.b16 {%0,%1,%2,%3}, [%4];"
                 : "=r"(r[0]), "=r"(r[1]), "=r"(r[2]), "=r"(r[3]) : "r"(addr));
}
__device__ __forceinline__ void ldm_x4_t(uint32_t* r, uint32_t addr) {
    asm volatile("ldmatrix.sync.aligned.m8n8.x4.trans.shared.b16 {%0,%1,%2,%3}, [%4];"
                 : "=r"(r[0]), "=r"(r[1]), "=r"(r[2]), "=r"(r[3]) : "r"(addr));
}
__device__ __forceinline__ void mma16816(float* d, const uint32_t* a, const uint32_t* b) {
    asm volatile("mma.sync.aligned.m16n8k16.row.col.f32.bf16.bf16.f32 "
        "{%0,%1,%2,%3}, {%4,%5,%6,%7}, {%8,%9}, {%0,%1,%2,%3};"
        : "+f"(d[0]), "+f"(d[1]), "+f"(d[2]), "+f"(d[3])
        : "r"(a[0]), "r"(a[1]), "r"(a[2]), "r"(a[3]), "r"(b[0]), "r"(b[1]));
}
__device__ __forceinline__ void split2(float x, float y, uint32_t &hi, uint32_t &lo) {
    asm("cvt.rn.bf16x2.f32 %0, %1, %2;" : "=r"(hi) : "f"(y), "f"(x));
    float xh = __uint_as_float(hi << 16);
    float yh = __uint_as_float(hi & 0xffff0000u);
    asm("cvt.rn.bf16x2.f32 %0, %1, %2;" : "=r"(lo) : "f"(y - yh), "f"(x - xh));
}
__device__ __forceinline__ void cpa16(uint32_t saddr, const void* g) {
    asm volatile("cp.async.cg.shared.global [%0], [%1], 16;" :: "r"(saddr), "l"(g));
}
#define CP_COMMIT() asm volatile("cp.async.commit_group;" ::: "memory")
#define CP_WAIT1()  asm volatile("cp.async.wait_group 1;" ::: "memory")
#define CP_WAIT0()  asm volatile("cp.async.wait_group 0;" ::: "memory")

// ==================== scratch ====================
__device__ __nv_bfloat16 g_hqT_hi [16u * 1024 * 256];
__device__ __nv_bfloat16 g_hqT_lo [16u * 1024 * 256];
__device__ __nv_bfloat16 g_hkvT_hi[16u * 256 * 256];
__device__ __nv_bfloat16 g_hkvT_lo[16u * 256 * 256];
__device__ __nv_bfloat16 g_wq_hi [512 * 256],  g_wq_lo [512 * 256];
__device__ __nv_bfloat16 g_wkv_hi[1024 * 256], g_wkv_lo[1024 * 256];
__device__ __nv_bfloat16 g_wo_hi [256 * 512],  g_wo_lo [256 * 512];
__device__ __nv_bfloat16 g_qs_hi [16u * 1024 * 512], g_qs_lo [16u * 1024 * 512];
__device__ __nv_bfloat16 g_kvs_hi[16u * 256 * 1024], g_kvs_lo[16u * 256 * 1024];
__device__ __nv_bfloat16 g_ao_hi [16u * 1024 * 512], g_ao_lo [16u * 1024 * 512];

// ==================== merged dw conv + BN + transpose + split  (+ weight splits) ====================
__global__ void dw_bn_split2(const float* __restrict__ x, const float* __restrict__ y,
                             const float* __restrict__ qw, const float* __restrict__ qg,
                             const float* __restrict__ qb, const float* __restrict__ qm,
                             const float* __restrict__ qv,
                             const float* __restrict__ kw, const float* __restrict__ kg,
                             const float* __restrict__ kb, const float* __restrict__ km,
                             const float* __restrict__ kvv,
                             __nv_bfloat16* __restrict__ qhi, __nv_bfloat16* __restrict__ qlo,
                             __nv_bfloat16* __restrict__ khi, __nv_bfloat16* __restrict__ klo,
                             const float* __restrict__ qpw, const float* __restrict__ kvpw,
                             const float* __restrict__ ow,
                             __nv_bfloat16* __restrict__ wqhi, __nv_bfloat16* __restrict__ wqlo,
                             __nv_bfloat16* __restrict__ wkvhi, __nv_bfloat16* __restrict__ wkvlo,
                             __nv_bfloat16* __restrict__ wohi, __nv_bfloat16* __restrict__ wolo) {
    const int zz = blockIdx.z;
    const int tidf = threadIdx.y * 32 + threadIdx.x;
    if (zz == 32) {
        int bid = blockIdx.x * 8 + blockIdx.y;
        int i = (bid * 256 + tidf) * 8;
        const float* in; __nv_bfloat16 *hi, *lo; int j; float sc = 1.f;
        if (i < 131072)      { in = qpw;  hi = wqhi;  lo = wqlo;  j = i;          sc = 0.125f; }
        else if (i < 393216) { in = kvpw; hi = wkvhi; lo = wkvlo; j = i - 131072; }
        else                 { in = ow;   hi = wohi;  lo = wolo;  j = i - 393216; }
        float4 v0 = *(const float4*)&in[j];
        float4 v1 = *(const float4*)&in[j + 4];
        float f[8] = {v0.x, v0.y, v0.z, v0.w, v1.x, v1.y, v1.z, v1.w};
        __nv_bfloat16 hb[8], lb[8];
#pragma unroll
        for (int k = 0; k < 8; k++) {
            float v = f[k] * sc;
            hb[k] = __float2bfloat16(v);
            lb[k] = __float2bfloat16(v - __bfloat162float(hb[k]));
        }
        *(uint4*)&hi[j] = *(uint4*)hb;
        *(uint4*)&lo[j] = *(uint4*)lb;
        return;
    }
    const bool isQ = (zz < 16);
    if (!isQ && blockIdx.x >= 8) return;
    __shared__ float t[32][33];
    const int z = isQ ? zz : zz - 16;
    const int b = z & 7;
    const int HO = isQ ? 32 : 16;
    const int stride = isQ ? 1 : 2;
    const float* in = (z >= 8) ? y : x;
    const float* w     = isQ ? qw : kw;
    const float* gamma = isQ ? qg : kg;
    const float* beta  = isQ ? qb : kb;
    const float* mean  = isQ ? qm : km;
    const float* var   = isQ ? qv : kvv;
    __nv_bfloat16* hi = isQ ? qhi : khi;
    __nv_bfloat16* lo = isQ ? qlo : klo;

    const int HW = HO * HO;
    const int hw0 = blockIdx.x * 32, c0 = blockIdx.y * 32;
    const int tx = threadIdx.x, ty = threadIdx.y;
    const int hw = hw0 + tx;
    const int oh = hw / HO, ow2 = hw % HO;
    const int ih0 = oh * stride - 1, iw0 = ow2 * stride - 1;
#pragma unroll
    for (int r = 0; r < 4; r++) {
        int c = c0 + ty + r * 8;
        const float* ip = in + (size_t)(b * 256 + c) * 1024;
        const float* wp = w + c * 9;
        float acc = 0.f;
#pragma unroll
        for (int kh = 0; kh < 3; kh++) {
            int ih = ih0 + kh;
            if (ih < 0 || ih > 31) continue;
#pragma unroll
            for (int kw2 = 0; kw2 < 3; kw2++) {
                int iw = iw0 + kw2;
                if (iw < 0 || iw > 31) continue;
                acc += wp[kh * 3 + kw2] * ip[ih * 32 + iw];
            }
        }
        float sc = gamma[c] * rsqrtf(var[c] + BN_EPS);
        float sh = beta[c] - mean[c] * sc;
        t[ty + r * 8][tx] = acc * sc + sh;
    }
    __syncthreads();
    size_t ob = (size_t)z * HW * 256;
#pragma unroll
    for (int r = 0; r < 4; r++) {
        float v = t[tx][ty + r * 8];
        __nv_bfloat16 hh = __float2bfloat16(v);
        size_t o = ob + (size_t)(hw0 + ty + r * 8) * 256 + c0 + tx;
        hi[o] = hh;
        lo[o] = __float2bfloat16(v - __bfloat162float(hh));
    }
}

// ==================== 512-thread, 256x128-tile, 3-stage single-barrier GEMM ====================
#define SMS 40
#define A_HV (256 * SMS)                 // halves per A term buffer
#define B_HV (128 * SMS)
#define STG_B ((2 * A_HV + 2 * B_HV) * 2)   // 61440 bytes per stage
#define GEMM_SMEM3 (3 * STG_B)              // 184320

__device__ __forceinline__ void gemm_issue512(
    uint32_t smb, int stage,
    const __nv_bfloat16* Ah, const __nv_bfloat16* Al,
    const __nv_bfloat16* Bh, const __nv_bfloat16* Bl,
    int m0, int n0, int K, int k0, int rid, int cid) {
    uint32_t sb = smb + (uint32_t)stage * STG_B;
    uint32_t sA0 = (uint32_t)(rid * SMS + cid) * 2;
    uint32_t sA1 = (uint32_t)((rid + 128) * SMS + cid) * 2;
    cpa16(sb + sA0,              &Ah[(size_t)(m0 + rid) * K + k0 + cid]);
    cpa16(sb + sA1,              &Ah[(size_t)(m0 + rid + 128) * K + k0 + cid]);
    cpa16(sb + A_HV * 2 + sA0,   &Al[(size_t)(m0 + rid) * K + k0 + cid]);
    cpa16(sb + A_HV * 2 + sA1,   &Al[(size_t)(m0 + rid + 128) * K + k0 + cid]);
    cpa16(sb + 4 * A_HV + sA0,   &Bh[(size_t)(n0 + rid) * K + k0 + cid]);          // Bh at 2*A_HV halves = 4*A_HV bytes
    cpa16(sb + 4 * A_HV + B_HV * 2 + sA0, &Bl[(size_t)(n0 + rid) * K + k0 + cid]);
}

template <bool SPLIT>
__device__ __forceinline__ void gemm_core512(
    uint32_t smb,
    const __nv_bfloat16* Ah, const __nv_bfloat16* Al,
    const __nv_bfloat16* Bh, const __nv_bfloat16* Bl,
    float* Cf, __nv_bfloat16* Chi, __nv_bfloat16* Clo,
    const float* bias, int N, int K, int m0, int n0) {
    const int tid = threadIdx.x, lane = tid & 31, wid = tid >> 5;
    const int warp_m = wid & 7, warp_n = wid >> 3;   // 8 x 2 warps, warp tile 32x64

    float acc[2][8][4];
#pragma unroll
    for (int i = 0; i < 2; i++)
#pragma unroll
        for (int j = 0; j < 8; j++)
#pragma unroll
            for (int k = 0; k < 4; k++) acc[i][j][k] = 0.f;

    const int rid = tid >> 2;            // 0..127
    const int cid = (tid & 3) * 8;
    const int a_row = warp_m * 32 + (lane & 15);
    const int a_colx = (lane >> 4) << 3;
    const int b_row = warp_n * 64 + (lane & 7) + ((lane >> 4) << 3);
    const int b_colx = ((lane >> 3) & 1) << 3;

    const int nk = K / 32;
    gemm_issue512(smb, 0, Ah, Al, Bh, Bl, m0, n0, K, 0, rid, cid);
    CP_COMMIT();
    gemm_issue512(smb, 1, Ah, Al, Bh, Bl, m0, n0, K, 32, rid, cid);
    CP_COMMIT();

    int stage = 0;
    for (int i = 0; i < nk; i++) {
        CP_WAIT1();
        __syncthreads();   // single barrier: orders compute(i-1) before issue(i+2) AND data visibility

        const uint32_t base = smb + (uint32_t)stage * STG_B;
#pragma unroll
        for (int ks = 0; ks < 2; ks++) {
            const int kc = ks * 16;
            uint32_t ah[2][4], al[2][4];
#pragma unroll
            for (int mt = 0; mt < 2; mt++) {
                uint32_t off = (uint32_t)((a_row + mt * 16) * SMS + kc + a_colx) * 2;
                ldm_x4(ah[mt], base + off);
                ldm_x4(al[mt], base + A_HV * 2 + off);
            }
#pragma unroll
            for (int ng = 0; ng < 4; ng++) {
                uint32_t bh[4], bl[4];
                uint32_t off = (uint32_t)((b_row + ng * 16) * SMS + kc + b_colx) * 2;
                ldm_x4(bh, base + 4 * A_HV + off);
                ldm_x4(bl, base + 4 * A_HV + B_HV * 2 + off);
#pragma unroll
                for (int mt = 0; mt < 2; mt++)
#pragma unroll
                    for (int nt = 0; nt < 2; nt++)
                        mma16816(acc[mt][ng * 2 + nt], ah[mt], &bh[nt * 2]);
#pragma unroll
                for (int mt = 0; mt < 2; mt++)
#pragma unroll
                    for (int nt = 0; nt < 2; nt++)
                        mma16816(acc[mt][ng * 2 + nt], ah[mt], &bl[nt * 2]);
#pragma unroll
                for (int mt = 0; mt < 2; mt++)
#pragma unroll
                    for (int nt = 0; nt < 2; nt++)
                        mma16816(acc[mt][ng * 2 + nt], al[mt], &bh[nt * 2]);
            }
        }

        if (i + 2 < nk)
            gemm_issue512(smb, (stage + 2 >= 3) ? stage - 1 : stage + 2,
                          Ah, Al, Bh, Bl, m0, n0, K, (i + 2) * 32, rid, cid);
        CP_COMMIT();
        stage = (stage + 1 == 3) ? 0 : stage + 1;
    }

#pragma unroll
    for (int mt = 0; mt < 2; mt++) {
        int mrow0 = m0 + warp_m * 32 + mt * 16 + (lane >> 2);
        int mrow1 = mrow0 + 8;
        float bv0 = (!SPLIT && bias) ? bias[mrow0] : 0.f;
        float bv1 = (!SPLIT && bias) ? bias[mrow1] : 0.f;
#pragma unroll
        for (int j = 0; j < 8; j++) {
            int n = n0 + warp_n * 64 + j * 8 + (lane & 3) * 2;
            float* c = acc[mt][j];
            if (SPLIT) {
                uint32_t h0, l0, h1, l1;
                split2(c[0], c[1], h0, l0);
                split2(c[2], c[3], h1, l1);
                size_t o0 = (size_t)mrow0 * N + n;
                size_t o1 = (size_t)mrow1 * N + n;
                *(uint32_t*)&Chi[o0] = h0; *(uint32_t*)&Clo[o0] = l0;
                *(uint32_t*)&Chi[o1] = h1; *(uint32_t*)&Clo[o1] = l1;
            } else {
                *(float2*)&Cf[(size_t)mrow0 * N + n] = make_float2(c[0] + bv0, c[1] + bv0);
                *(float2*)&Cf[(size_t)mrow1 * N + n] = make_float2(c[2] + bv1, c[3] + bv1);
            }
        }
    }
}

// ---- merged q + kv pointwise GEMMs.  grid (24, 16), 512 threads ----
__global__ void __launch_bounds__(512, 1)
gemm_dual(const __nv_bfloat16* __restrict__ qAh, const __nv_bfloat16* __restrict__ qAl,
          const __nv_bfloat16* __restrict__ qBh, const __nv_bfloat16* __restrict__ qBl,
          __nv_bfloat16* __restrict__ qChi, __nv_bfloat16* __restrict__ qClo,
          const __nv_bfloat16* __restrict__ kAh, const __nv_bfloat16* __restrict__ kAl,
          const __nv_bfloat16* __restrict__ kBh, const __nv_bfloat16* __restrict__ kBl,
          __nv_bfloat16* __restrict__ kChi, __nv_bfloat16* __restrict__ kClo) {
    extern __shared__ __nv_bfloat16 gsm[];
    const uint32_t smb = smem_u32(gsm);
    const int bx = blockIdx.x, z = blockIdx.y;
    if (bx < 16) {
        // q: M=1024 pos (4 tiles of 256), N=512 ch (4 tiles of 128), K=256
        int m0 = (bx >> 2) * 256, n0 = (bx & 3) * 128;
        gemm_core512<true>(smb,
            qAh + (size_t)z * 1024 * 256, qAl + (size_t)z * 1024 * 256,
            qBh, qBl,
            nullptr, qChi + (size_t)z * 1024 * 512, qClo + (size_t)z * 1024 * 512,
            nullptr, 512, 256, m0, n0);
    } else {
        // kv: M=256 pos (1 tile), N=1024 ch (8 tiles), K=256
        int n0 = (bx - 16) * 128;
        gemm_core512<true>(smb,
            kAh + (size_t)z * 256 * 256, kAl + (size_t)z * 256 * 256,
            kBh, kBl,
            nullptr, kChi + (size_t)z * 256 * 1024, kClo + (size_t)z * 256 * 1024,
            nullptr, 1024, 256, 0, n0);
    }
}

// ---- out projection GEMM.  grid (8, 16), 512 threads ----
__global__ void __launch_bounds__(512, 1)
gemm_out(const __nv_bfloat16* __restrict__ Ah, const __nv_bfloat16* __restrict__ Al,
         const __nv_bfloat16* __restrict__ Bh, const __nv_bfloat16* __restrict__ Bl,
         float* __restrict__ Cf, const float* __restrict__ bias) {
    extern __shared__ __nv_bfloat16 gsm[];
    const uint32_t smb = smem_u32(gsm);
    const int z = blockIdx.y;
    int n0 = blockIdx.x * 128;
    // M=256 ch (1 tile), N=1024 pos (8 tiles), K=512
    gemm_core512<false>(smb,
        Ah, Al,
        Bh + (size_t)z * 1024 * 512, Bl + (size_t)z * 1024 * 512,
        Cf + (size_t)z * 256 * 1024, nullptr, nullptr,
        bias, 1024, 512, 0, n0);
}

// ==================== attention: 16 warps, online softmax over 64-kv chunks ====================
#define ATT_S 72
#define AKH 0
#define AKL (AKH + 256 * ATT_S)
#define AVH (AKH + 2 * 256 * ATT_S)
#define AVL (AKH + 3 * 256 * ATT_S)
#define AQW (4 * 256 * ATT_S)
#define QSLOT (2 * 16 * ATT_S)
#define ATT_SMEM ((4 * 256 + 16 * 2 * 16) * ATT_S * 2)   // 221184 B

__device__ __forceinline__ void att_stage_qw(uint32_t smb, int wid,
                                             const __nv_bfloat16* qhi,
                                             const __nv_bfloat16* qlo,
                                             size_t qb, int lane) {
    uint32_t base = smb + (uint32_t)(AQW + wid * QSLOT) * 2;
#pragma unroll
    for (int j = 0; j < 4; j++) {
        int idx = j * 32 + lane;
        int row = idx >> 3, ch = (idx & 7) * 8;
        uint32_t so = (uint32_t)(row * ATT_S + ch) * 2;
        cpa16(base + so,                  &qhi[qb + (size_t)row * 512 + ch]);
        cpa16(base + 16 * ATT_S * 2 + so, &qlo[qb + (size_t)row * 512 + ch]);
    }
}

__global__ void __launch_bounds__(512, 1)
attn_mma(const __nv_bfloat16* __restrict__ qhi, const __nv_bfloat16* __restrict__ qlo,
         const __nv_bfloat16* __restrict__ kvhi, const __nv_bfloat16* __restrict__ kvlo,
         __nv_bfloat16* __restrict__ aohi, __nv_bfloat16* __restrict__ aolo) {
    extern __shared__ __nv_bfloat16 sm[];
    const int tid = threadIdx.x, lane = tid & 31, wid = tid >> 5;
    const int h = blockIdx.x, z = blockIdx.y;
    const int zk = ((z >> 3) ^ 1) * 8 + (z & 7);
    const uint32_t smb = smem_u32(sm);

    {
        size_t kb = (size_t)zk * 256 * 1024 + h * 64;
        size_t vb = kb + 512;
        for (int i = tid; i < 2048; i += 512) {
            int row = i >> 3, ch = (i & 7) * 8;
            uint32_t so = (uint32_t)(row * ATT_S + ch) * 2;
            cpa16(smb + AKH * 2 + so, &kvhi[kb + (size_t)row * 1024 + ch]);
            cpa16(smb + AKL * 2 + so, &kvlo[kb + (size_t)row * 1024 + ch]);
            cpa16(smb + AVH * 2 + so, &kvhi[vb + (size_t)row * 1024 + ch]);
            cpa16(smb + AVL * 2 + so, &kvlo[vb + (size_t)row * 1024 + ch]);
        }
        att_stage_qw(smb, wid, qhi, qlo,
                     ((size_t)z * 1024 + wid * 16) * 512 + h * 64, lane);
        CP_COMMIT();
        CP_WAIT0();
        __syncthreads();
    }

    const int a_row = lane & 15;
    const int a_cx = (lane >> 4) << 3;
    const int b_rx = (lane & 7) + ((lane >> 4) << 3);
    const int b_cx = ((lane >> 3) & 1) << 3;
    const int v_rx = (lane & 7) + (((lane >> 3) & 1) << 3);
    const int v_cx = (lane >> 4) << 3;
    const uint32_t qbase = smb + (uint32_t)(AQW + wid * QSLOT) * 2;

    for (int i = 0; i < 4; i++) {
        const int trow = (i * 16 + wid) * 16;

        float o[8][4];
#pragma unroll
        for (int j = 0; j < 8; j++)
#pragma unroll
            for (int k = 0; k < 4; k++) o[j][k] = 0.f;
        float m0 = -1e30f, m1 = -1e30f, s0 = 0.f, s1 = 0.f;

#pragma unroll
        for (int ck = 0; ck < 4; ck++) {
            float c[8][4];
#pragma unroll
            for (int t = 0; t < 8; t++)
#pragma unroll
                for (int k = 0; k < 4; k++) c[t][k] = 0.f;

#pragma unroll
            for (int kt = 0; kt < 4; kt++) {
                uint32_t aH[4], aL[4];
                uint32_t aoff = (uint32_t)(a_row * ATT_S + kt * 16 + a_cx) * 2;
                ldm_x4(aH, qbase + aoff);
                ldm_x4(aL, qbase + 16 * ATT_S * 2 + aoff);
#pragma unroll
                for (int jp = 0; jp < 2; jp++) {
                    int jt = jp * 2;
                    uint32_t bo0 = (uint32_t)((ck * 64 + jt * 16 + b_rx) * ATT_S + kt * 16 + b_cx) * 2;
                    uint32_t bo1 = (uint32_t)((ck * 64 + (jt + 1) * 16 + b_rx) * ATT_S + kt * 16 + b_cx) * 2;
                    uint32_t bH0[4], bL0[4], bH1[4], bL1[4];
                    ldm_x4(bH0, smb + AKH * 2 + bo0);
                    ldm_x4(bL0, smb + AKL * 2 + bo0);
                    ldm_x4(bH1, smb + AKH * 2 + bo1);
                    ldm_x4(bL1, smb + AKL * 2 + bo1);
                    float *c0 = c[jt * 2], *c1 = c[jt * 2 + 1];
                    float *c2 = c[jt * 2 + 2], *c3 = c[jt * 2 + 3];
                    mma16816(c0, aH, &bH0[0]); mma16816(c1, aH, &bH0[2]);
                    mma16816(c2, aH, &bH1[0]); mma16816(c3, aH, &bH1[2]);
                    mma16816(c0, aH, &bL0[0]); mma16816(c1, aH, &bL0[2]);
                    mma16816(c2, aH, &bL1[0]); mma16816(c3, aH, &bL1[2]);
                    mma16816(c0, aL, &bH0[0]); mma16816(c1, aL, &bH0[2]);
                    mma16816(c2, aL, &bH1[0]); mma16816(c3, aL, &bH1[2]);
                }
            }

            if (ck == 3 && i < 3) {
                att_stage_qw(smb, wid, qhi, qlo,
                             ((size_t)z * 1024 + ((i + 1) * 16 + wid) * 16) * 512 + h * 64, lane);
                CP_COMMIT();
            }

            {
                float cm0 = -1e30f, cm1 = -1e30f;
#pragma unroll
                for (int t = 0; t < 8; t++) {
                    cm0 = fmaxf(cm0, fmaxf(c[t][0], c[t][1]));
                    cm1 = fmaxf(cm1, fmaxf(c[t][2], c[t][3]));
                }
                cm0 = fmaxf(cm0, __shfl_xor_sync(0xffffffffu, cm0, 1));
                cm0 = fmaxf(cm0, __shfl_xor_sync(0xffffffffu, cm0, 2));
                cm1 = fmaxf(cm1, __shfl_xor_sync(0xffffffffu, cm1, 1));
                cm1 = fmaxf(cm1, __shfl_xor_sync(0xffffffffu, cm1, 2));
                float mn0 = fmaxf(m0, cm0), mn1 = fmaxf(m1, cm1);
                float sc0 = __expf(m0 - mn0), sc1 = __expf(m1 - mn1);
                s0 *= sc0; s1 *= sc1;
#pragma unroll
                for (int j = 0; j < 8; j++) {
                    o[j][0] *= sc0; o[j][1] *= sc0;
                    o[j][2] *= sc1; o[j][3] *= sc1;
                }
#pragma unroll
                for (int t = 0; t < 8; t++) {
                    c[t][0] = __expf(c[t][0] - mn0); s0 += c[t][0];
                    c[t][1] = __expf(c[t][1] - mn0); s0 += c[t][1];
                    c[t][2] = __expf(c[t][2] - mn1); s1 += c[t][2];
                    c[t][3] = __expf(c[t][3] - mn1); s1 += c[t][3];
                }
                m0 = mn0; m1 = mn1;
            }

#pragma unroll
            for (int ktl = 0; ktl < 4; ktl++) {
                uint32_t aH[4], aL[4];
                split2(c[2 * ktl][0], c[2 * ktl][1], aH[0], aL[0]);
                split2(c[2 * ktl][2], c[2 * ktl][3], aH[1], aL[1]);
                split2(c[2 * ktl + 1][0], c[2 * ktl + 1][1], aH[2], aL[2]);
                split2(c[2 * ktl + 1][2], c[2 * ktl + 1][3], aH[3], aL[3]);
#pragma unroll
                for (int db = 0; db < 4; db += 2) {
                    uint32_t bo0 = (uint32_t)((ck * 64 + ktl * 16 + v_rx) * ATT_S + db * 16 + v_cx) * 2;
                    uint32_t bo1 = (uint32_t)((ck * 64 + ktl * 16 + v_rx) * ATT_S + (db + 1) * 16 + v_cx) * 2;
                    uint32_t bH0[4], bL0[4], bH1[4], bL1[4];
                    ldm_x4_t(bH0, smb + AVH * 2 + bo0);
                    ldm_x4_t(bL0, smb + AVL * 2 + bo0);
                    ldm_x4_t(bH1, smb + AVH * 2 + bo1);
                    ldm_x4_t(bL1, smb + AVL * 2 + bo1);
                    float *o0 = o[db * 2], *o1 = o[db * 2 + 1];
                    float *o2 = o[db * 2 + 2], *o3 = o[db * 2 + 3];
                    mma16816(o0, aH, &bH0[0]); mma16816(o1, aH, &bH0[2]);
                    mma16816(o2, aH, &bH1[0]); mma16816(o3, aH, &bH1[2]);
                    mma16816(o0, aH, &bL0[0]); mma16816(o1, aH, &bL0[2]);
                    mma16816(o2, aH, &bL1[0]); mma16816(o3, aH, &bL1[2]);
                    mma16816(o0, aL, &bH0[0]); mma16816(o1, aL, &bH0[2]);
                    mma16816(o2, aL, &bH1[0]); mma16816(o3, aL, &bH1[2]);
                }
            }
        }

        s0 += __shfl_xor_sync(0xffffffffu, s0, 1);
        s0 += __shfl_xor_sync(0xffffffffu, s0, 2);
        s1 += __shfl_xor_sync(0xffffffffu, s1, 1);
        s1 += __shfl_xor_sync(0xffffffffu, s1, 2);
        float i0 = 1.f / s0, i1 = 1.f / s1;
        {
            int row0 = trow + (lane >> 2);
            int row1 = row0 + 8;
            size_t b0 = ((size_t)z * 1024 + row0) * 512 + h * 64 + (lane & 3) * 2;
            size_t b1 = ((size_t)z * 1024 + row1) * 512 + h * 64 + (lane & 3) * 2;
#pragma unroll
            for (int nt = 0; nt < 8; nt++) {
                uint32_t h0, l0, h1, l1;
                split2(o[nt][0] * i0, o[nt][1] * i0, h0, l0);
                split2(o[nt][2] * i1, o[nt][3] * i1, h1, l1);
                *(uint32_t*)&aohi[b0 + nt * 8] = h0;
                *(uint32_t*)&aolo[b0 + nt * 8] = l0;
                *(uint32_t*)&aohi[b1 + nt * 8] = h1;
                *(uint32_t*)&aolo[b1 + nt * 8] = l1;
            }
        }
        if (i < 3) CP_WAIT0();
    }
}

// ==================== launch ====================
extern "C" void kernel_launch(void* const* d_in, const int* in_sizes, int n_in,
                              void* d_out, int out_size) {
    const float* x        = (const float*)d_in[0];
    const float* y        = (const float*)d_in[1];
    const float* q_dw_w   = (const float*)d_in[2];
    const float* q_bn_g   = (const float*)d_in[3];
    const float* q_bn_b   = (const float*)d_in[4];
    const float* q_bn_m   = (const float*)d_in[5];
    const float* q_bn_v   = (const float*)d_in[6];
    const float* q_pw_w   = (const float*)d_in[7];
    const float* kv_dw_w  = (const float*)d_in[8];
    const float* kv_bn_g  = (const float*)d_in[9];
    const float* kv_bn_b  = (const float*)d_in[10];
    const float* kv_bn_m  = (const float*)d_in[11];
    const float* kv_bn_v  = (const float*)d_in[12];
    const float* kv_pw_w  = (const float*)d_in[13];
    const float* out_w    = (const float*)d_in[14];
    const float* out_b    = (const float*)d_in[15];
    float* out = (float*)d_out;

    __nv_bfloat16 *p_hqT_hi, *p_hqT_lo, *p_hkvT_hi, *p_hkvT_lo;
    __nv_bfloat16 *p_wq_hi, *p_wq_lo, *p_wkv_hi, *p_wkv_lo, *p_wo_hi, *p_wo_lo;
    __nv_bfloat16 *p_qs_hi, *p_qs_lo, *p_kvs_hi, *p_kvs_lo, *p_ao_hi, *p_ao_lo;
    cudaGetSymbolAddress((void**)&p_hqT_hi,  g_hqT_hi);
    cudaGetSymbolAddress((void**)&p_hqT_lo,  g_hqT_lo);
    cudaGetSymbolAddress((void**)&p_hkvT_hi, g_hkvT_hi);
    cudaGetSymbolAddress((void**)&p_hkvT_lo, g_hkvT_lo);
    cudaGetSymbolAddress((void**)&p_wq_hi,  g_wq_hi);
    cudaGetSymbolAddress((void**)&p_wq_lo,  g_wq_lo);
    cudaGetSymbolAddress((void**)&p_wkv_hi, g_wkv_hi);
    cudaGetSymbolAddress((void**)&p_wkv_lo, g_wkv_lo);
    cudaGetSymbolAddress((void**)&p_wo_hi,  g_wo_hi);
    cudaGetSymbolAddress((void**)&p_wo_lo,  g_wo_lo);
    cudaGetSymbolAddress((void**)&p_qs_hi,  g_qs_hi);
    cudaGetSymbolAddress((void**)&p_qs_lo,  g_qs_lo);
    cudaGetSymbolAddress((void**)&p_kvs_hi, g_kvs_hi);
    cudaGetSymbolAddress((void**)&p_kvs_lo, g_kvs_lo);
    cudaGetSymbolAddress((void**)&p_ao_hi,  g_ao_hi);
    cudaGetSymbolAddress((void**)&p_ao_lo,  g_ao_lo);

    cudaFuncSetAttribute(attn_mma,
                         cudaFuncAttributeMaxDynamicSharedMemorySize, ATT_SMEM);
    cudaFuncSetAttribute(gemm_dual,
                         cudaFuncAttributeMaxDynamicSharedMemorySize, GEMM_SMEM3);
    cudaFuncSetAttribute(gemm_out,
                         cudaFuncAttributeMaxDynamicSharedMemorySize, GEMM_SMEM3);

    // 1) merged dw conv + BN + transpose + split, plus weight splits (z==32)
    {
        dim3 blk(32, 8);
        dim3 grid(32, 8, 33);
        dw_bn_split2<<<grid, blk>>>(x, y,
                                    q_dw_w, q_bn_g, q_bn_b, q_bn_m, q_bn_v,
                                    kv_dw_w, kv_bn_g, kv_bn_b, kv_bn_m, kv_bn_v,
                                    p_hqT_hi, p_hqT_lo, p_hkvT_hi, p_hkvT_lo,
                                    q_pw_w, kv_pw_w, out_w,
                                    p_wq_hi, p_wq_lo, p_wkv_hi, p_wkv_lo,
                                    p_wo_hi, p_wo_lo);
    }
    // 2) merged q + kv pointwise GEMMs (512 threads, 3-stage, 1 barrier/iter)
    {
        dim3 grid(24, 16);
        gemm_dual<<<grid, 512, GEMM_SMEM3>>>(p_hqT_hi, p_hqT_lo, p_wq_hi, p_wq_lo,
                                             p_qs_hi, p_qs_lo,
                                             p_hkvT_hi, p_hkvT_lo, p_wkv_hi, p_wkv_lo,
                                             p_kvs_hi, p_kvs_lo);
    }
    // 3) attention (512 threads, online softmax)
    {
        dim3 grid(8, 16);
        attn_mma<<<grid, 512, ATT_SMEM>>>(p_qs_hi, p_qs_lo, p_kvs_hi, p_kvs_lo,
                                          p_ao_hi, p_ao_lo);
    }
    // 4) out projection (512 threads, 3-stage)
    {
        dim3 grid(8, 16);
        gemm_out<<<grid, 512, GEMM_SMEM3>>>(p_wo_hi, p_wo_lo, p_ao_hi, p_ao_lo,
                                            out, out_b);
    }
}

// round 12
// speedup vs baseline: 3.5338x; 1.3029x over previous
#include <cuda_runtime.h>
#include <cuda_fp16.h>
#include <math.h>
#include <cstdint>

#define BN_EPS 1e-5f

// ==================== PTX helpers (baseline, sm_103-safe) ====================
__device__ __forceinline__ uint32_t smem_u32(const void* p) {
    uint32_t a;
    asm("{ .reg .u64 t; cvta.to.shared.u64 t, %1; cvt.u32.u64 %0, t; }" : "=r"(a) : "l"(p));
    return a;
}
__device__ __forceinline__ void ldm_x4(uint32_t* r, uint32_t addr) {
    asm volatile("ldmatrix.sync.aligned.m8n8.x4.shared.b16 {%0,%1,%2,%3}, [%4];"
                 : "=r"(r[0]), "=r"(r[1]), "=r"(r[2]), "=r"(r[3]) : "r"(addr));
}
__device__ __forceinline__ void ldm_x4_t(uint32_t* r, uint32_t addr) {
    asm volatile("ldmatrix.sync.aligned.m8n8.x4.trans.shared.b16 {%0,%1,%2,%3}, [%4];"
                 : "=r"(r[0]), "=r"(r[1]), "=r"(r[2]), "=r"(r[3]) : "r"(addr));
}
// fp16 mma (sm_80 baseline)
__device__ __forceinline__ void mma16816(float* d, const uint32_t* a, const uint32_t* b) {
    asm volatile("mma.sync.aligned.m16n8k16.row.col.f32.f16.f16.f32 "
        "{%0,%1,%2,%3}, {%4,%5,%6,%7}, {%8,%9}, {%0,%1,%2,%3};"
        : "+f"(d[0]), "+f"(d[1]), "+f"(d[2]), "+f"(d[3])
        : "r"(a[0]), "r"(a[1]), "r"(a[2]), "r"(a[3]), "r"(b[0]), "r"(b[1]));
}
// pack (x,y) -> fp16x2 hi word + fp16x2 residual word
__device__ __forceinline__ void split2h(float x, float y, uint32_t &hi, uint32_t &lo) {
    __half2 h = __floats2half2_rn(x, y);
    hi = *(uint32_t*)&h;
    float2 hf = __half22float2(h);
    __half2 l = __floats2half2_rn(x - hf.x, y - hf.y);
    lo = *(uint32_t*)&l;
}
__device__ __forceinline__ uint32_t pack2h(float x, float y) {
    __half2 h = __floats2half2_rn(x, y);
    return *(uint32_t*)&h;
}
__device__ __forceinline__ void cpa16(uint32_t saddr, const void* g) {
    asm volatile("cp.async.cg.shared.global [%0], [%1], 16;" :: "r"(saddr), "l"(g));
}
#define CP_COMMIT() asm volatile("cp.async.commit_group;" ::: "memory")
#define CP_WAIT1()  asm volatile("cp.async.wait_group 1;" ::: "memory")
#define CP_WAIT0()  asm volatile("cp.async.wait_group 0;" ::: "memory")

// ==================== scratch ====================
__device__ __half g_hqT_hi [16u * 1024 * 256];   // activations: split (A operand)
__device__ __half g_hqT_lo [16u * 1024 * 256];
__device__ __half g_hkvT_hi[16u * 256 * 256];
__device__ __half g_hkvT_lo[16u * 256 * 256];
__device__ __half g_wq  [512 * 256];             // weights: single fp16 (B operand); wq pre-scaled 0.125
__device__ __half g_wkv [1024 * 256];
__device__ __half g_wo_hi[256 * 512], g_wo_lo[256 * 512];   // wo split (A of out-proj)
__device__ __half g_qs_hi [16u * 1024 * 512], g_qs_lo [16u * 1024 * 512]; // q: split (QK A)
__device__ __half g_kvs [16u * 256 * 1024];      // kv: single fp16 (K,V are B operands)
__device__ __half g_ao  [16u * 1024 * 512];      // attn out: single fp16 (B of out-proj)

// ==================== merged dw conv + BN + transpose + split (+ weight conversion) ====================
// grid (32, 8, 33) block (32,8): z<16 q-act, 16<=z<32 kv-act, z==32 weights
__global__ void dw_bn_split2(const float* __restrict__ x, const float* __restrict__ y,
                             const float* __restrict__ qw, const float* __restrict__ qg,
                             const float* __restrict__ qb, const float* __restrict__ qm,
                             const float* __restrict__ qv,
                             const float* __restrict__ kw, const float* __restrict__ kg,
                             const float* __restrict__ kb, const float* __restrict__ km,
                             const float* __restrict__ kvv,
                             __half* __restrict__ qhi, __half* __restrict__ qlo,
                             __half* __restrict__ khi, __half* __restrict__ klo,
                             const float* __restrict__ qpw, const float* __restrict__ kvpw,
                             const float* __restrict__ ow,
                             __half* __restrict__ wq1, __half* __restrict__ wkv1,
                             __half* __restrict__ wohi, __half* __restrict__ wolo) {
    const int zz = blockIdx.z;
    const int tidf = threadIdx.y * 32 + threadIdx.x;
    if (zz == 32) {
        int bid = blockIdx.x * 8 + blockIdx.y;
        int i = (bid * 256 + tidf) * 8;   // 0..524287 step 8
        if (i < 131072) {
            // wq single, pre-scaled by 0.125
            const float* in = qpw; int j = i;
            __half hb[8];
#pragma unroll
            for (int k = 0; k < 8; k++) hb[k] = __float2half(in[j + k] * 0.125f);
            *(uint4*)&wq1[j] = *(uint4*)hb;
        } else if (i < 393216) {
            const float* in = kvpw; int j = i - 131072;
            __half hb[8];
#pragma unroll
            for (int k = 0; k < 8; k++) hb[k] = __float2half(in[j + k]);
            *(uint4*)&wkv1[j] = *(uint4*)hb;
        } else {
            const float* in = ow; int j = i - 393216;
            __half hb[8], lb[8];
#pragma unroll
            for (int k = 0; k < 8; k++) {
                float v = in[j + k];
                hb[k] = __float2half(v);
                lb[k] = __float2half(v - __half2float(hb[k]));
            }
            *(uint4*)&wohi[j] = *(uint4*)hb;
            *(uint4*)&wolo[j] = *(uint4*)lb;
        }
        return;
    }
    const bool isQ = (zz < 16);
    if (!isQ && blockIdx.x >= 8) return;
    __shared__ float t[32][33];
    const int z = isQ ? zz : zz - 16;
    const int b = z & 7;
    const int HO = isQ ? 32 : 16;
    const int stride = isQ ? 1 : 2;
    const float* in = (z >= 8) ? y : x;
    const float* w     = isQ ? qw : kw;
    const float* gamma = isQ ? qg : kg;
    const float* beta  = isQ ? qb : kb;
    const float* mean  = isQ ? qm : km;
    const float* var   = isQ ? qv : kvv;
    __half* hi = isQ ? qhi : khi;
    __half* lo = isQ ? qlo : klo;

    const int HW = HO * HO;
    const int hw0 = blockIdx.x * 32, c0 = blockIdx.y * 32;
    const int tx = threadIdx.x, ty = threadIdx.y;
    const int hw = hw0 + tx;
    const int oh = hw / HO, ow2 = hw % HO;
    const int ih0 = oh * stride - 1, iw0 = ow2 * stride - 1;
#pragma unroll
    for (int r = 0; r < 4; r++) {
        int c = c0 + ty + r * 8;
        const float* ip = in + (size_t)(b * 256 + c) * 1024;
        const float* wp = w + c * 9;
        float acc = 0.f;
#pragma unroll
        for (int kh = 0; kh < 3; kh++) {
            int ih = ih0 + kh;
            if (ih < 0 || ih > 31) continue;
#pragma unroll
            for (int kw2 = 0; kw2 < 3; kw2++) {
                int iw = iw0 + kw2;
                if (iw < 0 || iw > 31) continue;
                acc += wp[kh * 3 + kw2] * ip[ih * 32 + iw];
            }
        }
        float sc = gamma[c] * rsqrtf(var[c] + BN_EPS);
        float sh = beta[c] - mean[c] * sc;
        t[ty + r * 8][tx] = acc * sc + sh;
    }
    __syncthreads();
    size_t ob = (size_t)z * HW * 256;
#pragma unroll
    for (int r = 0; r < 4; r++) {
        float v = t[tx][ty + r * 8];
        __half hh = __float2half(v);
        size_t o = ob + (size_t)(hw0 + ty + r * 8) * 256 + c0 + tx;
        hi[o] = hh;
        lo[o] = __float2half(v - __half2float(hh));
    }
}

// ==================== 512-thread 256x128-tile 3-stage GEMM (A split, B single) ====================
#define SMS 40
#define A_HV (256 * SMS)                 // halves per A term buffer
#define B_HV (128 * SMS)
#define STG_B ((2 * A_HV + B_HV) * 2)    // 51200 bytes per stage
#define GEMM_SMEM3 (3 * STG_B)           // 153600

__device__ __forceinline__ void gemm_issue512(
    uint32_t smb, int stage,
    const __half* Ah, const __half* Al, const __half* Bh,
    int m0, int n0, int K, int k0, int rid, int cid) {
    uint32_t sb = smb + (uint32_t)stage * STG_B;
    uint32_t s0 = (uint32_t)(rid * SMS + cid) * 2;
    uint32_t s1 = (uint32_t)((rid + 128) * SMS + cid) * 2;
    cpa16(sb + s0,             &Ah[(size_t)(m0 + rid) * K + k0 + cid]);
    cpa16(sb + s1,             &Ah[(size_t)(m0 + rid + 128) * K + k0 + cid]);
    cpa16(sb + A_HV * 2 + s0,  &Al[(size_t)(m0 + rid) * K + k0 + cid]);
    cpa16(sb + A_HV * 2 + s1,  &Al[(size_t)(m0 + rid + 128) * K + k0 + cid]);
    cpa16(sb + 4 * A_HV + s0,  &Bh[(size_t)(n0 + rid) * K + k0 + cid]);
}

// OUT: 0 = fp32 + bias, 1 = fp16 hi/lo, 2 = fp16 single
template <int OUT>
__device__ __forceinline__ void gemm_core512(
    uint32_t smb,
    const __half* Ah, const __half* Al, const __half* Bh,
    float* Cf, __half* Chi, __half* Clo,
    const float* bias, int N, int K, int m0, int n0) {
    const int tid = threadIdx.x, lane = tid & 31, wid = tid >> 5;
    const int warp_m = wid & 7, warp_n = wid >> 3;   // 8 x 2 warps, warp tile 32x64

    float acc[2][8][4];
#pragma unroll
    for (int i = 0; i < 2; i++)
#pragma unroll
        for (int j = 0; j < 8; j++)
#pragma unroll
            for (int k = 0; k < 4; k++) acc[i][j][k] = 0.f;

    const int rid = tid >> 2;            // 0..127
    const int cid = (tid & 3) * 8;
    const int a_row = warp_m * 32 + (lane & 15);
    const int a_colx = (lane >> 4) << 3;
    const int b_row = warp_n * 64 + (lane & 7) + ((lane >> 4) << 3);
    const int b_colx = ((lane >> 3) & 1) << 3;

    const int nk = K / 32;
    gemm_issue512(smb, 0, Ah, Al, Bh, m0, n0, K, 0, rid, cid);
    CP_COMMIT();
    gemm_issue512(smb, 1, Ah, Al, Bh, m0, n0, K, 32, rid, cid);
    CP_COMMIT();

    int stage = 0;
    for (int i = 0; i < nk; i++) {
        CP_WAIT1();
        __syncthreads();

        const uint32_t base = smb + (uint32_t)stage * STG_B;
#pragma unroll
        for (int ks = 0; ks < 2; ks++) {
            const int kc = ks * 16;
            uint32_t ah[2][4], al[2][4];
#pragma unroll
            for (int mt = 0; mt < 2; mt++) {
                uint32_t off = (uint32_t)((a_row + mt * 16) * SMS + kc + a_colx) * 2;
                ldm_x4(ah[mt], base + off);
                ldm_x4(al[mt], base + A_HV * 2 + off);
            }
#pragma unroll
            for (int ng = 0; ng < 4; ng++) {
                uint32_t bh[4];
                uint32_t off = (uint32_t)((b_row + ng * 16) * SMS + kc + b_colx) * 2;
                ldm_x4(bh, base + 4 * A_HV + off);
#pragma unroll
                for (int mt = 0; mt < 2; mt++)
#pragma unroll
                    for (int nt = 0; nt < 2; nt++)
                        mma16816(acc[mt][ng * 2 + nt], ah[mt], &bh[nt * 2]);
#pragma unroll
                for (int mt = 0; mt < 2; mt++)
#pragma unroll
                    for (int nt = 0; nt < 2; nt++)
                        mma16816(acc[mt][ng * 2 + nt], al[mt], &bh[nt * 2]);
            }
        }

        if (i + 2 < nk)
            gemm_issue512(smb, (stage + 2 >= 3) ? stage - 1 : stage + 2,
                          Ah, Al, Bh, m0, n0, K, (i + 2) * 32, rid, cid);
        CP_COMMIT();
        stage = (stage + 1 == 3) ? 0 : stage + 1;
    }

#pragma unroll
    for (int mt = 0; mt < 2; mt++) {
        int mrow0 = m0 + warp_m * 32 + mt * 16 + (lane >> 2);
        int mrow1 = mrow0 + 8;
        float bv0 = (OUT == 0 && bias) ? bias[mrow0] : 0.f;
        float bv1 = (OUT == 0 && bias) ? bias[mrow1] : 0.f;
#pragma unroll
        for (int j = 0; j < 8; j++) {
            int n = n0 + warp_n * 64 + j * 8 + (lane & 3) * 2;
            float* c = acc[mt][j];
            size_t o0 = (size_t)mrow0 * N + n;
            size_t o1 = (size_t)mrow1 * N + n;
            if (OUT == 1) {
                uint32_t h0, l0, h1, l1;
                split2h(c[0], c[1], h0, l0);
                split2h(c[2], c[3], h1, l1);
                *(uint32_t*)&Chi[o0] = h0; *(uint32_t*)&Clo[o0] = l0;
                *(uint32_t*)&Chi[o1] = h1; *(uint32_t*)&Clo[o1] = l1;
            } else if (OUT == 2) {
                *(uint32_t*)&Chi[o0] = pack2h(c[0], c[1]);
                *(uint32_t*)&Chi[o1] = pack2h(c[2], c[3]);
            } else {
                *(float2*)&Cf[o0] = make_float2(c[0] + bv0, c[1] + bv0);
                *(float2*)&Cf[o1] = make_float2(c[2] + bv1, c[3] + bv1);
            }
        }
    }
}

// ---- merged q + kv pointwise GEMMs.  grid (24, 16), 512 threads ----
__global__ void __launch_bounds__(512, 1)
gemm_dual(const __half* __restrict__ qAh, const __half* __restrict__ qAl,
          const __half* __restrict__ qB,
          __half* __restrict__ qChi, __half* __restrict__ qClo,
          const __half* __restrict__ kAh, const __half* __restrict__ kAl,
          const __half* __restrict__ kB,
          __half* __restrict__ kC) {
    extern __shared__ __half gsm[];
    const uint32_t smb = smem_u32(gsm);
    const int bx = blockIdx.x, z = blockIdx.y;
    if (bx < 16) {
        int m0 = (bx >> 2) * 256, n0 = (bx & 3) * 128;
        gemm_core512<1>(smb,
            qAh + (size_t)z * 1024 * 256, qAl + (size_t)z * 1024 * 256, qB,
            nullptr, qChi + (size_t)z * 1024 * 512, qClo + (size_t)z * 1024 * 512,
            nullptr, 512, 256, m0, n0);
    } else {
        int n0 = (bx - 16) * 128;
        gemm_core512<2>(smb,
            kAh + (size_t)z * 256 * 256, kAl + (size_t)z * 256 * 256, kB,
            nullptr, kC + (size_t)z * 256 * 1024, nullptr,
            nullptr, 1024, 256, 0, n0);
    }
}

// ---- out projection GEMM.  grid (8, 16), 512 threads ----
__global__ void __launch_bounds__(512, 1)
gemm_out(const __half* __restrict__ Ah, const __half* __restrict__ Al,
         const __half* __restrict__ B,
         float* __restrict__ Cf, const float* __restrict__ bias) {
    extern __shared__ __half gsm[];
    const uint32_t smb = smem_u32(gsm);
    const int z = blockIdx.y;
    int n0 = blockIdx.x * 128;
    gemm_core512<0>(smb,
        Ah, Al, B + (size_t)z * 1024 * 512,
        Cf + (size_t)z * 256 * 1024, nullptr, nullptr,
        bias, 1024, 512, 0, n0);
}

// ==================== attention: Q split / K,V single fp16, online softmax ====================
#define ATT_S 72
#define AKH 0
#define AVH (256 * ATT_S)
#define AQW (2 * 256 * ATT_S)
#define QSLOT (2 * 16 * ATT_S)
#define ATT_SMEM ((2 * 256 + 16 * 2 * 16) * ATT_S * 2)   // 147456 B

__device__ __forceinline__ void att_stage_qw(uint32_t smb, int wid,
                                             const __half* qhi, const __half* qlo,
                                             size_t qb, int lane) {
    uint32_t base = smb + (uint32_t)(AQW + wid * QSLOT) * 2;
#pragma unroll
    for (int j = 0; j < 4; j++) {
        int idx = j * 32 + lane;
        int row = idx >> 3, ch = (idx & 7) * 8;
        uint32_t so = (uint32_t)(row * ATT_S + ch) * 2;
        cpa16(base + so,                  &qhi[qb + (size_t)row * 512 + ch]);
        cpa16(base + 16 * ATT_S * 2 + so, &qlo[qb + (size_t)row * 512 + ch]);
    }
}

__global__ void __launch_bounds__(512, 1)
attn_mma(const __half* __restrict__ qhi, const __half* __restrict__ qlo,
         const __half* __restrict__ kv,
         __half* __restrict__ ao) {
    extern __shared__ __half sm[];
    const int tid = threadIdx.x, lane = tid & 31, wid = tid >> 5;
    const int h = blockIdx.x, z = blockIdx.y;
    const int zk = ((z >> 3) ^ 1) * 8 + (z & 7);
    const uint32_t smb = smem_u32(sm);

    {
        size_t kb = (size_t)zk * 256 * 1024 + h * 64;
        size_t vb = kb + 512;
        for (int i = tid; i < 2048; i += 512) {
            int row = i >> 3, ch = (i & 7) * 8;
            uint32_t so = (uint32_t)(row * ATT_S + ch) * 2;
            cpa16(smb + AKH * 2 + so, &kv[kb + (size_t)row * 1024 + ch]);
            cpa16(smb + AVH * 2 + so, &kv[vb + (size_t)row * 1024 + ch]);
        }
        att_stage_qw(smb, wid, qhi, qlo,
                     ((size_t)z * 1024 + wid * 16) * 512 + h * 64, lane);
        CP_COMMIT();
        CP_WAIT0();
        __syncthreads();
    }

    const int a_row = lane & 15;
    const int a_cx = (lane >> 4) << 3;
    const int b_rx = (lane & 7) + ((lane >> 4) << 3);
    const int b_cx = ((lane >> 3) & 1) << 3;
    const int v_rx = (lane & 7) + (((lane >> 3) & 1) << 3);
    const int v_cx = (lane >> 4) << 3;
    const uint32_t qbase = smb + (uint32_t)(AQW + wid * QSLOT) * 2;

    for (int i = 0; i < 4; i++) {
        const int trow = (i * 16 + wid) * 16;

        float o[8][4];
#pragma unroll
        for (int j = 0; j < 8; j++)
#pragma unroll
            for (int k = 0; k < 4; k++) o[j][k] = 0.f;
        float m0 = -1e30f, m1 = -1e30f, s0 = 0.f, s1 = 0.f;

#pragma unroll
        for (int ck = 0; ck < 4; ck++) {
            float c[8][4];
#pragma unroll
            for (int t = 0; t < 8; t++)
#pragma unroll
                for (int k = 0; k < 4; k++) c[t][k] = 0.f;

#pragma unroll
            for (int kt = 0; kt < 4; kt++) {
                uint32_t aH[4], aL[4];
                uint32_t aoff = (uint32_t)(a_row * ATT_S + kt * 16 + a_cx) * 2;
                ldm_x4(aH, qbase + aoff);
                ldm_x4(aL, qbase + 16 * ATT_S * 2 + aoff);
#pragma unroll
                for (int jp = 0; jp < 2; jp++) {
                    int jt = jp * 2;
                    uint32_t bo0 = (uint32_t)((ck * 64 + jt * 16 + b_rx) * ATT_S + kt * 16 + b_cx) * 2;
                    uint32_t bo1 = (uint32_t)((ck * 64 + (jt + 1) * 16 + b_rx) * ATT_S + kt * 16 + b_cx) * 2;
                    uint32_t bH0[4], bH1[4];
                    ldm_x4(bH0, smb + AKH * 2 + bo0);
                    ldm_x4(bH1, smb + AKH * 2 + bo1);
                    float *c0 = c[jt * 2], *c1 = c[jt * 2 + 1];
                    float *c2 = c[jt * 2 + 2], *c3 = c[jt * 2 + 3];
                    mma16816(c0, aH, &bH0[0]); mma16816(c1, aH, &bH0[2]);
                    mma16816(c2, aH, &bH1[0]); mma16816(c3, aH, &bH1[2]);
                    mma16816(c0, aL, &bH0[0]); mma16816(c1, aL, &bH0[2]);
                    mma16816(c2, aL, &bH1[0]); mma16816(c3, aL, &bH1[2]);
                }
            }

            if (ck == 3 && i < 3) {
                att_stage_qw(smb, wid, qhi, qlo,
                             ((size_t)z * 1024 + ((i + 1) * 16 + wid) * 16) * 512 + h * 64, lane);
                CP_COMMIT();
            }

            {
                float cm0 = -1e30f, cm1 = -1e30f;
#pragma unroll
                for (int t = 0; t < 8; t++) {
                    cm0 = fmaxf(cm0, fmaxf(c[t][0], c[t][1]));
                    cm1 = fmaxf(cm1, fmaxf(c[t][2], c[t][3]));
                }
                cm0 = fmaxf(cm0, __shfl_xor_sync(0xffffffffu, cm0, 1));
                cm0 = fmaxf(cm0, __shfl_xor_sync(0xffffffffu, cm0, 2));
                cm1 = fmaxf(cm1, __shfl_xor_sync(0xffffffffu, cm1, 1));
                cm1 = fmaxf(cm1, __shfl_xor_sync(0xffffffffu, cm1, 2));
                float mn0 = fmaxf(m0, cm0), mn1 = fmaxf(m1, cm1);
                float sc0 = __expf(m0 - mn0), sc1 = __expf(m1 - mn1);
                s0 *= sc0; s1 *= sc1;
#pragma unroll
                for (int j = 0; j < 8; j++) {
                    o[j][0] *= sc0; o[j][1] *= sc0;
                    o[j][2] *= sc1; o[j][3] *= sc1;
                }
#pragma unroll
                for (int t = 0; t < 8; t++) {
                    c[t][0] = __expf(c[t][0] - mn0); s0 += c[t][0];
                    c[t][1] = __expf(c[t][1] - mn0); s0 += c[t][1];
                    c[t][2] = __expf(c[t][2] - mn1); s1 += c[t][2];
                    c[t][3] = __expf(c[t][3] - mn1); s1 += c[t][3];
                }
                m0 = mn0; m1 = mn1;
            }

#pragma unroll
            for (int ktl = 0; ktl < 4; ktl++) {
                uint32_t aH[4], aL[4];
                split2h(c[2 * ktl][0], c[2 * ktl][1], aH[0], aL[0]);
                split2h(c[2 * ktl][2], c[2 * ktl][3], aH[1], aL[1]);
                split2h(c[2 * ktl + 1][0], c[2 * ktl + 1][1], aH[2], aL[2]);
                split2h(c[2 * ktl + 1][2], c[2 * ktl + 1][3], aH[3], aL[3]);
#pragma unroll
                for (int db = 0; db < 4; db += 2) {
                    uint32_t bo0 = (uint32_t)((ck * 64 + ktl * 16 + v_rx) * ATT_S + db * 16 + v_cx) * 2;
                    uint32_t bo1 = (uint32_t)((ck * 64 + ktl * 16 + v_rx) * ATT_S + (db + 1) * 16 + v_cx) * 2;
                    uint32_t bH0[4], bH1[4];
                    ldm_x4_t(bH0, smb + AVH * 2 + bo0);
                    ldm_x4_t(bH1, smb + AVH * 2 + bo1);
                    float *o0 = o[db * 2], *o1 = o[db * 2 + 1];
                    float *o2 = o[db * 2 + 2], *o3 = o[db * 2 + 3];
                    mma16816(o0, aH, &bH0[0]); mma16816(o1, aH, &bH0[2]);
                    mma16816(o2, aH, &bH1[0]); mma16816(o3, aH, &bH1[2]);
                    mma16816(o0, aL, &bH0[0]); mma16816(o1, aL, &bH0[2]);
                    mma16816(o2, aL, &bH1[0]); mma16816(o3, aL, &bH1[2]);
                }
            }
        }

        s0 += __shfl_xor_sync(0xffffffffu, s0, 1);
        s0 += __shfl_xor_sync(0xffffffffu, s0, 2);
        s1 += __shfl_xor_sync(0xffffffffu, s1, 1);
        s1 += __shfl_xor_sync(0xffffffffu, s1, 2);
        float i0 = 1.f / s0, i1 = 1.f / s1;
        {
            int row0 = trow + (lane >> 2);
            int row1 = row0 + 8;
            size_t b0 = ((size_t)z * 1024 + row0) * 512 + h * 64 + (lane & 3) * 2;
            size_t b1 = ((size_t)z * 1024 + row1) * 512 + h * 64 + (lane & 3) * 2;
#pragma unroll
            for (int nt = 0; nt < 8; nt++) {
                *(uint32_t*)&ao[b0 + nt * 8] = pack2h(o[nt][0] * i0, o[nt][1] * i0);
                *(uint32_t*)&ao[b1 + nt * 8] = pack2h(o[nt][2] * i1, o[nt][3] * i1);
            }
        }
        if (i < 3) CP_WAIT0();
    }
}

// ==================== launch ====================
extern "C" void kernel_launch(void* const* d_in, const int* in_sizes, int n_in,
                              void* d_out, int out_size) {
    const float* x        = (const float*)d_in[0];
    const float* y        = (const float*)d_in[1];
    const float* q_dw_w   = (const float*)d_in[2];
    const float* q_bn_g   = (const float*)d_in[3];
    const float* q_bn_b   = (const float*)d_in[4];
    const float* q_bn_m   = (const float*)d_in[5];
    const float* q_bn_v   = (const float*)d_in[6];
    const float* q_pw_w   = (const float*)d_in[7];
    const float* kv_dw_w  = (const float*)d_in[8];
    const float* kv_bn_g  = (const float*)d_in[9];
    const float* kv_bn_b  = (const float*)d_in[10];
    const float* kv_bn_m  = (const float*)d_in[11];
    const float* kv_bn_v  = (const float*)d_in[12];
    const float* kv_pw_w  = (const float*)d_in[13];
    const float* out_w    = (const float*)d_in[14];
    const float* out_b    = (const float*)d_in[15];
    float* out = (float*)d_out;

    __half *p_hqT_hi, *p_hqT_lo, *p_hkvT_hi, *p_hkvT_lo;
    __half *p_wq, *p_wkv, *p_wo_hi, *p_wo_lo;
    __half *p_qs_hi, *p_qs_lo, *p_kvs, *p_ao;
    cudaGetSymbolAddress((void**)&p_hqT_hi,  g_hqT_hi);
    cudaGetSymbolAddress((void**)&p_hqT_lo,  g_hqT_lo);
    cudaGetSymbolAddress((void**)&p_hkvT_hi, g_hkvT_hi);
    cudaGetSymbolAddress((void**)&p_hkvT_lo, g_hkvT_lo);
    cudaGetSymbolAddress((void**)&p_wq,     g_wq);
    cudaGetSymbolAddress((void**)&p_wkv,    g_wkv);
    cudaGetSymbolAddress((void**)&p_wo_hi,  g_wo_hi);
    cudaGetSymbolAddress((void**)&p_wo_lo,  g_wo_lo);
    cudaGetSymbolAddress((void**)&p_qs_hi,  g_qs_hi);
    cudaGetSymbolAddress((void**)&p_qs_lo,  g_qs_lo);
    cudaGetSymbolAddress((void**)&p_kvs,    g_kvs);
    cudaGetSymbolAddress((void**)&p_ao,     g_ao);

    cudaFuncSetAttribute(attn_mma,
                         cudaFuncAttributeMaxDynamicSharedMemorySize, ATT_SMEM);
    cudaFuncSetAttribute(gemm_dual,
                         cudaFuncAttributeMaxDynamicSharedMemorySize, GEMM_SMEM3);
    cudaFuncSetAttribute(gemm_out,
                         cudaFuncAttributeMaxDynamicSharedMemorySize, GEMM_SMEM3);

    // 1) merged dw conv + BN + transpose + split, plus weight conversion (z==32)
    {
        dim3 blk(32, 8);
        dim3 grid(32, 8, 33);
        dw_bn_split2<<<grid, blk>>>(x, y,
                                    q_dw_w, q_bn_g, q_bn_b, q_bn_m, q_bn_v,
                                    kv_dw_w, kv_bn_g, kv_bn_b, kv_bn_m, kv_bn_v,
                                    p_hqT_hi, p_hqT_lo, p_hkvT_hi, p_hkvT_lo,
                                    q_pw_w, kv_pw_w, out_w,
                                    p_wq, p_wkv, p_wo_hi, p_wo_lo);
    }
    // 2) merged q + kv pointwise GEMMs
    {
        dim3 grid(24, 16);
        gemm_dual<<<grid, 512, GEMM_SMEM3>>>(p_hqT_hi, p_hqT_lo, p_wq,
                                             p_qs_hi, p_qs_lo,
                                             p_hkvT_hi, p_hkvT_lo, p_wkv,
                                             p_kvs);
    }
    // 3) attention
    {
        dim3 grid(8, 16);
        attn_mma<<<grid, 512, ATT_SMEM>>>(p_qs_hi, p_qs_lo, p_kvs, p_ao);
    }
    // 4) out projection
    {
        dim3 grid(8, 16);
        gemm_out<<<grid, 512, GEMM_SMEM3>>>(p_wo_hi, p_wo_lo, p_ao, out, out_b);
    }
}

// round 14
// speedup vs baseline: 3.5365x; 1.0008x over previous
#include <cuda_runtime.h>
#include <cuda_fp16.h>
#include <math.h>
#include <cstdint>

#define BN_EPS 1e-5f

// ==================== PTX helpers (baseline, sm_103-safe) ====================
__device__ __forceinline__ uint32_t smem_u32(const void* p) {
    uint32_t a;
    asm("{ .reg .u64 t; cvta.to.shared.u64 t, %1; cvt.u32.u64 %0, t; }" : "=r"(a) : "l"(p));
    return a;
}
__device__ __forceinline__ void ldm_x4(uint32_t* r, uint32_t addr) {
    asm volatile("ldmatrix.sync.aligned.m8n8.x4.shared.b16 {%0,%1,%2,%3}, [%4];"
                 : "=r"(r[0]), "=r"(r[1]), "=r"(r[2]), "=r"(r[3]) : "r"(addr));
}
__device__ __forceinline__ void ldm_x4_t(uint32_t* r, uint32_t addr) {
    asm volatile("ldmatrix.sync.aligned.m8n8.x4.trans.shared.b16 {%0,%1,%2,%3}, [%4];"
                 : "=r"(r[0]), "=r"(r[1]), "=r"(r[2]), "=r"(r[3]) : "r"(addr));
}
__device__ __forceinline__ void mma16816(float* d, const uint32_t* a, const uint32_t* b) {
    asm volatile("mma.sync.aligned.m16n8k16.row.col.f32.f16.f16.f32 "
        "{%0,%1,%2,%3}, {%4,%5,%6,%7}, {%8,%9}, {%0,%1,%2,%3};"
        : "+f"(d[0]), "+f"(d[1]), "+f"(d[2]), "+f"(d[3])
        : "r"(a[0]), "r"(a[1]), "r"(a[2]), "r"(a[3]), "r"(b[0]), "r"(b[1]));
}
__device__ __forceinline__ void split2h(float x, float y, uint32_t &hi, uint32_t &lo) {
    __half2 h = __floats2half2_rn(x, y);
    hi = *(uint32_t*)&h;
    float2 hf = __half22float2(h);
    __half2 l = __floats2half2_rn(x - hf.x, y - hf.y);
    lo = *(uint32_t*)&l;
}
__device__ __forceinline__ uint32_t pack2h(float x, float y) {
    __half2 h = __floats2half2_rn(x, y);
    return *(uint32_t*)&h;
}
__device__ __forceinline__ void cpa16(uint32_t saddr, const void* g) {
    asm volatile("cp.async.cg.shared.global [%0], [%1], 16;" :: "r"(saddr), "l"(g));
}
#define CP_COMMIT() asm volatile("cp.async.commit_group;" ::: "memory")
#define CP_WAIT0()  asm volatile("cp.async.wait_group 0;" ::: "memory")

// ==================== scratch ====================
__device__ __half g_hqT_hi [16u * 1024 * 256];
__device__ __half g_hqT_lo [16u * 1024 * 256];
__device__ __half g_hkvT_hi[16u * 256 * 256];
__device__ __half g_hkvT_lo[16u * 256 * 256];
__device__ __half g_wq  [512 * 256];             // single fp16, pre-scaled 0.125
__device__ __half g_wkv [1024 * 256];
__device__ __half g_wo_hi[256 * 512], g_wo_lo[256 * 512];
__device__ __half g_qs_hi [16u * 1024 * 512], g_qs_lo [16u * 1024 * 512];
__device__ __half g_kvs [16u * 256 * 1024];
__device__ __half g_ao  [16u * 1024 * 512];

// ==================== merged dw conv + BN + transpose + split (+ weight conversion) ====================
__global__ void dw_bn_split2(const float* __restrict__ x, const float* __restrict__ y,
                             const float* __restrict__ qw, const float* __restrict__ qg,
                             const float* __restrict__ qb, const float* __restrict__ qm,
                             const float* __restrict__ qv,
                             const float* __restrict__ kw, const float* __restrict__ kg,
                             const float* __restrict__ kb, const float* __restrict__ km,
                             const float* __restrict__ kvv,
                             __half* __restrict__ qhi, __half* __restrict__ qlo,
                             __half* __restrict__ khi, __half* __restrict__ klo,
                             const float* __restrict__ qpw, const float* __restrict__ kvpw,
                             const float* __restrict__ ow,
                             __half* __restrict__ wq1, __half* __restrict__ wkv1,
                             __half* __restrict__ wohi, __half* __restrict__ wolo) {
    const int zz = blockIdx.z;
    const int tidf = threadIdx.y * 32 + threadIdx.x;
    if (zz == 32) {
        int bid = blockIdx.x * 8 + blockIdx.y;
        int i = (bid * 256 + tidf) * 8;
        if (i < 131072) {
            const float* in = qpw; int j = i;
            __half hb[8];
#pragma unroll
            for (int k = 0; k < 8; k++) hb[k] = __float2half(in[j + k] * 0.125f);
            *(uint4*)&wq1[j] = *(uint4*)hb;
        } else if (i < 393216) {
            const float* in = kvpw; int j = i - 131072;
            __half hb[8];
#pragma unroll
            for (int k = 0; k < 8; k++) hb[k] = __float2half(in[j + k]);
            *(uint4*)&wkv1[j] = *(uint4*)hb;
        } else {
            const float* in = ow; int j = i - 393216;
            __half hb[8], lb[8];
#pragma unroll
            for (int k = 0; k < 8; k++) {
                float v = in[j + k];
                hb[k] = __float2half(v);
                lb[k] = __float2half(v - __half2float(hb[k]));
            }
            *(uint4*)&wohi[j] = *(uint4*)hb;
            *(uint4*)&wolo[j] = *(uint4*)lb;
        }
        return;
    }
    const bool isQ = (zz < 16);
    if (!isQ && blockIdx.x >= 8) return;
    __shared__ float t[32][33];
    const int z = isQ ? zz : zz - 16;
    const int b = z & 7;
    const int HO = isQ ? 32 : 16;
    const int stride = isQ ? 1 : 2;
    const float* in = (z >= 8) ? y : x;
    const float* w     = isQ ? qw : kw;
    const float* gamma = isQ ? qg : kg;
    const float* beta  = isQ ? qb : kb;
    const float* mean  = isQ ? qm : km;
    const float* var   = isQ ? qv : kvv;
    __half* hi = isQ ? qhi : khi;
    __half* lo = isQ ? qlo : klo;

    const int HW = HO * HO;
    const int hw0 = blockIdx.x * 32, c0 = blockIdx.y * 32;
    const int tx = threadIdx.x, ty = threadIdx.y;
    const int hw = hw0 + tx;
    const int oh = hw / HO, ow2 = hw % HO;
    const int ih0 = oh * stride - 1, iw0 = ow2 * stride - 1;
#pragma unroll
    for (int r = 0; r < 4; r++) {
        int c = c0 + ty + r * 8;
        const float* ip = in + (size_t)(b * 256 + c) * 1024;
        const float* wp = w + c * 9;
        float acc = 0.f;
#pragma unroll
        for (int kh = 0; kh < 3; kh++) {
            int ih = ih0 + kh;
            if (ih < 0 || ih > 31) continue;
#pragma unroll
            for (int kw2 = 0; kw2 < 3; kw2++) {
                int iw = iw0 + kw2;
                if (iw < 0 || iw > 31) continue;
                acc += wp[kh * 3 + kw2] * ip[ih * 32 + iw];
            }
        }
        float sc = gamma[c] * rsqrtf(var[c] + BN_EPS);
        float sh = beta[c] - mean[c] * sc;
        t[ty + r * 8][tx] = acc * sc + sh;
    }
    __syncthreads();
    size_t ob = (size_t)z * HW * 256;
#pragma unroll
    for (int r = 0; r < 4; r++) {
        float v = t[tx][ty + r * 8];
        __half hh = __float2half(v);
        size_t o = ob + (size_t)(hw0 + ty + r * 8) * 256 + c0 + tx;
        hi[o] = hh;
        lo[o] = __float2half(v - __half2float(hh));
    }
}

// ==================== 512-thread 256x128-tile GEMM, 64-K chunks, 2-stage ====================
#define SMS 72                            // halves per row (64 + 8 pad)
#define A_HV (256 * SMS)
#define B_HV (128 * SMS)
#define STG_B ((2 * A_HV + B_HV) * 2)     // 92160 bytes per stage
#define GEMM_SMEM2 (2 * STG_B)            // 184320

__device__ __forceinline__ void gemm_issue64(
    uint32_t smb, int stage,
    const __half* Ah, const __half* Al, const __half* Bh,
    int m0, int n0, int K, int k0, int rid, int cid) {
    // rid 0..127, cid in halves {0,16,32,48}; each thread covers halves [cid,cid+16)
    uint32_t sb = smb + (uint32_t)stage * STG_B;
    uint32_t s0 = (uint32_t)(rid * SMS + cid) * 2;
    uint32_t s1 = (uint32_t)((rid + 128) * SMS + cid) * 2;
    const __half* a0 = &Ah[(size_t)(m0 + rid) * K + k0 + cid];
    const __half* a1 = &Ah[(size_t)(m0 + rid + 128) * K + k0 + cid];
    const __half* l0 = &Al[(size_t)(m0 + rid) * K + k0 + cid];
    const __half* l1 = &Al[(size_t)(m0 + rid + 128) * K + k0 + cid];
    const __half* b0 = &Bh[(size_t)(n0 + rid) * K + k0 + cid];
    cpa16(sb + s0,                  a0);     cpa16(sb + s0 + 16,                  a0 + 8);
    cpa16(sb + s1,                  a1);     cpa16(sb + s1 + 16,                  a1 + 8);
    cpa16(sb + A_HV * 2 + s0,       l0);     cpa16(sb + A_HV * 2 + s0 + 16,      l0 + 8);
    cpa16(sb + A_HV * 2 + s1,       l1);     cpa16(sb + A_HV * 2 + s1 + 16,      l1 + 8);
    cpa16(sb + 4 * A_HV + s0,       b0);     cpa16(sb + 4 * A_HV + s0 + 16,      b0 + 8);
}

// OUT: 0 = fp32 + bias, 1 = fp16 hi/lo, 2 = fp16 single
template <int OUT>
__device__ __forceinline__ void gemm_core64(
    uint32_t smb,
    const __half* Ah, const __half* Al, const __half* Bh,
    float* Cf, __half* Chi, __half* Clo,
    const float* bias, int N, int K, int m0, int n0) {
    const int tid = threadIdx.x, lane = tid & 31, wid = tid >> 5;
    const int warp_m = wid & 7, warp_n = wid >> 3;   // 8 x 2 warps, warp tile 32x64

    float acc[2][8][4];
#pragma unroll
    for (int i = 0; i < 2; i++)
#pragma unroll
        for (int j = 0; j < 8; j++)
#pragma unroll
            for (int k = 0; k < 4; k++) acc[i][j][k] = 0.f;

    const int rid = tid >> 2;            // 0..127
    const int cid = (tid & 3) * 16;      // halves
    const int a_row = warp_m * 32 + (lane & 15);
    const int a_colx = (lane >> 4) << 3;
    const int b_row = warp_n * 64 + (lane & 7) + ((lane >> 4) << 3);
    const int b_colx = ((lane >> 3) & 1) << 3;

    const int nk = K / 64;
    gemm_issue64(smb, 0, Ah, Al, Bh, m0, n0, K, 0, rid, cid);
    CP_COMMIT();

    int stage = 0;
    for (int i = 0; i < nk; i++) {
        CP_WAIT0();
        __syncthreads();   // chunk i visible; compute(i-1) done in all warps

        if (i + 1 < nk) {
            gemm_issue64(smb, stage ^ 1, Ah, Al, Bh, m0, n0, K, (i + 1) * 64, rid, cid);
            CP_COMMIT();
        }

        const uint32_t base = smb + (uint32_t)stage * STG_B;
#pragma unroll
        for (int ks = 0; ks < 4; ks++) {
            const int kc = ks * 16;
            uint32_t ah[2][4], al[2][4];
#pragma unroll
            for (int mt = 0; mt < 2; mt++) {
                uint32_t off = (uint32_t)((a_row + mt * 16) * SMS + kc + a_colx) * 2;
                ldm_x4(ah[mt], base + off);
                ldm_x4(al[mt], base + A_HV * 2 + off);
            }
#pragma unroll
            for (int ng = 0; ng < 4; ng++) {
                uint32_t bh[4];
                uint32_t off = (uint32_t)((b_row + ng * 16) * SMS + kc + b_colx) * 2;
                ldm_x4(bh, base + 4 * A_HV + off);
#pragma unroll
                for (int mt = 0; mt < 2; mt++)
#pragma unroll
                    for (int nt = 0; nt < 2; nt++)
                        mma16816(acc[mt][ng * 2 + nt], ah[mt], &bh[nt * 2]);
#pragma unroll
                for (int mt = 0; mt < 2; mt++)
#pragma unroll
                    for (int nt = 0; nt < 2; nt++)
                        mma16816(acc[mt][ng * 2 + nt], al[mt], &bh[nt * 2]);
            }
        }
        stage ^= 1;
    }

#pragma unroll
    for (int mt = 0; mt < 2; mt++) {
        int mrow0 = m0 + warp_m * 32 + mt * 16 + (lane >> 2);
        int mrow1 = mrow0 + 8;
        float bv0 = (OUT == 0 && bias) ? bias[mrow0] : 0.f;
        float bv1 = (OUT == 0 && bias) ? bias[mrow1] : 0.f;
#pragma unroll
        for (int j = 0; j < 8; j++) {
            int n = n0 + warp_n * 64 + j * 8 + (lane & 3) * 2;
            float* c = acc[mt][j];
            size_t o0 = (size_t)mrow0 * N + n;
            size_t o1 = (size_t)mrow1 * N + n;
            if (OUT == 1) {
                uint32_t h0, l0, h1, l1;
                split2h(c[0], c[1], h0, l0);
                split2h(c[2], c[3], h1, l1);
                *(uint32_t*)&Chi[o0] = h0; *(uint32_t*)&Clo[o0] = l0;
                *(uint32_t*)&Chi[o1] = h1; *(uint32_t*)&Clo[o1] = l1;
            } else if (OUT == 2) {
                *(uint32_t*)&Chi[o0] = pack2h(c[0], c[1]);
                *(uint32_t*)&Chi[o1] = pack2h(c[2], c[3]);
            } else {
                *(float2*)&Cf[o0] = make_float2(c[0] + bv0, c[1] + bv0);
                *(float2*)&Cf[o1] = make_float2(c[2] + bv1, c[3] + bv1);
            }
        }
    }
}

// ---- merged q + kv pointwise GEMMs.  grid (24, 16), 512 threads ----
__global__ void __launch_bounds__(512, 1)
gemm_dual(const __half* __restrict__ qAh, const __half* __restrict__ qAl,
          const __half* __restrict__ qB,
          __half* __restrict__ qChi, __half* __restrict__ qClo,
          const __half* __restrict__ kAh, const __half* __restrict__ kAl,
          const __half* __restrict__ kB,
          __half* __restrict__ kC) {
    extern __shared__ __half gsm[];
    const uint32_t smb = smem_u32(gsm);
    const int bx = blockIdx.x, z = blockIdx.y;
    if (bx < 16) {
        int m0 = (bx >> 2) * 256, n0 = (bx & 3) * 128;
        gemm_core64<1>(smb,
            qAh + (size_t)z * 1024 * 256, qAl + (size_t)z * 1024 * 256, qB,
            nullptr, qChi + (size_t)z * 1024 * 512, qClo + (size_t)z * 1024 * 512,
            nullptr, 512, 256, m0, n0);
    } else {
        int n0 = (bx - 16) * 128;
        gemm_core64<2>(smb,
            kAh + (size_t)z * 256 * 256, kAl + (size_t)z * 256 * 256, kB,
            nullptr, kC + (size_t)z * 256 * 1024, nullptr,
            nullptr, 1024, 256, 0, n0);
    }
}

// ---- out projection GEMM.  grid (8, 16), 512 threads ----
__global__ void __launch_bounds__(512, 1)
gemm_out(const __half* __restrict__ Ah, const __half* __restrict__ Al,
         const __half* __restrict__ B,
         float* __restrict__ Cf, const float* __restrict__ bias) {
    extern __shared__ __half gsm[];
    const uint32_t smb = smem_u32(gsm);
    const int z = blockIdx.y;
    int n0 = blockIdx.x * 128;
    gemm_core64<0>(smb,
        Ah, Al, B + (size_t)z * 1024 * 512,
        Cf + (size_t)z * 256 * 1024, nullptr, nullptr,
        bias, 1024, 512, 0, n0);
}

// ==================== attention: Q split / K,V,P single fp16, online softmax ====================
#define ATT_S 72
#define AKH 0
#define AVH (256 * ATT_S)
#define AQW (2 * 256 * ATT_S)
#define QSLOT (2 * 16 * ATT_S)
#define ATT_SMEM ((2 * 256 + 16 * 2 * 16) * ATT_S * 2)   // 147456 B

__device__ __forceinline__ void att_stage_qw(uint32_t smb, int wid,
                                             const __half* qhi, const __half* qlo,
                                             size_t qb, int lane) {
    uint32_t base = smb + (uint32_t)(AQW + wid * QSLOT) * 2;
#pragma unroll
    for (int j = 0; j < 4; j++) {
        int idx = j * 32 + lane;
        int row = idx >> 3, ch = (idx & 7) * 8;
        uint32_t so = (uint32_t)(row * ATT_S + ch) * 2;
        cpa16(base + so,                  &qhi[qb + (size_t)row * 512 + ch]);
        cpa16(base + 16 * ATT_S * 2 + so, &qlo[qb + (size_t)row * 512 + ch]);
    }
}

__global__ void __launch_bounds__(512, 1)
attn_mma(const __half* __restrict__ qhi, const __half* __restrict__ qlo,
         const __half* __restrict__ kv,
         __half* __restrict__ ao) {
    extern __shared__ __half sm[];
    const int tid = threadIdx.x, lane = tid & 31, wid = tid >> 5;
    const int h = blockIdx.x, z = blockIdx.y;
    const int zk = ((z >> 3) ^ 1) * 8 + (z & 7);
    const uint32_t smb = smem_u32(sm);

    {
        size_t kb = (size_t)zk * 256 * 1024 + h * 64;
        size_t vb = kb + 512;
        for (int i = tid; i < 2048; i += 512) {
            int row = i >> 3, ch = (i & 7) * 8;
            uint32_t so = (uint32_t)(row * ATT_S + ch) * 2;
            cpa16(smb + AKH * 2 + so, &kv[kb + (size_t)row * 1024 + ch]);
            cpa16(smb + AVH * 2 + so, &kv[vb + (size_t)row * 1024 + ch]);
        }
        att_stage_qw(smb, wid, qhi, qlo,
                     ((size_t)z * 1024 + wid * 16) * 512 + h * 64, lane);
        CP_COMMIT();
        CP_WAIT0();
        __syncthreads();
    }

    const int a_row = lane & 15;
    const int a_cx = (lane >> 4) << 3;
    const int b_rx = (lane & 7) + ((lane >> 4) << 3);
    const int b_cx = ((lane >> 3) & 1) << 3;
    const int v_rx = (lane & 7) + (((lane >> 3) & 1) << 3);
    const int v_cx = (lane >> 4) << 3;
    const uint32_t qbase = smb + (uint32_t)(AQW + wid * QSLOT) * 2;

    for (int i = 0; i < 4; i++) {
        const int trow = (i * 16 + wid) * 16;

        float o[8][4];
#pragma unroll
        for (int j = 0; j < 8; j++)
#pragma unroll
            for (int k = 0; k < 4; k++) o[j][k] = 0.f;
        float m0 = -1e30f, m1 = -1e30f, s0 = 0.f, s1 = 0.f;

#pragma unroll
        for (int ck = 0; ck < 4; ck++) {
            float c[8][4];
#pragma unroll
            for (int t = 0; t < 8; t++)
#pragma unroll
                for (int k = 0; k < 4; k++) c[t][k] = 0.f;

#pragma unroll
            for (int kt = 0; kt < 4; kt++) {
                uint32_t aH[4], aL[4];
                uint32_t aoff = (uint32_t)(a_row * ATT_S + kt * 16 + a_cx) * 2;
                ldm_x4(aH, qbase + aoff);
                ldm_x4(aL, qbase + 16 * ATT_S * 2 + aoff);
#pragma unroll
                for (int jp = 0; jp < 2; jp++) {
                    int jt = jp * 2;
                    uint32_t bo0 = (uint32_t)((ck * 64 + jt * 16 + b_rx) * ATT_S + kt * 16 + b_cx) * 2;
                    uint32_t bo1 = (uint32_t)((ck * 64 + (jt + 1) * 16 + b_rx) * ATT_S + kt * 16 + b_cx) * 2;
                    uint32_t bH0[4], bH1[4];
                    ldm_x4(bH0, smb + AKH * 2 + bo0);
                    ldm_x4(bH1, smb + AKH * 2 + bo1);
                    float *c0 = c[jt * 2], *c1 = c[jt * 2 + 1];
                    float *c2 = c[jt * 2 + 2], *c3 = c[jt * 2 + 3];
                    mma16816(c0, aH, &bH0[0]); mma16816(c1, aH, &bH0[2]);
                    mma16816(c2, aH, &bH1[0]); mma16816(c3, aH, &bH1[2]);
                    mma16816(c0, aL, &bH0[0]); mma16816(c1, aL, &bH0[2]);
                    mma16816(c2, aL, &bH1[0]); mma16816(c3, aL, &bH1[2]);
                }
            }

            if (ck == 3 && i < 3) {
                att_stage_qw(smb, wid, qhi, qlo,
                             ((size_t)z * 1024 + ((i + 1) * 16 + wid) * 16) * 512 + h * 64, lane);
                CP_COMMIT();
            }

            {
                float cm0 = -1e30f, cm1 = -1e30f;
#pragma unroll
                for (int t = 0; t < 8; t++) {
                    cm0 = fmaxf(cm0, fmaxf(c[t][0], c[t][1]));
                    cm1 = fmaxf(cm1, fmaxf(c[t][2], c[t][3]));
                }
                cm0 = fmaxf(cm0, __shfl_xor_sync(0xffffffffu, cm0, 1));
                cm0 = fmaxf(cm0, __shfl_xor_sync(0xffffffffu, cm0, 2));
                cm1 = fmaxf(cm1, __shfl_xor_sync(0xffffffffu, cm1, 1));
                cm1 = fmaxf(cm1, __shfl_xor_sync(0xffffffffu, cm1, 2));
                float mn0 = fmaxf(m0, cm0), mn1 = fmaxf(m1, cm1);
                float sc0 = __expf(m0 - mn0), sc1 = __expf(m1 - mn1);
                s0 *= sc0; s1 *= sc1;
#pragma unroll
                for (int j = 0; j < 8; j++) {
                    o[j][0] *= sc0; o[j][1] *= sc0;
                    o[j][2] *= sc1; o[j][3] *= sc1;
                }
#pragma unroll
                for (int t = 0; t < 8; t++) {
                    c[t][0] = __expf(c[t][0] - mn0); s0 += c[t][0];
                    c[t][1] = __expf(c[t][1] - mn0); s0 += c[t][1];
                    c[t][2] = __expf(c[t][2] - mn1); s1 += c[t][2];
                    c[t][3] = __expf(c[t][3] - mn1); s1 += c[t][3];
                }
                m0 = mn0; m1 = mn1;
            }

            // ---- PV chunk (single fp16 P) ----
#pragma unroll
            for (int ktl = 0; ktl < 4; ktl++) {
                uint32_t aP[4];
                aP[0] = pack2h(c[2 * ktl][0], c[2 * ktl][1]);
                aP[1] = pack2h(c[2 * ktl][2], c[2 * ktl][3]);
                aP[2] = pack2h(c[2 * ktl + 1][0], c[2 * ktl + 1][1]);
                aP[3] = pack2h(c[2 * ktl + 1][2], c[2 * ktl + 1][3]);
#pragma unroll
                for (int db = 0; db < 4; db += 2) {
                    uint32_t bo0 = (uint32_t)((ck * 64 + ktl * 16 + v_rx) * ATT_S + db * 16 + v_cx) * 2;
                    uint32_t bo1 = (uint32_t)((ck * 64 + ktl * 16 + v_rx) * ATT_S + (db + 1) * 16 + v_cx) * 2;
                    uint32_t bH0[4], bH1[4];
                    ldm_x4_t(bH0, smb + AVH * 2 + bo0);
                    ldm_x4_t(bH1, smb + AVH * 2 + bo1);
                    mma16816(o[db * 2],     aP, &bH0[0]);
                    mma16816(o[db * 2 + 1], aP, &bH0[2]);
                    mma16816(o[db * 2 + 2], aP, &bH1[0]);
                    mma16816(o[db * 2 + 3], aP, &bH1[2]);
                }
            }
        }

        s0 += __shfl_xor_sync(0xffffffffu, s0, 1);
        s0 += __shfl_xor_sync(0xffffffffu, s0, 2);
        s1 += __shfl_xor_sync(0xffffffffu, s1, 1);
        s1 += __shfl_xor_sync(0xffffffffu, s1, 2);
        float i0 = 1.f / s0, i1 = 1.f / s1;
        {
            int row0 = trow + (lane >> 2);
            int row1 = row0 + 8;
            size_t b0 = ((size_t)z * 1024 + row0) * 512 + h * 64 + (lane & 3) * 2;
            size_t b1 = ((size_t)z * 1024 + row1) * 512 + h * 64 + (lane & 3) * 2;
#pragma unroll
            for (int nt = 0; nt < 8; nt++) {
                *(uint32_t*)&ao[b0 + nt * 8] = pack2h(o[nt][0] * i0, o[nt][1] * i0);
                *(uint32_t*)&ao[b1 + nt * 8] = pack2h(o[nt][2] * i1, o[nt][3] * i1);
            }
        }
        if (i < 3) CP_WAIT0();
    }
}

// ==================== launch ====================
extern "C" void kernel_launch(void* const* d_in, const int* in_sizes, int n_in,
                              void* d_out, int out_size) {
    const float* x        = (const float*)d_in[0];
    const float* y        = (const float*)d_in[1];
    const float* q_dw_w   = (const float*)d_in[2];
    const float* q_bn_g   = (const float*)d_in[3];
    const float* q_bn_b   = (const float*)d_in[4];
    const float* q_bn_m   = (const float*)d_in[5];
    const float* q_bn_v   = (const float*)d_in[6];
    const float* q_pw_w   = (const float*)d_in[7];
    const float* kv_dw_w  = (const float*)d_in[8];
    const float* kv_bn_g  = (const float*)d_in[9];
    const float* kv_bn_b  = (const float*)d_in[10];
    const float* kv_bn_m  = (const float*)d_in[11];
    const float* kv_bn_v  = (const float*)d_in[12];
    const float* kv_pw_w  = (const float*)d_in[13];
    const float* out_w    = (const float*)d_in[14];
    const float* out_b    = (const float*)d_in[15];
    float* out = (float*)d_out;

    __half *p_hqT_hi, *p_hqT_lo, *p_hkvT_hi, *p_hkvT_lo;
    __half *p_wq, *p_wkv, *p_wo_hi, *p_wo_lo;
    __half *p_qs_hi, *p_qs_lo, *p_kvs, *p_ao;
    cudaGetSymbolAddress((void**)&p_hqT_hi,  g_hqT_hi);
    cudaGetSymbolAddress((void**)&p_hqT_lo,  g_hqT_lo);
    cudaGetSymbolAddress((void**)&p_hkvT_hi, g_hkvT_hi);
    cudaGetSymbolAddress((void**)&p_hkvT_lo, g_hkvT_lo);
    cudaGetSymbolAddress((void**)&p_wq,     g_wq);
    cudaGetSymbolAddress((void**)&p_wkv,    g_wkv);
    cudaGetSymbolAddress((void**)&p_wo_hi,  g_wo_hi);
    cudaGetSymbolAddress((void**)&p_wo_lo,  g_wo_lo);
    cudaGetSymbolAddress((void**)&p_qs_hi,  g_qs_hi);
    cudaGetSymbolAddress((void**)&p_qs_lo,  g_qs_lo);
    cudaGetSymbolAddress((void**)&p_kvs,    g_kvs);
    cudaGetSymbolAddress((void**)&p_ao,     g_ao);

    cudaFuncSetAttribute(attn_mma,
                         cudaFuncAttributeMaxDynamicSharedMemorySize, ATT_SMEM);
    cudaFuncSetAttribute(gemm_dual,
                         cudaFuncAttributeMaxDynamicSharedMemorySize, GEMM_SMEM2);
    cudaFuncSetAttribute(gemm_out,
                         cudaFuncAttributeMaxDynamicSharedMemorySize, GEMM_SMEM2);

    // 1) merged dw conv + BN + transpose + split, plus weight conversion (z==32)
    {
        dim3 blk(32, 8);
        dim3 grid(32, 8, 33);
        dw_bn_split2<<<grid, blk>>>(x, y,
                                    q_dw_w, q_bn_g, q_bn_b, q_bn_m, q_bn_v,
                                    kv_dw_w, kv_bn_g, kv_bn_b, kv_bn_m, kv_bn_v,
                                    p_hqT_hi, p_hqT_lo, p_hkvT_hi, p_hkvT_lo,
                                    q_pw_w, kv_pw_w, out_w,
                                    p_wq, p_wkv, p_wo_hi, p_wo_lo);
    }
    // 2) merged q + kv pointwise GEMMs
    {
        dim3 grid(24, 16);
        gemm_dual<<<grid, 512, GEMM_SMEM2>>>(p_hqT_hi, p_hqT_lo, p_wq,
                                             p_qs_hi, p_qs_lo,
                                             p_hkvT_hi, p_hkvT_lo, p_wkv,
                                             p_kvs);
    }
    // 3) attention
    {
        dim3 grid(8, 16);
        attn_mma<<<grid, 512, ATT_SMEM>>>(p_qs_hi, p_qs_lo, p_kvs, p_ao);
    }
    // 4) out projection
    {
        dim3 grid(8, 16);
        gemm_out<<<grid, 512, GEMM_SMEM2>>>(p_wo_hi, p_wo_lo, p_ao, out, out_b);
    }
}

// round 15
// speedup vs baseline: 3.5698x; 1.0094x over previous
#include <cuda_runtime.h>
#include <cuda_fp16.h>
#include <math.h>
#include <cstdint>

#define BN_EPS 1e-5f

// ==================== PTX helpers (baseline, sm_103-safe) ====================
__device__ __forceinline__ uint32_t smem_u32(const void* p) {
    uint32_t a;
    asm("{ .reg .u64 t; cvta.to.shared.u64 t, %1; cvt.u32.u64 %0, t; }" : "=r"(a) : "l"(p));
    return a;
}
__device__ __forceinline__ void ldm_x4(uint32_t* r, uint32_t addr) {
    asm volatile("ldmatrix.sync.aligned.m8n8.x4.shared.b16 {%0,%1,%2,%3}, [%4];"
                 : "=r"(r[0]), "=r"(r[1]), "=r"(r[2]), "=r"(r[3]) : "r"(addr));
}
__device__ __forceinline__ void ldm_x4_t(uint32_t* r, uint32_t addr) {
    asm volatile("ldmatrix.sync.aligned.m8n8.x4.trans.shared.b16 {%0,%1,%2,%3}, [%4];"
                 : "=r"(r[0]), "=r"(r[1]), "=r"(r[2]), "=r"(r[3]) : "r"(addr));
}
__device__ __forceinline__ void mma16816(float* d, const uint32_t* a, const uint32_t* b) {
    asm volatile("mma.sync.aligned.m16n8k16.row.col.f32.f16.f16.f32 "
        "{%0,%1,%2,%3}, {%4,%5,%6,%7}, {%8,%9}, {%0,%1,%2,%3};"
        : "+f"(d[0]), "+f"(d[1]), "+f"(d[2]), "+f"(d[3])
        : "r"(a[0]), "r"(a[1]), "r"(a[2]), "r"(a[3]), "r"(b[0]), "r"(b[1]));
}
__device__ __forceinline__ void split2h(float x, float y, uint32_t &hi, uint32_t &lo) {
    __half2 h = __floats2half2_rn(x, y);
    hi = *(uint32_t*)&h;
    float2 hf = __half22float2(h);
    __half2 l = __floats2half2_rn(x - hf.x, y - hf.y);
    lo = *(uint32_t*)&l;
}
__device__ __forceinline__ uint32_t pack2h(float x, float y) {
    __half2 h = __floats2half2_rn(x, y);
    return *(uint32_t*)&h;
}
__device__ __forceinline__ void cpa16(uint32_t saddr, const void* g) {
    asm volatile("cp.async.cg.shared.global [%0], [%1], 16;" :: "r"(saddr), "l"(g));
}
#define CP_COMMIT() asm volatile("cp.async.commit_group;" ::: "memory")
#define CP_WAIT1()  asm volatile("cp.async.wait_group 1;" ::: "memory")
#define CP_WAIT0()  asm volatile("cp.async.wait_group 0;" ::: "memory")

// ==================== scratch ====================
__device__ __half g_hqT_hi [16u * 1024 * 256];
__device__ __half g_hqT_lo [16u * 1024 * 256];
__device__ __half g_hkvT_hi[16u * 256 * 256];
__device__ __half g_hkvT_lo[16u * 256 * 256];
__device__ __half g_wq  [512 * 256];             // single fp16, pre-scaled 0.125
__device__ __half g_wkv [1024 * 256];
__device__ __half g_wo_hi[256 * 512], g_wo_lo[256 * 512];
__device__ __half g_qs_hi [16u * 1024 * 512], g_qs_lo [16u * 1024 * 512];
__device__ __half g_kvs [16u * 256 * 1024];
__device__ __half g_ao  [16u * 1024 * 512];

// ==================== merged dw conv + BN + transpose + split (+ weight conversion) ====================
__global__ void dw_bn_split2(const float* __restrict__ x, const float* __restrict__ y,
                             const float* __restrict__ qw, const float* __restrict__ qg,
                             const float* __restrict__ qb, const float* __restrict__ qm,
                             const float* __restrict__ qv,
                             const float* __restrict__ kw, const float* __restrict__ kg,
                             const float* __restrict__ kb, const float* __restrict__ km,
                             const float* __restrict__ kvv,
                             __half* __restrict__ qhi, __half* __restrict__ qlo,
                             __half* __restrict__ khi, __half* __restrict__ klo,
                             const float* __restrict__ qpw, const float* __restrict__ kvpw,
                             const float* __restrict__ ow,
                             __half* __restrict__ wq1, __half* __restrict__ wkv1,
                             __half* __restrict__ wohi, __half* __restrict__ wolo) {
    const int zz = blockIdx.z;
    const int tidf = threadIdx.y * 32 + threadIdx.x;
    if (zz == 32) {
        int bid = blockIdx.x * 8 + blockIdx.y;
        int i = (bid * 256 + tidf) * 8;
        if (i < 131072) {
            const float* in = qpw; int j = i;
            __half hb[8];
#pragma unroll
            for (int k = 0; k < 8; k++) hb[k] = __float2half(in[j + k] * 0.125f);
            *(uint4*)&wq1[j] = *(uint4*)hb;
        } else if (i < 393216) {
            const float* in = kvpw; int j = i - 131072;
            __half hb[8];
#pragma unroll
            for (int k = 0; k < 8; k++) hb[k] = __float2half(in[j + k]);
            *(uint4*)&wkv1[j] = *(uint4*)hb;
        } else {
            const float* in = ow; int j = i - 393216;
            __half hb[8], lb[8];
#pragma unroll
            for (int k = 0; k < 8; k++) {
                float v = in[j + k];
                hb[k] = __float2half(v);
                lb[k] = __float2half(v - __half2float(hb[k]));
            }
            *(uint4*)&wohi[j] = *(uint4*)hb;
            *(uint4*)&wolo[j] = *(uint4*)lb;
        }
        return;
    }
    const bool isQ = (zz < 16);
    if (!isQ && blockIdx.x >= 8) return;
    __shared__ float t[32][33];
    const int z = isQ ? zz : zz - 16;
    const int b = z & 7;
    const int HO = isQ ? 32 : 16;
    const int stride = isQ ? 1 : 2;
    const float* in = (z >= 8) ? y : x;
    const float* w     = isQ ? qw : kw;
    const float* gamma = isQ ? qg : kg;
    const float* beta  = isQ ? qb : kb;
    const float* mean  = isQ ? qm : km;
    const float* var   = isQ ? qv : kvv;
    __half* hi = isQ ? qhi : khi;
    __half* lo = isQ ? qlo : klo;

    const int HW = HO * HO;
    const int hw0 = blockIdx.x * 32, c0 = blockIdx.y * 32;
    const int tx = threadIdx.x, ty = threadIdx.y;
    const int hw = hw0 + tx;
    const int oh = hw / HO, ow2 = hw % HO;
    const int ih0 = oh * stride - 1, iw0 = ow2 * stride - 1;
#pragma unroll
    for (int r = 0; r < 4; r++) {
        int c = c0 + ty + r * 8;
        const float* ip = in + (size_t)(b * 256 + c) * 1024;
        const float* wp = w + c * 9;
        float acc = 0.f;
#pragma unroll
        for (int kh = 0; kh < 3; kh++) {
            int ih = ih0 + kh;
            if (ih < 0 || ih > 31) continue;
#pragma unroll
            for (int kw2 = 0; kw2 < 3; kw2++) {
                int iw = iw0 + kw2;
                if (iw < 0 || iw > 31) continue;
                acc += wp[kh * 3 + kw2] * ip[ih * 32 + iw];
            }
        }
        float sc = gamma[c] * rsqrtf(var[c] + BN_EPS);
        float sh = beta[c] - mean[c] * sc;
        t[ty + r * 8][tx] = acc * sc + sh;
    }
    __syncthreads();
    size_t ob = (size_t)z * HW * 256;
#pragma unroll
    for (int r = 0; r < 4; r++) {
        float v = t[tx][ty + r * 8];
        __half hh = __float2half(v);
        size_t o = ob + (size_t)(hw0 + ty + r * 8) * 256 + c0 + tx;
        hi[o] = hh;
        lo[o] = __float2half(v - __half2float(hh));
    }
}

// ==================== 512-thread 256x128-tile GEMM, 32-K chunks, 3-stage ====================
#define SMS 40
#define A_HV (256 * SMS)                 // halves per A term buffer
#define B_HV (128 * SMS)
#define STG_B ((2 * A_HV + B_HV) * 2)    // 51200 bytes per stage
#define GEMM_SMEM3 (3 * STG_B)           // 153600

__device__ __forceinline__ void gemm_issue512(
    uint32_t smb, int stage,
    const __half* Ah, const __half* Al, const __half* Bh,
    int m0, int n0, int K, int k0, int rid, int cid) {
    uint32_t sb = smb + (uint32_t)stage * STG_B;
    uint32_t s0 = (uint32_t)(rid * SMS + cid) * 2;
    uint32_t s1 = (uint32_t)((rid + 128) * SMS + cid) * 2;
    cpa16(sb + s0,             &Ah[(size_t)(m0 + rid) * K + k0 + cid]);
    cpa16(sb + s1,             &Ah[(size_t)(m0 + rid + 128) * K + k0 + cid]);
    cpa16(sb + A_HV * 2 + s0,  &Al[(size_t)(m0 + rid) * K + k0 + cid]);
    cpa16(sb + A_HV * 2 + s1,  &Al[(size_t)(m0 + rid + 128) * K + k0 + cid]);
    cpa16(sb + 4 * A_HV + s0,  &Bh[(size_t)(n0 + rid) * K + k0 + cid]);
}

// OUT: 0 = fp32 + bias, 1 = fp16 hi/lo, 2 = fp16 single
template <int OUT>
__device__ __forceinline__ void gemm_core512(
    uint32_t smb,
    const __half* Ah, const __half* Al, const __half* Bh,
    float* Cf, __half* Chi, __half* Clo,
    const float* bias, int N, int K, int m0, int n0) {
    const int tid = threadIdx.x, lane = tid & 31, wid = tid >> 5;
    const int warp_m = wid & 7, warp_n = wid >> 3;   // 8 x 2 warps, warp tile 32x64

    float acc[2][8][4];
#pragma unroll
    for (int i = 0; i < 2; i++)
#pragma unroll
        for (int j = 0; j < 8; j++)
#pragma unroll
            for (int k = 0; k < 4; k++) acc[i][j][k] = 0.f;

    const int rid = tid >> 2;            // 0..127
    const int cid = (tid & 3) * 8;
    const int a_row = warp_m * 32 + (lane & 15);
    const int a_colx = (lane >> 4) << 3;
    const int b_row = warp_n * 64 + (lane & 7) + ((lane >> 4) << 3);
    const int b_colx = ((lane >> 3) & 1) << 3;

    const int nk = K / 32;
    gemm_issue512(smb, 0, Ah, Al, Bh, m0, n0, K, 0, rid, cid);
    CP_COMMIT();
    gemm_issue512(smb, 1, Ah, Al, Bh, m0, n0, K, 32, rid, cid);
    CP_COMMIT();

    int stage = 0;
    for (int i = 0; i < nk; i++) {
        CP_WAIT1();
        __syncthreads();   // chunk i landed in all warps' view; compute(i-1) done everywhere

        // issue chunk i+2 into buffer (i+2)%3 == (i-1)%3 (safe: read finished pre-barrier)
        if (i + 2 < nk) {
            gemm_issue512(smb, (stage + 2 >= 3) ? stage - 1 : stage + 2,
                          Ah, Al, Bh, m0, n0, K, (i + 2) * 32, rid, cid);
        }
        CP_COMMIT();

        const uint32_t base = smb + (uint32_t)stage * STG_B;
#pragma unroll
        for (int ks = 0; ks < 2; ks++) {
            const int kc = ks * 16;
            uint32_t ah[2][4], al[2][4];
#pragma unroll
            for (int mt = 0; mt < 2; mt++) {
                uint32_t off = (uint32_t)((a_row + mt * 16) * SMS + kc + a_colx) * 2;
                ldm_x4(ah[mt], base + off);
                ldm_x4(al[mt], base + A_HV * 2 + off);
            }
#pragma unroll
            for (int ng = 0; ng < 4; ng++) {
                uint32_t bh[4];
                uint32_t off = (uint32_t)((b_row + ng * 16) * SMS + kc + b_colx) * 2;
                ldm_x4(bh, base + 4 * A_HV + off);
#pragma unroll
                for (int mt = 0; mt < 2; mt++)
#pragma unroll
                    for (int nt = 0; nt < 2; nt++)
                        mma16816(acc[mt][ng * 2 + nt], ah[mt], &bh[nt * 2]);
#pragma unroll
                for (int mt = 0; mt < 2; mt++)
#pragma unroll
                    for (int nt = 0; nt < 2; nt++)
                        mma16816(acc[mt][ng * 2 + nt], al[mt], &bh[nt * 2]);
            }
        }
        stage = (stage + 1 == 3) ? 0 : stage + 1;
    }

#pragma unroll
    for (int mt = 0; mt < 2; mt++) {
        int mrow0 = m0 + warp_m * 32 + mt * 16 + (lane >> 2);
        int mrow1 = mrow0 + 8;
        float bv0 = (OUT == 0 && bias) ? bias[mrow0] : 0.f;
        float bv1 = (OUT == 0 && bias) ? bias[mrow1] : 0.f;
#pragma unroll
        for (int j = 0; j < 8; j++) {
            int n = n0 + warp_n * 64 + j * 8 + (lane & 3) * 2;
            float* c = acc[mt][j];
            size_t o0 = (size_t)mrow0 * N + n;
            size_t o1 = (size_t)mrow1 * N + n;
            if (OUT == 1) {
                uint32_t h0, l0, h1, l1;
                split2h(c[0], c[1], h0, l0);
                split2h(c[2], c[3], h1, l1);
                *(uint32_t*)&Chi[o0] = h0; *(uint32_t*)&Clo[o0] = l0;
                *(uint32_t*)&Chi[o1] = h1; *(uint32_t*)&Clo[o1] = l1;
            } else if (OUT == 2) {
                *(uint32_t*)&Chi[o0] = pack2h(c[0], c[1]);
                *(uint32_t*)&Chi[o1] = pack2h(c[2], c[3]);
            } else {
                *(float2*)&Cf[o0] = make_float2(c[0] + bv0, c[1] + bv0);
                *(float2*)&Cf[o1] = make_float2(c[2] + bv1, c[3] + bv1);
            }
        }
    }
}

// ---- merged q + kv pointwise GEMMs.  grid (24, 16), 512 threads ----
__global__ void __launch_bounds__(512, 1)
gemm_dual(const __half* __restrict__ qAh, const __half* __restrict__ qAl,
          const __half* __restrict__ qB,
          __half* __restrict__ qChi, __half* __restrict__ qClo,
          const __half* __restrict__ kAh, const __half* __restrict__ kAl,
          const __half* __restrict__ kB,
          __half* __restrict__ kC) {
    extern __shared__ __half gsm[];
    const uint32_t smb = smem_u32(gsm);
    const int bx = blockIdx.x, z = blockIdx.y;
    if (bx < 16) {
        int m0 = (bx >> 2) * 256, n0 = (bx & 3) * 128;
        gemm_core512<1>(smb,
            qAh + (size_t)z * 1024 * 256, qAl + (size_t)z * 1024 * 256, qB,
            nullptr, qChi + (size_t)z * 1024 * 512, qClo + (size_t)z * 1024 * 512,
            nullptr, 512, 256, m0, n0);
    } else {
        int n0 = (bx - 16) * 128;
        gemm_core512<2>(smb,
            kAh + (size_t)z * 256 * 256, kAl + (size_t)z * 256 * 256, kB,
            nullptr, kC + (size_t)z * 256 * 1024, nullptr,
            nullptr, 1024, 256, 0, n0);
    }
}

// ---- out projection GEMM.  grid (8, 16), 512 threads ----
__global__ void __launch_bounds__(512, 1)
gemm_out(const __half* __restrict__ Ah, const __half* __restrict__ Al,
         const __half* __restrict__ B,
         float* __restrict__ Cf, const float* __restrict__ bias) {
    extern __shared__ __half gsm[];
    const uint32_t smb = smem_u32(gsm);
    const int z = blockIdx.y;
    int n0 = blockIdx.x * 128;
    gemm_core512<0>(smb,
        Ah, Al, B + (size_t)z * 1024 * 512,
        Cf + (size_t)z * 256 * 1024, nullptr, nullptr,
        bias, 1024, 512, 0, n0);
}

// ==================== attention: Q split / K,V,P single fp16, online softmax ====================
#define ATT_S 72
#define AKH 0
#define AVH (256 * ATT_S)
#define AQW (2 * 256 * ATT_S)
#define QSLOT (2 * 16 * ATT_S)
#define ATT_SMEM ((2 * 256 + 16 * 2 * 16) * ATT_S * 2)   // 147456 B

__device__ __forceinline__ void att_stage_qw(uint32_t smb, int wid,
                                             const __half* qhi, const __half* qlo,
                                             size_t qb, int lane) {
    uint32_t base = smb + (uint32_t)(AQW + wid * QSLOT) * 2;
#pragma unroll
    for (int j = 0; j < 4; j++) {
        int idx = j * 32 + lane;
        int row = idx >> 3, ch = (idx & 7) * 8;
        uint32_t so = (uint32_t)(row * ATT_S + ch) * 2;
        cpa16(base + so,                  &qhi[qb + (size_t)row * 512 + ch]);
        cpa16(base + 16 * ATT_S * 2 + so, &qlo[qb + (size_t)row * 512 + ch]);
    }
}

__global__ void __launch_bounds__(512, 1)
attn_mma(const __half* __restrict__ qhi, const __half* __restrict__ qlo,
         const __half* __restrict__ kv,
         __half* __restrict__ ao) {
    extern __shared__ __half sm[];
    const int tid = threadIdx.x, lane = tid & 31, wid = tid >> 5;
    const int h = blockIdx.x, z = blockIdx.y;
    const int zk = ((z >> 3) ^ 1) * 8 + (z & 7);
    const uint32_t smb = smem_u32(sm);

    {
        size_t kb = (size_t)zk * 256 * 1024 + h * 64;
        size_t vb = kb + 512;
        for (int i = tid; i < 2048; i += 512) {
            int row = i >> 3, ch = (i & 7) * 8;
            uint32_t so = (uint32_t)(row * ATT_S + ch) * 2;
            cpa16(smb + AKH * 2 + so, &kv[kb + (size_t)row * 1024 + ch]);
            cpa16(smb + AVH * 2 + so, &kv[vb + (size_t)row * 1024 + ch]);
        }
        att_stage_qw(smb, wid, qhi, qlo,
                     ((size_t)z * 1024 + wid * 16) * 512 + h * 64, lane);
        CP_COMMIT();
        CP_WAIT0();
        __syncthreads();
    }

    const int a_row = lane & 15;
    const int a_cx = (lane >> 4) << 3;
    const int b_rx = (lane & 7) + ((lane >> 4) << 3);
    const int b_cx = ((lane >> 3) & 1) << 3;
    const int v_rx = (lane & 7) + (((lane >> 3) & 1) << 3);
    const int v_cx = (lane >> 4) << 3;
    const uint32_t qbase = smb + (uint32_t)(AQW + wid * QSLOT) * 2;

    for (int i = 0; i < 4; i++) {
        const int trow = (i * 16 + wid) * 16;

        float o[8][4];
#pragma unroll
        for (int j = 0; j < 8; j++)
#pragma unroll
            for (int k = 0; k < 4; k++) o[j][k] = 0.f;
        float m0 = -1e30f, m1 = -1e30f, s0 = 0.f, s1 = 0.f;

#pragma unroll
        for (int ck = 0; ck < 4; ck++) {
            float c[8][4];
#pragma unroll
            for (int t = 0; t < 8; t++)
#pragma unroll
                for (int k = 0; k < 4; k++) c[t][k] = 0.f;

#pragma unroll
            for (int kt = 0; kt < 4; kt++) {
                uint32_t aH[4], aL[4];
                uint32_t aoff = (uint32_t)(a_row * ATT_S + kt * 16 + a_cx) * 2;
                ldm_x4(aH, qbase + aoff);
                ldm_x4(aL, qbase + 16 * ATT_S * 2 + aoff);
#pragma unroll
                for (int jp = 0; jp < 2; jp++) {
                    int jt = jp * 2;
                    uint32_t bo0 = (uint32_t)((ck * 64 + jt * 16 + b_rx) * ATT_S + kt * 16 + b_cx) * 2;
                    uint32_t bo1 = (uint32_t)((ck * 64 + (jt + 1) * 16 + b_rx) * ATT_S + kt * 16 + b_cx) * 2;
                    uint32_t bH0[4], bH1[4];
                    ldm_x4(bH0, smb + AKH * 2 + bo0);
                    ldm_x4(bH1, smb + AKH * 2 + bo1);
                    float *c0 = c[jt * 2], *c1 = c[jt * 2 + 1];
                    float *c2 = c[jt * 2 + 2], *c3 = c[jt * 2 + 3];
                    mma16816(c0, aH, &bH0[0]); mma16816(c1, aH, &bH0[2]);
                    mma16816(c2, aH, &bH1[0]); mma16816(c3, aH, &bH1[2]);
                    mma16816(c0, aL, &bH0[0]); mma16816(c1, aL, &bH0[2]);
                    mma16816(c2, aL, &bH1[0]); mma16816(c3, aL, &bH1[2]);
                }
            }

            if (ck == 3 && i < 3) {
                att_stage_qw(smb, wid, qhi, qlo,
                             ((size_t)z * 1024 + ((i + 1) * 16 + wid) * 16) * 512 + h * 64, lane);
                CP_COMMIT();
            }

            {
                float cm0 = -1e30f, cm1 = -1e30f;
#pragma unroll
                for (int t = 0; t < 8; t++) {
                    cm0 = fmaxf(cm0, fmaxf(c[t][0], c[t][1]));
                    cm1 = fmaxf(cm1, fmaxf(c[t][2], c[t][3]));
                }
                cm0 = fmaxf(cm0, __shfl_xor_sync(0xffffffffu, cm0, 1));
                cm0 = fmaxf(cm0, __shfl_xor_sync(0xffffffffu, cm0, 2));
                cm1 = fmaxf(cm1, __shfl_xor_sync(0xffffffffu, cm1, 1));
                cm1 = fmaxf(cm1, __shfl_xor_sync(0xffffffffu, cm1, 2));
                float mn0 = fmaxf(m0, cm0), mn1 = fmaxf(m1, cm1);
                float sc0 = __expf(m0 - mn0), sc1 = __expf(m1 - mn1);
                s0 *= sc0; s1 *= sc1;
#pragma unroll
                for (int j = 0; j < 8; j++) {
                    o[j][0] *= sc0; o[j][1] *= sc0;
                    o[j][2] *= sc1; o[j][3] *= sc1;
                }
#pragma unroll
                for (int t = 0; t < 8; t++) {
                    c[t][0] = __expf(c[t][0] - mn0); s0 += c[t][0];
                    c[t][1] = __expf(c[t][1] - mn0); s0 += c[t][1];
                    c[t][2] = __expf(c[t][2] - mn1); s1 += c[t][2];
                    c[t][3] = __expf(c[t][3] - mn1); s1 += c[t][3];
                }
                m0 = mn0; m1 = mn1;
            }

            // ---- PV chunk (single fp16 P) ----
#pragma unroll
            for (int ktl = 0; ktl < 4; ktl++) {
                uint32_t aP[4];
                aP[0] = pack2h(c[2 * ktl][0], c[2 * ktl][1]);
                aP[1] = pack2h(c[2 * ktl][2], c[2 * ktl][3]);
                aP[2] = pack2h(c[2 * ktl + 1][0], c[2 * ktl + 1][1]);
                aP[3] = pack2h(c[2 * ktl + 1][2], c[2 * ktl + 1][3]);
#pragma unroll
                for (int db = 0; db < 4; db += 2) {
                    uint32_t bo0 = (uint32_t)((ck * 64 + ktl * 16 + v_rx) * ATT_S + db * 16 + v_cx) * 2;
                    uint32_t bo1 = (uint32_t)((ck * 64 + ktl * 16 + v_rx) * ATT_S + (db + 1) * 16 + v_cx) * 2;
                    uint32_t bH0[4], bH1[4];
                    ldm_x4_t(bH0, smb + AVH * 2 + bo0);
                    ldm_x4_t(bH1, smb + AVH * 2 + bo1);
                    mma16816(o[db * 2],     aP, &bH0[0]);
                    mma16816(o[db * 2 + 1], aP, &bH0[2]);
                    mma16816(o[db * 2 + 2], aP, &bH1[0]);
                    mma16816(o[db * 2 + 3], aP, &bH1[2]);
                }
            }
        }

        s0 += __shfl_xor_sync(0xffffffffu, s0, 1);
        s0 += __shfl_xor_sync(0xffffffffu, s0, 2);
        s1 += __shfl_xor_sync(0xffffffffu, s1, 1);
        s1 += __shfl_xor_sync(0xffffffffu, s1, 2);
        float i0 = 1.f / s0, i1 = 1.f / s1;
        {
            int row0 = trow + (lane >> 2);
            int row1 = row0 + 8;
            size_t b0 = ((size_t)z * 1024 + row0) * 512 + h * 64 + (lane & 3) * 2;
            size_t b1 = ((size_t)z * 1024 + row1) * 512 + h * 64 + (lane & 3) * 2;
#pragma unroll
            for (int nt = 0; nt < 8; nt++) {
                *(uint32_t*)&ao[b0 + nt * 8] = pack2h(o[nt][0] * i0, o[nt][1] * i0);
                *(uint32_t*)&ao[b1 + nt * 8] = pack2h(o[nt][2] * i1, o[nt][3] * i1);
            }
        }
        if (i < 3) CP_WAIT0();
    }
}

// ==================== launch ====================
extern "C" void kernel_launch(void* const* d_in, const int* in_sizes, int n_in,
                              void* d_out, int out_size) {
    const float* x        = (const float*)d_in[0];
    const float* y        = (const float*)d_in[1];
    const float* q_dw_w   = (const float*)d_in[2];
    const float* q_bn_g   = (const float*)d_in[3];
    const float* q_bn_b   = (const float*)d_in[4];
    const float* q_bn_m   = (const float*)d_in[5];
    const float* q_bn_v   = (const float*)d_in[6];
    const float* q_pw_w   = (const float*)d_in[7];
    const float* kv_dw_w  = (const float*)d_in[8];
    const float* kv_bn_g  = (const float*)d_in[9];
    const float* kv_bn_b  = (const float*)d_in[10];
    const float* kv_bn_m  = (const float*)d_in[11];
    const float* kv_bn_v  = (const float*)d_in[12];
    const float* kv_pw_w  = (const float*)d_in[13];
    const float* out_w    = (const float*)d_in[14];
    const float* out_b    = (const float*)d_in[15];
    float* out = (float*)d_out;

    __half *p_hqT_hi, *p_hqT_lo, *p_hkvT_hi, *p_hkvT_lo;
    __half *p_wq, *p_wkv, *p_wo_hi, *p_wo_lo;
    __half *p_qs_hi, *p_qs_lo, *p_kvs, *p_ao;
    cudaGetSymbolAddress((void**)&p_hqT_hi,  g_hqT_hi);
    cudaGetSymbolAddress((void**)&p_hqT_lo,  g_hqT_lo);
    cudaGetSymbolAddress((void**)&p_hkvT_hi, g_hkvT_hi);
    cudaGetSymbolAddress((void**)&p_hkvT_lo, g_hkvT_lo);
    cudaGetSymbolAddress((void**)&p_wq,     g_wq);
    cudaGetSymbolAddress((void**)&p_wkv,    g_wkv);
    cudaGetSymbolAddress((void**)&p_wo_hi,  g_wo_hi);
    cudaGetSymbolAddress((void**)&p_wo_lo,  g_wo_lo);
    cudaGetSymbolAddress((void**)&p_qs_hi,  g_qs_hi);
    cudaGetSymbolAddress((void**)&p_qs_lo,  g_qs_lo);
    cudaGetSymbolAddress((void**)&p_kvs,    g_kvs);
    cudaGetSymbolAddress((void**)&p_ao,     g_ao);

    cudaFuncSetAttribute(attn_mma,
                         cudaFuncAttributeMaxDynamicSharedMemorySize, ATT_SMEM);
    cudaFuncSetAttribute(gemm_dual,
                         cudaFuncAttributeMaxDynamicSharedMemorySize, GEMM_SMEM3);
    cudaFuncSetAttribute(gemm_out,
                         cudaFuncAttributeMaxDynamicSharedMemorySize, GEMM_SMEM3);

    // 1) merged dw conv + BN + transpose + split, plus weight conversion (z==32)
    {
        dim3 blk(32, 8);
        dim3 grid(32, 8, 33);
        dw_bn_split2<<<grid, blk>>>(x, y,
                                    q_dw_w, q_bn_g, q_bn_b, q_bn_m, q_bn_v,
                                    kv_dw_w, kv_bn_g, kv_bn_b, kv_bn_m, kv_bn_v,
                                    p_hqT_hi, p_hqT_lo, p_hkvT_hi, p_hkvT_lo,
                                    q_pw_w, kv_pw_w, out_w,
                                    p_wq, p_wkv, p_wo_hi, p_wo_lo);
    }
    // 2) merged q + kv pointwise GEMMs
    {
        dim3 grid(24, 16);
        gemm_dual<<<grid, 512, GEMM_SMEM3>>>(p_hqT_hi, p_hqT_lo, p_wq,
                                             p_qs_hi, p_qs_lo,
                                             p_hkvT_hi, p_hkvT_lo, p_wkv,
                                             p_kvs);
    }
    // 3) attention
    {
        dim3 grid(8, 16);
        attn_mma<<<grid, 512, ATT_SMEM>>>(p_qs_hi, p_qs_lo, p_kvs, p_ao);
    }
    // 4) out projection
    {
        dim3 grid(8, 16);
        gemm_out<<<grid, 512, GEMM_SMEM3>>>(p_wo_hi, p_wo_lo, p_ao, out, out_b);
    }
}

// round 16
// speedup vs baseline: 3.6758x; 1.0297x over previous
#include <cuda_runtime.h>
#include <cuda_fp16.h>
#include <math.h>
#include <cstdint>

#define BN_EPS 1e-5f

// ==================== PTX helpers (baseline, sm_103-safe) ====================
__device__ __forceinline__ uint32_t smem_u32(const void* p) {
    uint32_t a;
    asm("{ .reg .u64 t; cvta.to.shared.u64 t, %1; cvt.u32.u64 %0, t; }" : "=r"(a) : "l"(p));
    return a;
}
__device__ __forceinline__ void ldm_x4(uint32_t* r, uint32_t addr) {
    asm volatile("ldmatrix.sync.aligned.m8n8.x4.shared.b16 {%0,%1,%2,%3}, [%4];"
                 : "=r"(r[0]), "=r"(r[1]), "=r"(r[2]), "=r"(r[3]) : "r"(addr));
}
__device__ __forceinline__ void ldm_x4_t(uint32_t* r, uint32_t addr) {
    asm volatile("ldmatrix.sync.aligned.m8n8.x4.trans.shared.b16 {%0,%1,%2,%3}, [%4];"
                 : "=r"(r[0]), "=r"(r[1]), "=r"(r[2]), "=r"(r[3]) : "r"(addr));
}
__device__ __forceinline__ void mma16816(float* d, const uint32_t* a, const uint32_t* b) {
    asm volatile("mma.sync.aligned.m16n8k16.row.col.f32.f16.f16.f32 "
        "{%0,%1,%2,%3}, {%4,%5,%6,%7}, {%8,%9}, {%0,%1,%2,%3};"
        : "+f"(d[0]), "+f"(d[1]), "+f"(d[2]), "+f"(d[3])
        : "r"(a[0]), "r"(a[1]), "r"(a[2]), "r"(a[3]), "r"(b[0]), "r"(b[1]));
}
__device__ __forceinline__ void split2h(float x, float y, uint32_t &hi, uint32_t &lo) {
    __half2 h = __floats2half2_rn(x, y);
    hi = *(uint32_t*)&h;
    float2 hf = __half22float2(h);
    __half2 l = __floats2half2_rn(x - hf.x, y - hf.y);
    lo = *(uint32_t*)&l;
}
__device__ __forceinline__ uint32_t pack2h(float x, float y) {
    __half2 h = __floats2half2_rn(x, y);
    return *(uint32_t*)&h;
}
__device__ __forceinline__ void cpa16(uint32_t saddr, const void* g) {
    asm volatile("cp.async.cg.shared.global [%0], [%1], 16;" :: "r"(saddr), "l"(g));
}
#define CP_COMMIT() asm volatile("cp.async.commit_group;" ::: "memory")
#define CP_WAIT1()  asm volatile("cp.async.wait_group 1;" ::: "memory")
#define CP_WAIT0()  asm volatile("cp.async.wait_group 0;" ::: "memory")

// ==================== scratch ====================
__device__ __half g_hqT_hi [16u * 1024 * 256];
__device__ __half g_hqT_lo [16u * 1024 * 256];
__device__ __half g_hkvT_hi[16u * 256 * 256];
__device__ __half g_hkvT_lo[16u * 256 * 256];
__device__ __half g_wq  [512 * 256];             // single fp16, pre-scaled 0.125
__device__ __half g_wkv [1024 * 256];
__device__ __half g_wo_hi[256 * 512], g_wo_lo[256 * 512];
__device__ __half g_qs_hi [16u * 1024 * 512], g_qs_lo [16u * 1024 * 512];
__device__ __half g_kvs [16u * 256 * 1024];
__device__ __half g_ao  [16u * 1024 * 512];

// ==================== merged dw conv + BN + transpose + split (+ weight conversion) ====================
__global__ void dw_bn_split2(const float* __restrict__ x, const float* __restrict__ y,
                             const float* __restrict__ qw, const float* __restrict__ qg,
                             const float* __restrict__ qb, const float* __restrict__ qm,
                             const float* __restrict__ qv,
                             const float* __restrict__ kw, const float* __restrict__ kg,
                             const float* __restrict__ kb, const float* __restrict__ km,
                             const float* __restrict__ kvv,
                             __half* __restrict__ qhi, __half* __restrict__ qlo,
                             __half* __restrict__ khi, __half* __restrict__ klo,
                             const float* __restrict__ qpw, const float* __restrict__ kvpw,
                             const float* __restrict__ ow,
                             __half* __restrict__ wq1, __half* __restrict__ wkv1,
                             __half* __restrict__ wohi, __half* __restrict__ wolo) {
    const int zz = blockIdx.z;
    const int tidf = threadIdx.y * 32 + threadIdx.x;
    if (zz == 32) {
        int bid = blockIdx.x * 8 + blockIdx.y;
        int i = (bid * 256 + tidf) * 8;
        if (i < 131072) {
            const float* in = qpw; int j = i;
            __half hb[8];
#pragma unroll
            for (int k = 0; k < 8; k++) hb[k] = __float2half(in[j + k] * 0.125f);
            *(uint4*)&wq1[j] = *(uint4*)hb;
        } else if (i < 393216) {
            const float* in = kvpw; int j = i - 131072;
            __half hb[8];
#pragma unroll
            for (int k = 0; k < 8; k++) hb[k] = __float2half(in[j + k]);
            *(uint4*)&wkv1[j] = *(uint4*)hb;
        } else {
            const float* in = ow; int j = i - 393216;
            __half hb[8], lb[8];
#pragma unroll
            for (int k = 0; k < 8; k++) {
                float v = in[j + k];
                hb[k] = __float2half(v);
                lb[k] = __float2half(v - __half2float(hb[k]));
            }
            *(uint4*)&wohi[j] = *(uint4*)hb;
            *(uint4*)&wolo[j] = *(uint4*)lb;
        }
        return;
    }
    const bool isQ = (zz < 16);
    if (!isQ && blockIdx.x >= 8) return;
    __shared__ float t[32][33];
    const int z = isQ ? zz : zz - 16;
    const int b = z & 7;
    const int HO = isQ ? 32 : 16;
    const int stride = isQ ? 1 : 2;
    const float* in = (z >= 8) ? y : x;
    const float* w     = isQ ? qw : kw;
    const float* gamma = isQ ? qg : kg;
    const float* beta  = isQ ? qb : kb;
    const float* mean  = isQ ? qm : km;
    const float* var   = isQ ? qv : kvv;
    __half* hi = isQ ? qhi : khi;
    __half* lo = isQ ? qlo : klo;

    const int HW = HO * HO;
    const int hw0 = blockIdx.x * 32, c0 = blockIdx.y * 32;
    const int tx = threadIdx.x, ty = threadIdx.y;
    const int hw = hw0 + tx;
    const int oh = hw / HO, ow2 = hw % HO;
    const int ih0 = oh * stride - 1, iw0 = ow2 * stride - 1;
#pragma unroll
    for (int r = 0; r < 4; r++) {
        int c = c0 + ty + r * 8;
        const float* ip = in + (size_t)(b * 256 + c) * 1024;
        const float* wp = w + c * 9;
        float acc = 0.f;
#pragma unroll
        for (int kh = 0; kh < 3; kh++) {
            int ih = ih0 + kh;
            if (ih < 0 || ih > 31) continue;
#pragma unroll
            for (int kw2 = 0; kw2 < 3; kw2++) {
                int iw = iw0 + kw2;
                if (iw < 0 || iw > 31) continue;
                acc += wp[kh * 3 + kw2] * ip[ih * 32 + iw];
            }
        }
        float sc = gamma[c] * rsqrtf(var[c] + BN_EPS);
        float sh = beta[c] - mean[c] * sc;
        t[ty + r * 8][tx] = acc * sc + sh;
    }
    __syncthreads();
    size_t ob = (size_t)z * HW * 256;
#pragma unroll
    for (int r = 0; r < 4; r++) {
        float v = t[tx][ty + r * 8];
        __half hh = __float2half(v);
        size_t o = ob + (size_t)(hw0 + ty + r * 8) * 256 + c0 + tx;
        hi[o] = hh;
        lo[o] = __float2half(v - __half2float(hh));
    }
}

// ==================== 256-thread 128x128-tile GEMM, 32-K chunks, 3-stage, 2 CTAs/SM ====================
#define SMS 40
#define A_HV (128 * SMS)                 // halves per A term buffer (5120)
#define B_HV (128 * SMS)
#define STG_B ((2 * A_HV + B_HV) * 2)    // 30720 bytes per stage
#define GEMM_SMEM3 (3 * STG_B)           // 92160

__device__ __forceinline__ void gemm_issue128(
    uint32_t smb, int stage,
    const __half* Ah, const __half* Al, const __half* Bh,
    int m0, int n0, int K, int k0, int rid, int cid) {
    uint32_t sb = smb + (uint32_t)stage * STG_B;
    uint32_t s0 = (uint32_t)(rid * SMS + cid) * 2;
    const __half* a = &Ah[(size_t)(m0 + rid) * K + k0 + cid];
    const __half* l = &Al[(size_t)(m0 + rid) * K + k0 + cid];
    const __half* bb = &Bh[(size_t)(n0 + rid) * K + k0 + cid];
    cpa16(sb + s0,                 a);    cpa16(sb + s0 + 16,                 a + 8);
    cpa16(sb + A_HV * 2 + s0,      l);    cpa16(sb + A_HV * 2 + s0 + 16,     l + 8);
    cpa16(sb + 4 * A_HV + s0,      bb);   cpa16(sb + 4 * A_HV + s0 + 16,     bb + 8);
}

// OUT: 0 = fp32 + bias, 1 = fp16 hi/lo, 2 = fp16 single
template <int OUT>
__device__ __forceinline__ void gemm_core128(
    uint32_t smb,
    const __half* Ah, const __half* Al, const __half* Bh,
    float* Cf, __half* Chi, __half* Clo,
    const float* bias, int N, int K, int m0, int n0) {
    const int tid = threadIdx.x, lane = tid & 31, wid = tid >> 5;
    const int warp_m = wid & 3, warp_n = wid >> 2;   // 4 x 2 warps, warp tile 32x64

    float acc[2][8][4];
#pragma unroll
    for (int i = 0; i < 2; i++)
#pragma unroll
        for (int j = 0; j < 8; j++)
#pragma unroll
            for (int k = 0; k < 4; k++) acc[i][j][k] = 0.f;

    const int rid = tid >> 1;            // 0..127
    const int cid = (tid & 1) * 16;      // halves
    const int a_row = warp_m * 32 + (lane & 15);
    const int a_colx = (lane >> 4) << 3;
    const int b_row = warp_n * 64 + (lane & 7) + ((lane >> 4) << 3);
    const int b_colx = ((lane >> 3) & 1) << 3;

    const int nk = K / 32;
    gemm_issue128(smb, 0, Ah, Al, Bh, m0, n0, K, 0, rid, cid);
    CP_COMMIT();
    gemm_issue128(smb, 1, Ah, Al, Bh, m0, n0, K, 32, rid, cid);
    CP_COMMIT();

    int stage = 0;
    for (int i = 0; i < nk; i++) {
        CP_WAIT1();
        __syncthreads();   // chunk i visible everywhere; compute(i-1) done everywhere

        const uint32_t base = smb + (uint32_t)stage * STG_B;
#pragma unroll
        for (int ks = 0; ks < 2; ks++) {
            const int kc = ks * 16;
            uint32_t ah[2][4], al[2][4];
#pragma unroll
            for (int mt = 0; mt < 2; mt++) {
                uint32_t off = (uint32_t)((a_row + mt * 16) * SMS + kc + a_colx) * 2;
                ldm_x4(ah[mt], base + off);
                ldm_x4(al[mt], base + A_HV * 2 + off);
            }
#pragma unroll
            for (int ng = 0; ng < 4; ng++) {
                uint32_t bh[4];
                uint32_t off = (uint32_t)((b_row + ng * 16) * SMS + kc + b_colx) * 2;
                ldm_x4(bh, base + 4 * A_HV + off);
#pragma unroll
                for (int mt = 0; mt < 2; mt++)
#pragma unroll
                    for (int nt = 0; nt < 2; nt++)
                        mma16816(acc[mt][ng * 2 + nt], ah[mt], &bh[nt * 2]);
#pragma unroll
                for (int mt = 0; mt < 2; mt++)
#pragma unroll
                    for (int nt = 0; nt < 2; nt++)
                        mma16816(acc[mt][ng * 2 + nt], al[mt], &bh[nt * 2]);
            }
        }

        // issue chunk i+2 (buffer (i+2)%3 == (i-1)%3, read finished pre-barrier)
        if (i + 2 < nk)
            gemm_issue128(smb, (stage + 2 >= 3) ? stage - 1 : stage + 2,
                          Ah, Al, Bh, m0, n0, K, (i + 2) * 32, rid, cid);
        CP_COMMIT();
        stage = (stage + 1 == 3) ? 0 : stage + 1;
    }

#pragma unroll
    for (int mt = 0; mt < 2; mt++) {
        int mrow0 = m0 + warp_m * 32 + mt * 16 + (lane >> 2);
        int mrow1 = mrow0 + 8;
        float bv0 = (OUT == 0 && bias) ? bias[mrow0] : 0.f;
        float bv1 = (OUT == 0 && bias) ? bias[mrow1] : 0.f;
#pragma unroll
        for (int j = 0; j < 8; j++) {
            int n = n0 + warp_n * 64 + j * 8 + (lane & 3) * 2;
            float* c = acc[mt][j];
            size_t o0 = (size_t)mrow0 * N + n;
            size_t o1 = (size_t)mrow1 * N + n;
            if (OUT == 1) {
                uint32_t h0, l0, h1, l1;
                split2h(c[0], c[1], h0, l0);
                split2h(c[2], c[3], h1, l1);
                *(uint32_t*)&Chi[o0] = h0; *(uint32_t*)&Clo[o0] = l0;
                *(uint32_t*)&Chi[o1] = h1; *(uint32_t*)&Clo[o1] = l1;
            } else if (OUT == 2) {
                *(uint32_t*)&Chi[o0] = pack2h(c[0], c[1]);
                *(uint32_t*)&Chi[o1] = pack2h(c[2], c[3]);
            } else {
                *(float2*)&Cf[o0] = make_float2(c[0] + bv0, c[1] + bv0);
                *(float2*)&Cf[o1] = make_float2(c[2] + bv1, c[3] + bv1);
            }
        }
    }
}

// ---- merged q + kv pointwise GEMMs.  grid (48, 16), 256 threads ----
__global__ void __launch_bounds__(256, 2)
gemm_dual(const __half* __restrict__ qAh, const __half* __restrict__ qAl,
          const __half* __restrict__ qB,
          __half* __restrict__ qChi, __half* __restrict__ qClo,
          const __half* __restrict__ kAh, const __half* __restrict__ kAl,
          const __half* __restrict__ kB,
          __half* __restrict__ kC) {
    extern __shared__ __half gsm[];
    const uint32_t smb = smem_u32(gsm);
    const int bx = blockIdx.x, z = blockIdx.y;
    if (bx < 32) {
        // q: M=1024 pos (8 tiles of 128), N=512 ch (4 tiles of 128), K=256
        int m0 = (bx >> 2) * 128, n0 = (bx & 3) * 128;
        gemm_core128<1>(smb,
            qAh + (size_t)z * 1024 * 256, qAl + (size_t)z * 1024 * 256, qB,
            nullptr, qChi + (size_t)z * 1024 * 512, qClo + (size_t)z * 1024 * 512,
            nullptr, 512, 256, m0, n0);
    } else {
        // kv: M=256 pos (2 tiles), N=1024 ch (8 tiles), K=256
        int bk = bx - 32;
        int m0 = (bk >> 3) * 128, n0 = (bk & 7) * 128;
        gemm_core128<2>(smb,
            kAh + (size_t)z * 256 * 256, kAl + (size_t)z * 256 * 256, kB,
            nullptr, kC + (size_t)z * 256 * 1024, nullptr,
            nullptr, 1024, 256, m0, n0);
    }
}

// ---- out projection GEMM.  grid (8, 2, 16), 256 threads ----
__global__ void __launch_bounds__(256, 2)
gemm_out(const __half* __restrict__ Ah, const __half* __restrict__ Al,
         const __half* __restrict__ B,
         float* __restrict__ Cf, const float* __restrict__ bias) {
    extern __shared__ __half gsm[];
    const uint32_t smb = smem_u32(gsm);
    const int z = blockIdx.z;
    int m0 = blockIdx.y * 128, n0 = blockIdx.x * 128;
    gemm_core128<0>(smb,
        Ah, Al, B + (size_t)z * 1024 * 512,
        Cf + (size_t)z * 256 * 1024, nullptr, nullptr,
        bias, 1024, 512, m0, n0);
}

// ==================== attention: Q split / K,V,P single fp16, online softmax ====================
#define ATT_S 72
#define AKH 0
#define AVH (256 * ATT_S)
#define AQW (2 * 256 * ATT_S)
#define QSLOT (2 * 16 * ATT_S)
#define ATT_SMEM ((2 * 256 + 16 * 2 * 16) * ATT_S * 2)   // 147456 B

__device__ __forceinline__ void att_stage_qw(uint32_t smb, int wid,
                                             const __half* qhi, const __half* qlo,
                                             size_t qb, int lane) {
    uint32_t base = smb + (uint32_t)(AQW + wid * QSLOT) * 2;
#pragma unroll
    for (int j = 0; j < 4; j++) {
        int idx = j * 32 + lane;
        int row = idx >> 3, ch = (idx & 7) * 8;
        uint32_t so = (uint32_t)(row * ATT_S + ch) * 2;
        cpa16(base + so,                  &qhi[qb + (size_t)row * 512 + ch]);
        cpa16(base + 16 * ATT_S * 2 + so, &qlo[qb + (size_t)row * 512 + ch]);
    }
}

__global__ void __launch_bounds__(512, 1)
attn_mma(const __half* __restrict__ qhi, const __half* __restrict__ qlo,
         const __half* __restrict__ kv,
         __half* __restrict__ ao) {
    extern __shared__ __half sm[];
    const int tid = threadIdx.x, lane = tid & 31, wid = tid >> 5;
    const int h = blockIdx.x, z = blockIdx.y;
    const int zk = ((z >> 3) ^ 1) * 8 + (z & 7);
    const uint32_t smb = smem_u32(sm);

    {
        size_t kb = (size_t)zk * 256 * 1024 + h * 64;
        size_t vb = kb + 512;
        for (int i = tid; i < 2048; i += 512) {
            int row = i >> 3, ch = (i & 7) * 8;
            uint32_t so = (uint32_t)(row * ATT_S + ch) * 2;
            cpa16(smb + AKH * 2 + so, &kv[kb + (size_t)row * 1024 + ch]);
            cpa16(smb + AVH * 2 + so, &kv[vb + (size_t)row * 1024 + ch]);
        }
        att_stage_qw(smb, wid, qhi, qlo,
                     ((size_t)z * 1024 + wid * 16) * 512 + h * 64, lane);
        CP_COMMIT();
        CP_WAIT0();
        __syncthreads();
    }

    const int a_row = lane & 15;
    const int a_cx = (lane >> 4) << 3;
    const int b_rx = (lane & 7) + ((lane >> 4) << 3);
    const int b_cx = ((lane >> 3) & 1) << 3;
    const int v_rx = (lane & 7) + (((lane >> 3) & 1) << 3);
    const int v_cx = (lane >> 4) << 3;
    const uint32_t qbase = smb + (uint32_t)(AQW + wid * QSLOT) * 2;

    for (int i = 0; i < 4; i++) {
        const int trow = (i * 16 + wid) * 16;

        float o[8][4];
#pragma unroll
        for (int j = 0; j < 8; j++)
#pragma unroll
            for (int k = 0; k < 4; k++) o[j][k] = 0.f;
        float m0 = -1e30f, m1 = -1e30f, s0 = 0.f, s1 = 0.f;

#pragma unroll
        for (int ck = 0; ck < 4; ck++) {
            float c[8][4];
#pragma unroll
            for (int t = 0; t < 8; t++)
#pragma unroll
                for (int k = 0; k < 4; k++) c[t][k] = 0.f;

#pragma unroll
            for (int kt = 0; kt < 4; kt++) {
                uint32_t aH[4], aL[4];
                uint32_t aoff = (uint32_t)(a_row * ATT_S + kt * 16 + a_cx) * 2;
                ldm_x4(aH, qbase + aoff);
                ldm_x4(aL, qbase + 16 * ATT_S * 2 + aoff);
#pragma unroll
                for (int jp = 0; jp < 2; jp++) {
                    int jt = jp * 2;
                    uint32_t bo0 = (uint32_t)((ck * 64 + jt * 16 + b_rx) * ATT_S + kt * 16 + b_cx) * 2;
                    uint32_t bo1 = (uint32_t)((ck * 64 + (jt + 1) * 16 + b_rx) * ATT_S + kt * 16 + b_cx) * 2;
                    uint32_t bH0[4], bH1[4];
                    ldm_x4(bH0, smb + AKH * 2 + bo0);
                    ldm_x4(bH1, smb + AKH * 2 + bo1);
                    float *c0 = c[jt * 2], *c1 = c[jt * 2 + 1];
                    float *c2 = c[jt * 2 + 2], *c3 = c[jt * 2 + 3];
                    mma16816(c0, aH, &bH0[0]); mma16816(c1, aH, &bH0[2]);
                    mma16816(c2, aH, &bH1[0]); mma16816(c3, aH, &bH1[2]);
                    mma16816(c0, aL, &bH0[0]); mma16816(c1, aL, &bH0[2]);
                    mma16816(c2, aL, &bH1[0]); mma16816(c3, aL, &bH1[2]);
                }
            }

            if (ck == 3 && i < 3) {
                att_stage_qw(smb, wid, qhi, qlo,
                             ((size_t)z * 1024 + ((i + 1) * 16 + wid) * 16) * 512 + h * 64, lane);
                CP_COMMIT();
            }

            {
                float cm0 = -1e30f, cm1 = -1e30f;
#pragma unroll
                for (int t = 0; t < 8; t++) {
                    cm0 = fmaxf(cm0, fmaxf(c[t][0], c[t][1]));
                    cm1 = fmaxf(cm1, fmaxf(c[t][2], c[t][3]));
                }
                cm0 = fmaxf(cm0, __shfl_xor_sync(0xffffffffu, cm0, 1));
                cm0 = fmaxf(cm0, __shfl_xor_sync(0xffffffffu, cm0, 2));
                cm1 = fmaxf(cm1, __shfl_xor_sync(0xffffffffu, cm1, 1));
                cm1 = fmaxf(cm1, __shfl_xor_sync(0xffffffffu, cm1, 2));
                float mn0 = fmaxf(m0, cm0), mn1 = fmaxf(m1, cm1);
                float sc0 = __expf(m0 - mn0), sc1 = __expf(m1 - mn1);
                s0 *= sc0; s1 *= sc1;
#pragma unroll
                for (int j = 0; j < 8; j++) {
                    o[j][0] *= sc0; o[j][1] *= sc0;
                    o[j][2] *= sc1; o[j][3] *= sc1;
                }
#pragma unroll
                for (int t = 0; t < 8; t++) {
                    c[t][0] = __expf(c[t][0] - mn0); s0 += c[t][0];
                    c[t][1] = __expf(c[t][1] - mn0); s0 += c[t][1];
                    c[t][2] = __expf(c[t][2] - mn1); s1 += c[t][2];
                    c[t][3] = __expf(c[t][3] - mn1); s1 += c[t][3];
                }
                m0 = mn0; m1 = mn1;
            }

            // ---- PV chunk (single fp16 P) ----
#pragma unroll
            for (int ktl = 0; ktl < 4; ktl++) {
                uint32_t aP[4];
                aP[0] = pack2h(c[2 * ktl][0], c[2 * ktl][1]);
                aP[1] = pack2h(c[2 * ktl][2], c[2 * ktl][3]);
                aP[2] = pack2h(c[2 * ktl + 1][0], c[2 * ktl + 1][1]);
                aP[3] = pack2h(c[2 * ktl + 1][2], c[2 * ktl + 1][3]);
#pragma unroll
                for (int db = 0; db < 4; db += 2) {
                    uint32_t bo0 = (uint32_t)((ck * 64 + ktl * 16 + v_rx) * ATT_S + db * 16 + v_cx) * 2;
                    uint32_t bo1 = (uint32_t)((ck * 64 + ktl * 16 + v_rx) * ATT_S + (db + 1) * 16 + v_cx) * 2;
                    uint32_t bH0[4], bH1[4];
                    ldm_x4_t(bH0, smb + AVH * 2 + bo0);
                    ldm_x4_t(bH1, smb + AVH * 2 + bo1);
                    mma16816(o[db * 2],     aP, &bH0[0]);
                    mma16816(o[db * 2 + 1], aP, &bH0[2]);
                    mma16816(o[db * 2 + 2], aP, &bH1[0]);
                    mma16816(o[db * 2 + 3], aP, &bH1[2]);
                }
            }
        }

        s0 += __shfl_xor_sync(0xffffffffu, s0, 1);
        s0 += __shfl_xor_sync(0xffffffffu, s0, 2);
        s1 += __shfl_xor_sync(0xffffffffu, s1, 1);
        s1 += __shfl_xor_sync(0xffffffffu, s1, 2);
        float i0 = 1.f / s0, i1 = 1.f / s1;
        {
            int row0 = trow + (lane >> 2);
            int row1 = row0 + 8;
            size_t b0 = ((size_t)z * 1024 + row0) * 512 + h * 64 + (lane & 3) * 2;
            size_t b1 = ((size_t)z * 1024 + row1) * 512 + h * 64 + (lane & 3) * 2;
#pragma unroll
            for (int nt = 0; nt < 8; nt++) {
                *(uint32_t*)&ao[b0 + nt * 8] = pack2h(o[nt][0] * i0, o[nt][1] * i0);
                *(uint32_t*)&ao[b1 + nt * 8] = pack2h(o[nt][2] * i1, o[nt][3] * i1);
            }
        }
        if (i < 3) CP_WAIT0();
    }
}

// ==================== launch ====================
extern "C" void kernel_launch(void* const* d_in, const int* in_sizes, int n_in,
                              void* d_out, int out_size) {
    const float* x        = (const float*)d_in[0];
    const float* y        = (const float*)d_in[1];
    const float* q_dw_w   = (const float*)d_in[2];
    const float* q_bn_g   = (const float*)d_in[3];
    const float* q_bn_b   = (const float*)d_in[4];
    const float* q_bn_m   = (const float*)d_in[5];
    const float* q_bn_v   = (const float*)d_in[6];
    const float* q_pw_w   = (const float*)d_in[7];
    const float* kv_dw_w  = (const float*)d_in[8];
    const float* kv_bn_g  = (const float*)d_in[9];
    const float* kv_bn_b  = (const float*)d_in[10];
    const float* kv_bn_m  = (const float*)d_in[11];
    const float* kv_bn_v  = (const float*)d_in[12];
    const float* kv_pw_w  = (const float*)d_in[13];
    const float* out_w    = (const float*)d_in[14];
    const float* out_b    = (const float*)d_in[15];
    float* out = (float*)d_out;

    __half *p_hqT_hi, *p_hqT_lo, *p_hkvT_hi, *p_hkvT_lo;
    __half *p_wq, *p_wkv, *p_wo_hi, *p_wo_lo;
    __half *p_qs_hi, *p_qs_lo, *p_kvs, *p_ao;
    cudaGetSymbolAddress((void**)&p_hqT_hi,  g_hqT_hi);
    cudaGetSymbolAddress((void**)&p_hqT_lo,  g_hqT_lo);
    cudaGetSymbolAddress((void**)&p_hkvT_hi, g_hkvT_hi);
    cudaGetSymbolAddress((void**)&p_hkvT_lo, g_hkvT_lo);
    cudaGetSymbolAddress((void**)&p_wq,     g_wq);
    cudaGetSymbolAddress((void**)&p_wkv,    g_wkv);
    cudaGetSymbolAddress((void**)&p_wo_hi,  g_wo_hi);
    cudaGetSymbolAddress((void**)&p_wo_lo,  g_wo_lo);
    cudaGetSymbolAddress((void**)&p_qs_hi,  g_qs_hi);
    cudaGetSymbolAddress((void**)&p_qs_lo,  g_qs_lo);
    cudaGetSymbolAddress((void**)&p_kvs,    g_kvs);
    cudaGetSymbolAddress((void**)&p_ao,     g_ao);

    cudaFuncSetAttribute(attn_mma,
                         cudaFuncAttributeMaxDynamicSharedMemorySize, ATT_SMEM);
    cudaFuncSetAttribute(gemm_dual,
                         cudaFuncAttributeMaxDynamicSharedMemorySize, GEMM_SMEM3);
    cudaFuncSetAttribute(gemm_out,
                         cudaFuncAttributeMaxDynamicSharedMemorySize, GEMM_SMEM3);

    // 1) merged dw conv + BN + transpose + split, plus weight conversion (z==32)
    {
        dim3 blk(32, 8);
        dim3 grid(32, 8, 33);
        dw_bn_split2<<<grid, blk>>>(x, y,
                                    q_dw_w, q_bn_g, q_bn_b, q_bn_m, q_bn_v,
                                    kv_dw_w, kv_bn_g, kv_bn_b, kv_bn_m, kv_bn_v,
                                    p_hqT_hi, p_hqT_lo, p_hkvT_hi, p_hkvT_lo,
                                    q_pw_w, kv_pw_w, out_w,
                                    p_wq, p_wkv, p_wo_hi, p_wo_lo);
    }
    // 2) merged q + kv pointwise GEMMs (128x128 tiles, 2 CTAs/SM)
    {
        dim3 grid(48, 16);
        gemm_dual<<<grid, 256, GEMM_SMEM3>>>(p_hqT_hi, p_hqT_lo, p_wq,
                                             p_qs_hi, p_qs_lo,
                                             p_hkvT_hi, p_hkvT_lo, p_wkv,
                                             p_kvs);
    }
    // 3) attention
    {
        dim3 grid(8, 16);
        attn_mma<<<grid, 512, ATT_SMEM>>>(p_qs_hi, p_qs_lo, p_kvs, p_ao);
    }
    // 4) out projection (128x128 tiles, 2 CTAs/SM)
    {
        dim3 grid(8, 2, 16);
        gemm_out<<<grid, 256, GEMM_SMEM3>>>(p_wo_hi, p_wo_lo, p_ao, out, out_b);
    }
}